// round 5
// baseline (speedup 1.0000x reference)
#include <cuda_runtime.h>
#include <math.h>

// ---------------- f32x2 packed helpers ----------------
__device__ __forceinline__ unsigned long long pk2(float x, float y) {
    unsigned long long r;
    asm("mov.b64 %0, {%1, %2};" : "=l"(r) : "f"(x), "f"(y));
    return r;
}
__device__ __forceinline__ void fma2(unsigned long long& d,
                                     unsigned long long a, unsigned long long b) {
    asm("fma.rn.f32x2 %0, %1, %2, %0;" : "+l"(d) : "l"(a), "l"(b));
}
union F4 { float4 v; unsigned long long u[2]; };

// ---------------- scratch (device globals; no allocation) ----------------
#define NPIX 16384              // 128*128
__device__ __align__(16) float g_bufA[4 * 256 * NPIX];    // 64 MB NCHW
__device__ __align__(16) float g_bufB[4 * 256 * NPIX];    // 64 MB NCHW
__device__ __align__(16) float g_bufC[4 * 256 * NPIX];    // 64 MB NHWC
__device__ __align__(16) float g_off [4 * 100 * NPIX];    // 26 MB
__device__ __align__(16) float g_wT  [2 * 25 * 128 * 256];// 6.4 MB
__device__ __align__(16) float g_owT [256 * 25 * 100];    // 2.56 MB
__device__ __align__(16) float g_rT  [256 * 128];
__device__ float g_pool[1024];
__device__ float g_scale[1024];

// ---------------- fused concat -> NCHW A + NHWC C ----------------
__global__ void __launch_bounds__(256) concat_nhwc(
    const float* __restrict__ bev1, const float* __restrict__ bev2,
    float* __restrict__ A, float* __restrict__ C) {
    __shared__ float tile[32][33];
    const int bp = blockIdx.x;   // 0..511 pixel tiles
    const int bc = blockIdx.y;   // 0..7 channel tiles of 32
    const int b  = blockIdx.z;
    const int tx = threadIdx.x & 31, ty = threadIdx.x >> 5;
    const float* src = ((bc < 4)
        ? bev1 + ((size_t)b * 128 + bc * 32) * NPIX
        : bev2 + ((size_t)b * 128 + (bc - 4) * 32) * NPIX) + bp * 32;
    float* adst = A + ((size_t)b * 256 + bc * 32) * NPIX + bp * 32;
#pragma unroll
    for (int r = 0; r < 4; r++) {
        int c = ty + r * 8;
        float v = src[(size_t)c * NPIX + tx];
        tile[c][tx] = v;
        adst[(size_t)c * NPIX + tx] = v;
    }
    __syncthreads();
    float* dst = C + ((size_t)b * NPIX + bp * 32) * 256 + bc * 32;
#pragma unroll
    for (int r = 0; r < 4; r++) {
        int p = ty + r * 8;
        dst[(size_t)p * 256 + tx] = tile[tx][p];
    }
}

// ---------------- NCHW -> NHWC transpose (stage 2) ----------------
__global__ void __launch_bounds__(256) to_nhwc(const float* __restrict__ in,
                                               float* __restrict__ outp) {
    __shared__ float tile[32][33];
    const int bp = blockIdx.x;
    const int bc = blockIdx.y;
    const int b  = blockIdx.z;
    const int tx = threadIdx.x & 31, ty = threadIdx.x >> 5;
    const float* src = in + ((size_t)b * 256 + bc * 32) * NPIX + bp * 32;
#pragma unroll
    for (int r = 0; r < 4; r++) {
        int c = ty + r * 8;
        tile[c][tx] = src[(size_t)c * NPIX + tx];
    }
    __syncthreads();
    float* dst = outp + ((size_t)b * NPIX + bp * 32) * 256 + bc * 32;
#pragma unroll
    for (int r = 0; r < 4; r++) {
        int p = ty + r * 8;
        dst[(size_t)p * 256 + tx] = tile[tx][p];
    }
}

// ---------------- fused weight transposes (dcn + off) ----------------
__global__ void fused_tw(const float* __restrict__ dcnw,
                         const float* __restrict__ offw,
                         float* __restrict__ WT, float* __restrict__ OWT) {
    int idx = blockIdx.x * 256 + threadIdx.x;
    if (idx < 1638400) {
        int o = idx & 255;
        int t = idx >> 8;
        int c = t & 127;
        int gk = t >> 7;
        int k = gk % 25, g = gk / 25;
        WT[idx] = dcnw[o * 6400 + (g * 128 + c) * 25 + k];
    } else {
        int i2 = idx - 1638400;
        if (i2 < 640000) {
            int o = i2 % 100;
            int t = i2 / 100;
            int tap = t % 25;
            int c = t / 25;
            OWT[i2] = offw[o * 6400 + c * 25 + tap];
        }
    }
}

__global__ void transpose_redw(const float* __restrict__ w, float* __restrict__ dst) {
    int idx = blockIdx.x * 256 + threadIdx.x;    // < 32768
    int o = idx & 127;
    int c = idx >> 7;
    dst[idx] = w[o * 256 + c];
}

// ---------------- offset conv: 256ch in, 100ch out, 5x5 pad2 (f32x2) --------
__global__ void __launch_bounds__(256) offconv_kernel(
    const float* __restrict__ xin, const float* __restrict__ offwT,
    const float* __restrict__ offb, float* __restrict__ offout) {
    const int tid = threadIdx.x;
    const int b = blockIdx.y;
    const int obase = blockIdx.z * 25;
    const int ty0 = (blockIdx.x >> 3) << 4;
    const int tx0 = (blockIdx.x & 7) << 4;
    const int ty = tid >> 4, tx = tid & 15;

    __shared__ __align__(16) float xt[8][20][20];
    __shared__ __align__(16) float ws[8][25][28];

    union { unsigned long long u[14]; float f[28]; } acc;
#pragma unroll
    for (int j = 0; j < 14; j++) acc.u[j] = 0ull;

    for (int cb = 0; cb < 256; cb += 8) {
        __syncthreads();
        for (int i = tid; i < 3200; i += 256) {
            int c = i / 400;
            int r = (i / 20) % 20;
            int col = i % 20;
            int gy = ty0 + r - 2, gx = tx0 + col - 2;
            float v = 0.f;
            if (gy >= 0 && gy < 128 && gx >= 0 && gx < 128)
                v = xin[((b * 256 + cb + c) * NPIX) + gy * 128 + gx];
            xt[c][r][col] = v;
        }
        for (int i = tid; i < 5600; i += 256) {
            int c = i / 700;
            int r = i % 700;
            int tap = r / 28;
            int o = r % 28;
            float v = 0.f;
            if (o < 25) v = offwT[(cb + c) * 2500 + tap * 100 + obase + o];
            ((float*)ws)[i] = v;
        }
        __syncthreads();
        for (int c = 0; c < 8; c++) {
            for (int kh = 0; kh < 5; kh++) {
#pragma unroll
                for (int kw = 0; kw < 5; kw++) {
                    float v = xt[c][ty + kh][tx + kw];
                    unsigned long long vd = pk2(v, v);
                    const F4* wp = (const F4*)ws[c][kh * 5 + kw];
#pragma unroll
                    for (int j = 0; j < 7; j++) {
                        F4 w = wp[j];
                        fma2(acc.u[2 * j], vd, w.u[0]);
                        fma2(acc.u[2 * j + 1], vd, w.u[1]);
                    }
                }
            }
        }
    }
    const int y = ty0 + ty, x = tx0 + tx;
#pragma unroll
    for (int o = 0; o < 25; o++) {
        float v = acc.f[o] + offb[obase + o];
        offout[(b * 100 + obase + o) * NPIX + y * 128 + x] = v;
    }
}

// ---------------- deformable conv v5 + BN + ReLU ----------------
// block: 512 thr, 1 CTA/SM; tile = 64 px x 256 couts; grid (256 tiles, B).
// FMA: warp -> o-group (warp&7)*32, px = (warp>>3)*32+lane; 1 px x 32 o/thread.
// Sampler: warp = 4 px x 8 consecutive 16B chunks (1 line/px), 4 tasks/warp.
#define SS_STRIDE 65
__global__ void __launch_bounds__(512, 1) deform5_kernel(
    const float* __restrict__ xh,    // NHWC [b][p][256]
    const float* __restrict__ off,   // NCHW [b][100][p]
    const float* __restrict__ wT,    // [50][128][256]
    const float* __restrict__ bng, const float* __restrict__ bnb,
    const float* __restrict__ bnm, const float* __restrict__ bnv,
    float* __restrict__ yout) {
    extern __shared__ float sm[];
    float* sPy = sm;                           // [50][64]
    float* sPx = sm + 3200;                    // [50][64]
    float* sS  = sm + 6400;                    // [128][65]
    float* sW  = sm + 6400 + 128 * SS_STRIDE;  // [2][16*256]
    float* sBN = sW + 8192;                    // inv[256], beta[256]

    const int tid = threadIdx.x;
    const int b = blockIdx.y;
    const int row = blockIdx.x >> 1;
    const int px0 = (blockIdx.x & 1) << 6;

    const int lane = tid & 31, warp = tid >> 5;
    // FMA mapping
    const int o0 = (warp & 7) * 32;
    const int pxf = (warp >> 3) * 32 + lane;   // 0..63
    // sampler mapping
    const int cg = warp & 3;                   // channel group of 32
    const int pb = (warp >> 2) * 16;           // px base (16 px per warp)
    const int lg = lane >> 3;                  // px within group of 4
    const int lc = lane & 7;                   // 16B chunk
    const int c0s = cg * 32 + lc * 4;          // this lane's 4 channels

    // ---- BN precompute ----
    if (tid < 256) {
        float inv = bng[tid] * rsqrtf(bnv[tid] + 1e-5f);
        sBN[tid] = inv;
        sBN[256 + tid] = bnb[tid] - bnm[tid] * inv;
    }

    // ---- precompute bilinear coords for all 50 (g,k) ----
    for (int idx = tid; idx < 3200; idx += 512) {
        int gk = idx >> 6, p = idx & 63;
        int g = gk / 25, k = gk % 25;
        int kh = k / 5, kw = k % 5;
        int ch = b * 100 + g * 50 + 2 * k;
        float oy = off[(size_t)ch * NPIX + row * 128 + px0 + p];
        float ox = off[(size_t)(ch + 1) * NPIX + row * 128 + px0 + p];
        sPy[idx] = (float)(row + kh - 2) + oy;
        sPx[idx] = (float)(px0 + p + kw - 2) + ox;
    }

    union { unsigned long long u[16]; float f[32]; } acc;
#pragma unroll
    for (int q = 0; q < 16; q++) acc.u[q] = 0ull;

    const float4 zero4 = make_float4(0.f, 0.f, 0.f, 0.f);

    for (int gk = 0; gk < 50; gk++) {
        const int g = (gk >= 25) ? 1 : 0;
        const float* xgb = xh + (size_t)b * NPIX * 256 + g * 128 + c0s;

        __syncthreads();   // sS free for reuse (covers coords/BN at gk=0)

        // ---- sample 64 px x 128 ch into sS ----
#pragma unroll
        for (int j = 0; j < 4; j++) {
            const int p = pb + j * 4 + lg;
            const float py = sPy[gk * 64 + p];
            const float pxv = sPx[gk * 64 + p];
            const float y0f = floorf(py), x0f = floorf(pxv);
            const float wy1 = py - y0f, wx1 = pxv - x0f;
            const float wy0 = 1.f - wy1, wx0 = 1.f - wx1;
            const float w00 = wy0 * wx0, w01 = wy0 * wx1;
            const float w10 = wy1 * wx0, w11 = wy1 * wx1;
            const int iy = (int)y0f, ix = (int)x0f;
            const bool vy0 = (iy >= 0) & (iy < 128);
            const bool vy1 = (iy >= -1) & (iy < 127);
            const bool vx0 = (ix >= 0) & (ix < 128);
            const bool vx1 = (ix >= -1) & (ix < 127);
            const long base = ((long)iy * 128 + ix) * 256;
            float4 va = (vy0 & vx0) ? *(const float4*)(xgb + base) : zero4;
            float4 vb = (vy0 & vx1) ? *(const float4*)(xgb + base + 256) : zero4;
            float4 vc = (vy1 & vx0) ? *(const float4*)(xgb + base + 128 * 256) : zero4;
            float4 vd = (vy1 & vx1) ? *(const float4*)(xgb + base + 128 * 256 + 256) : zero4;
            float* dst = &sS[c0s * SS_STRIDE + p];
            dst[0]             = w00 * va.x + w01 * vb.x + w10 * vc.x + w11 * vd.x;
            dst[SS_STRIDE]     = w00 * va.y + w01 * vb.y + w10 * vc.y + w11 * vd.y;
            dst[2 * SS_STRIDE] = w00 * va.z + w01 * vb.z + w10 * vc.z + w11 * vd.z;
            dst[3 * SS_STRIDE] = w00 * va.w + w01 * vb.w + w10 * vc.w + w11 * vd.w;
        }
        __syncthreads();

        // ---- FMA: out[64px][256o] += S[64px][128c] * W[128c][256o] ----
        const float4* wsrc = (const float4*)(wT + (size_t)gk * 32768);
        float4 wr0 = wsrc[tid];
        float4 wr1 = wsrc[512 + tid];
        for (int cc = 0; cc < 8; cc++) {
            float* buf = sW + (cc & 1) * 4096;
            ((float4*)buf)[tid]       = wr0;
            ((float4*)buf)[512 + tid] = wr1;
            if (cc < 7) {
                const float4* nxt = wsrc + (cc + 1) * 1024;
                wr0 = nxt[tid];
                wr1 = nxt[512 + tid];
            }
            __syncthreads();
            const float* sBase = &sS[(cc * 16) * SS_STRIDE + pxf];
#pragma unroll
            for (int c = 0; c < 16; c++) {
                float s = sBase[c * SS_STRIDE];
                unsigned long long sd = pk2(s, s);
                const F4* wrow = (const F4*)(buf + c * 256 + o0);
#pragma unroll
                for (int q4 = 0; q4 < 8; q4++) {
                    F4 w = wrow[q4];
                    fma2(acc.u[2 * q4],     sd, w.u[0]);
                    fma2(acc.u[2 * q4 + 1], sd, w.u[1]);
                }
            }
            // ping-pong: next write to this buffer is 2 iterations away,
            // separated by the next iteration's barrier.
        }
    }

    // epilogue: BN + ReLU, coalesced over px
    const size_t pbase = (size_t)row * 128 + px0 + pxf;
#pragma unroll
    for (int j = 0; j < 32; j++) {
        const int o = o0 + j;
        float v = acc.f[j] * sBN[o] + sBN[256 + o];
        yout[(size_t)(b * 256 + o) * NPIX + pbase] = fmaxf(v, 0.f);
    }
}

// ---------------- SE: pool / mlp / scale ----------------
__global__ void pool_kernel(const float* __restrict__ y, float* __restrict__ pool) {
    int bc = blockIdx.x;  // 0..1023
    const float* plane = y + (size_t)bc * NPIX;
    float s = 0.f;
    for (int i = threadIdx.x; i < NPIX; i += 256) s += plane[i];
    __shared__ float red[256];
    red[threadIdx.x] = s;
    __syncthreads();
    for (int st = 128; st > 0; st >>= 1) {
        if (threadIdx.x < st) red[threadIdx.x] += red[threadIdx.x + st];
        __syncthreads();
    }
    if (threadIdx.x == 0) pool[bc] = red[0] * (1.f / NPIX);
}

__global__ void se_kernel(const float* __restrict__ pool,
                          const float* __restrict__ w1,
                          const float* __restrict__ w2,
                          float* __restrict__ scale) {
    int b = blockIdx.x;
    int tid = threadIdx.x;
    __shared__ float sp[256], sh[16];
    sp[tid] = pool[b * 256 + tid];
    __syncthreads();
    if (tid < 16) {
        float a = 0.f;
        for (int c = 0; c < 256; c++) a += sp[c] * w1[tid * 256 + c];
        sh[tid] = fmaxf(a, 0.f);
    }
    __syncthreads();
    float a = 0.f;
#pragma unroll
    for (int j = 0; j < 16; j++) a += sh[j] * w2[tid * 16 + j];
    scale[b * 256 + tid] = 1.f / (1.f + expf(-a));
}

__global__ void scale_kernel(float4* __restrict__ y, const float* __restrict__ sc) {
    int i = blockIdx.x * 256 + threadIdx.x;  // < 4,194,304
    float s = sc[i >> 12];
    float4 v = y[i];
    v.x *= s; v.y *= s; v.z *= s; v.w *= s;
    y[i] = v;
}

// ---------------- final 1x1 conv + BN + ReLU (f32x2) ----------------
__global__ void __launch_bounds__(256) final_kernel(
    const float* __restrict__ xin, const float* __restrict__ redT,
    const float* __restrict__ bng, const float* __restrict__ bnb,
    const float* __restrict__ bnm, const float* __restrict__ bnv,
    float* __restrict__ out) {
    const int tid = threadIdx.x;
    const int b = blockIdx.y;
    const int p0 = blockIdx.x * 64;
    const int px = tid & 63, og = tid >> 6;
    __shared__ __align__(16) float sX[8][64];
    __shared__ __align__(16) float sWf[8][128];
    __shared__ float sBN[256];
    if (tid < 128) {
        float inv = bng[tid] * rsqrtf(bnv[tid] + 1e-5f);
        sBN[tid] = inv;
        sBN[128 + tid] = bnb[tid] - bnm[tid] * inv;
    }
    union { unsigned long long u[16]; float f[32]; } acc;
#pragma unroll
    for (int j = 0; j < 16; j++) acc.u[j] = 0ull;

    for (int cb = 0; cb < 256; cb += 8) {
        __syncthreads();
        {
            int i = tid;
            sX[i >> 6][i & 63] = xin[((size_t)(b * 256 + cb + (i >> 6))) * NPIX + p0 + (i & 63)];
            i = tid + 256;
            sX[i >> 6][i & 63] = xin[((size_t)(b * 256 + cb + (i >> 6))) * NPIX + p0 + (i & 63)];
            for (int t = tid; t < 1024; t += 256)
                sWf[t >> 7][t & 127] = redT[(cb + (t >> 7)) * 128 + (t & 127)];
        }
        __syncthreads();
#pragma unroll
        for (int c = 0; c < 8; c++) {
            float xv = sX[c][px];
            unsigned long long xd = pk2(xv, xv);
            const F4* wp = (const F4*)&sWf[c][og * 32];
#pragma unroll
            for (int j = 0; j < 8; j++) {
                F4 w = wp[j];
                fma2(acc.u[2 * j],     xd, w.u[0]);
                fma2(acc.u[2 * j + 1], xd, w.u[1]);
            }
        }
    }
#pragma unroll
    for (int j = 0; j < 32; j++) {
        int o = og * 32 + j;
        float v = acc.f[j] * sBN[o] + sBN[128 + o];
        out[((size_t)(b * 128 + o)) * NPIX + p0 + px] = fmaxf(v, 0.f);
    }
}

// ---------------- launch ----------------
extern "C" void kernel_launch(void* const* d_in, const int* in_sizes, int n_in,
                              void* d_out, int out_size) {
    const float* bev1   = (const float*)d_in[0];
    const float* bev2   = (const float*)d_in[1];
    const float* off_w1 = (const float*)d_in[2];
    const float* off_b1 = (const float*)d_in[3];
    const float* dcn_w1 = (const float*)d_in[4];
    const float* bn1_g  = (const float*)d_in[5];
    const float* bn1_b  = (const float*)d_in[6];
    const float* bn1_m  = (const float*)d_in[7];
    const float* bn1_v  = (const float*)d_in[8];
    const float* se1_w1 = (const float*)d_in[9];
    const float* se1_w2 = (const float*)d_in[10];
    const float* off_w2 = (const float*)d_in[11];
    const float* off_b2 = (const float*)d_in[12];
    const float* dcn_w2 = (const float*)d_in[13];
    const float* bn2_g  = (const float*)d_in[14];
    const float* bn2_b  = (const float*)d_in[15];
    const float* bn2_m  = (const float*)d_in[16];
    const float* bn2_v  = (const float*)d_in[17];
    const float* se2_w1 = (const float*)d_in[18];
    const float* se2_w2 = (const float*)d_in[19];
    const float* red_w  = (const float*)d_in[20];
    const float* bn3_g  = (const float*)d_in[21];
    const float* bn3_b  = (const float*)d_in[22];
    const float* bn3_m  = (const float*)d_in[23];
    const float* bn3_v  = (const float*)d_in[24];

    float *A, *B, *C, *OFF, *WT, *OWT, *RT, *POOL, *SCALE;
    cudaGetSymbolAddress((void**)&A,    g_bufA);
    cudaGetSymbolAddress((void**)&B,    g_bufB);
    cudaGetSymbolAddress((void**)&C,    g_bufC);
    cudaGetSymbolAddress((void**)&OFF,  g_off);
    cudaGetSymbolAddress((void**)&WT,   g_wT);
    cudaGetSymbolAddress((void**)&OWT,  g_owT);
    cudaGetSymbolAddress((void**)&RT,   g_rT);
    cudaGetSymbolAddress((void**)&POOL, g_pool);
    cudaGetSymbolAddress((void**)&SCALE,g_scale);

    const int DEF_SMEM = (3200 + 3200 + 128 * SS_STRIDE + 2 * 4096 + 512) * 4; // 93696 B
    cudaFuncSetAttribute(deform5_kernel,
                         cudaFuncAttributeMaxDynamicSharedMemorySize, DEF_SMEM);

    // ---- stage 1 (deform is launch #4 -> ncu capture slot) ----
    concat_nhwc<<<dim3(512, 8, 4), 256>>>(bev1, bev2, A, C);
    fused_tw<<<8900, 256>>>(dcn_w1, off_w1, WT, OWT);
    offconv_kernel<<<dim3(64, 4, 4), 256>>>(A, OWT, off_b1, OFF);
    deform5_kernel<<<dim3(256, 4), 512, DEF_SMEM>>>(C, OFF, WT, bn1_g, bn1_b, bn1_m, bn1_v, B);
    pool_kernel<<<1024, 256>>>(B, POOL);
    se_kernel<<<4, 256>>>(POOL, se1_w1, se1_w2, SCALE);
    scale_kernel<<<16384, 256>>>((float4*)B, SCALE);

    // ---- stage 2 ----
    to_nhwc<<<dim3(512, 8, 4), 256>>>(B, C);
    fused_tw<<<8900, 256>>>(dcn_w2, off_w2, WT, OWT);
    offconv_kernel<<<dim3(64, 4, 4), 256>>>(B, OWT, off_b2, OFF);
    deform5_kernel<<<dim3(256, 4), 512, DEF_SMEM>>>(C, OFF, WT, bn2_g, bn2_b, bn2_m, bn2_v, A);
    pool_kernel<<<1024, 256>>>(A, POOL);
    se_kernel<<<4, 256>>>(POOL, se2_w1, se2_w2, SCALE);
    scale_kernel<<<16384, 256>>>((float4*)A, SCALE);

    // ---- final ----
    transpose_redw<<<128, 256>>>(red_w, RT);
    final_kernel<<<dim3(256, 4), 256>>>(A, RT, bn3_g, bn3_b, bn3_m, bn3_v, (float*)d_out);
}

// round 7
// speedup vs baseline: 2.1316x; 2.1316x over previous
#include <cuda_runtime.h>
#include <cuda_fp16.h>
#include <math.h>
#include <stdint.h>

// ---------------- packed f32x2 helpers (offconv/final) ----------------
__device__ __forceinline__ unsigned long long pk2(float x, float y) {
    unsigned long long r;
    asm("mov.b64 %0, {%1, %2};" : "=l"(r) : "f"(x), "f"(y));
    return r;
}
__device__ __forceinline__ void fma2(unsigned long long& d,
                                     unsigned long long a, unsigned long long b) {
    asm("fma.rn.f32x2 %0, %1, %2, %0;" : "+l"(d) : "l"(a), "l"(b));
}
union F4 { float4 v; float f[4]; unsigned long long u[2]; };

// ---------------- mma.sync helpers (arch-agnostic tensor path) ----------
__device__ __forceinline__ void ldm4(uint32_t* r, uint32_t addr) {
    asm volatile("ldmatrix.sync.aligned.m8n8.x4.shared.b16 {%0,%1,%2,%3}, [%4];"
                 : "=r"(r[0]), "=r"(r[1]), "=r"(r[2]), "=r"(r[3]) : "r"(addr));
}
__device__ __forceinline__ void mma16816(float& d0, float& d1, float& d2, float& d3,
                                         const uint32_t* a, uint32_t b0, uint32_t b1) {
    asm volatile(
        "mma.sync.aligned.m16n8k16.row.col.f32.f16.f16.f32 "
        "{%0,%1,%2,%3}, {%4,%5,%6,%7}, {%8,%9}, {%0,%1,%2,%3};"
        : "+f"(d0), "+f"(d1), "+f"(d2), "+f"(d3)
        : "r"(a[0]), "r"(a[1]), "r"(a[2]), "r"(a[3]), "r"(b0), "r"(b1));
}
__device__ __forceinline__ uint32_t smem_u32(const void* p) {
    uint32_t a;
    asm("{ .reg .u64 t; cvta.to.shared.u64 t, %1; cvt.u32.u64 %0, t; }"
        : "=r"(a) : "l"(p));
    return a;
}
__device__ __forceinline__ uint32_t packh(float a, float b) {
    __half2 h = __halves2half2(__float2half_rn(a), __float2half_rn(b));
    return *(uint32_t*)&h;
}

// ---------------- scratch ----------------
#define NPIX 16384
__device__ __align__(16) float g_bufA[4 * 256 * NPIX];
__device__ __align__(16) float g_bufB[4 * 256 * NPIX];
__device__ __align__(16) float g_bufC[4 * 256 * NPIX];
__device__ __align__(16) float g_off [4 * 100 * NPIX];
__device__ __align__(16) uint2 g_bh  [50 * 8 * 32 * 32];  // B frags hi (3.3MB)
__device__ __align__(16) uint2 g_bl  [50 * 8 * 32 * 32];  // B frags lo
__device__ __align__(16) float g_owT [256 * 25 * 100];
__device__ __align__(16) float g_rT  [256 * 128];
__device__ float g_pool[1024];
__device__ float g_scale[1024];

// ---------------- fused concat -> NCHW A + NHWC C ----------------
__global__ void __launch_bounds__(256) concat_nhwc(
    const float* __restrict__ bev1, const float* __restrict__ bev2,
    float* __restrict__ A, float* __restrict__ C) {
    __shared__ float tile[32][33];
    const int bp = blockIdx.x, bc = blockIdx.y, b = blockIdx.z;
    const int tx = threadIdx.x & 31, ty = threadIdx.x >> 5;
    const float* src = ((bc < 4)
        ? bev1 + ((size_t)b * 128 + bc * 32) * NPIX
        : bev2 + ((size_t)b * 128 + (bc - 4) * 32) * NPIX) + bp * 32;
    float* adst = A + ((size_t)b * 256 + bc * 32) * NPIX + bp * 32;
#pragma unroll
    for (int r = 0; r < 4; r++) {
        int c = ty + r * 8;
        float v = src[(size_t)c * NPIX + tx];
        tile[c][tx] = v;
        adst[(size_t)c * NPIX + tx] = v;
    }
    __syncthreads();
    float* dst = C + ((size_t)b * NPIX + bp * 32) * 256 + bc * 32;
#pragma unroll
    for (int r = 0; r < 4; r++) {
        int p = ty + r * 8;
        dst[(size_t)p * 256 + tx] = tile[tx][p];
    }
}

__global__ void __launch_bounds__(256) to_nhwc(const float* __restrict__ in,
                                               float* __restrict__ outp) {
    __shared__ float tile[32][33];
    const int bp = blockIdx.x, bc = blockIdx.y, b = blockIdx.z;
    const int tx = threadIdx.x & 31, ty = threadIdx.x >> 5;
    const float* src = in + ((size_t)b * 256 + bc * 32) * NPIX + bp * 32;
#pragma unroll
    for (int r = 0; r < 4; r++) {
        int c = ty + r * 8;
        tile[c][tx] = src[(size_t)c * NPIX + tx];
    }
    __syncthreads();
    float* dst = outp + ((size_t)b * NPIX + bp * 32) * 256 + bc * 32;
#pragma unroll
    for (int r = 0; r < 4; r++) {
        int p = ty + r * 8;
        dst[(size_t)p * 256 + tx] = tile[tx][p];
    }
}

// ---------------- weight prep: B fragment pack (x64, hi/lo) + offw ---------
__global__ void prep_weights(const float* __restrict__ dcnw,
                             const float* __restrict__ offw,
                             uint2* __restrict__ BH, uint2* __restrict__ BL,
                             float* __restrict__ OWT) {
    int idx = blockIdx.x * 256 + threadIdx.x;
    if (idx < 409600) {
        const int t  = idx & 31;
        const int j  = (idx >> 5) & 31;
        const int s  = (idx >> 10) & 7;
        const int gk = idx >> 13;          // 0..49
        const int k = gk % 25, g = gk / 25;
        const int o = j * 8 + (t >> 2);
        const int c0 = s * 16 + 2 * (t & 3);
        float w0 = dcnw[o * 6400 + (g * 128 + c0    ) * 25 + k] * 64.f;
        float w1 = dcnw[o * 6400 + (g * 128 + c0 + 1) * 25 + k] * 64.f;
        float w8 = dcnw[o * 6400 + (g * 128 + c0 + 8) * 25 + k] * 64.f;
        float w9 = dcnw[o * 6400 + (g * 128 + c0 + 9) * 25 + k] * 64.f;
        float h0 = __half2float(__float2half_rn(w0));
        float h1 = __half2float(__float2half_rn(w1));
        float h8 = __half2float(__float2half_rn(w8));
        float h9 = __half2float(__float2half_rn(w9));
        BH[idx] = make_uint2(packh(h0, h1), packh(h8, h9));
        BL[idx] = make_uint2(packh(w0 - h0, w1 - h1), packh(w8 - h8, w9 - h9));
    } else {
        int i2 = idx - 409600;
        if (i2 < 640000) {
            int o = i2 % 100;
            int t2 = i2 / 100;
            int tap = t2 % 25;
            int c = t2 / 25;
            OWT[i2] = offw[o * 6400 + c * 25 + tap];
        }
    }
}

__global__ void transpose_redw(const float* __restrict__ w, float* __restrict__ dst) {
    int idx = blockIdx.x * 256 + threadIdx.x;
    int o = idx & 127;
    int c = idx >> 7;
    dst[idx] = w[o * 256 + c];
}

// ---------------- offset conv (fma2, verified) ----------------
__global__ void __launch_bounds__(256) offconv_kernel(
    const float* __restrict__ xin, const float* __restrict__ offwT,
    const float* __restrict__ offb, float* __restrict__ offout) {
    const int tid = threadIdx.x;
    const int b = blockIdx.y;
    const int obase = blockIdx.z * 25;
    const int ty0 = (blockIdx.x >> 3) << 4;
    const int tx0 = (blockIdx.x & 7) << 4;
    const int ty = tid >> 4, tx = tid & 15;

    __shared__ __align__(16) float xt[8][20][20];
    __shared__ __align__(16) float ws[8][25][28];

    union { unsigned long long u[14]; float f[28]; } acc;
#pragma unroll
    for (int j = 0; j < 14; j++) acc.u[j] = 0ull;

    for (int cb = 0; cb < 256; cb += 8) {
        __syncthreads();
        for (int i = tid; i < 3200; i += 256) {
            int c = i / 400;
            int r = (i / 20) % 20;
            int col = i % 20;
            int gy = ty0 + r - 2, gx = tx0 + col - 2;
            float v = 0.f;
            if (gy >= 0 && gy < 128 && gx >= 0 && gx < 128)
                v = xin[((b * 256 + cb + c) * NPIX) + gy * 128 + gx];
            xt[c][r][col] = v;
        }
        for (int i = tid; i < 5600; i += 256) {
            int c = i / 700;
            int r = i % 700;
            int tap = r / 28;
            int o = r % 28;
            float v = 0.f;
            if (o < 25) v = offwT[(cb + c) * 2500 + tap * 100 + obase + o];
            ((float*)ws)[i] = v;
        }
        __syncthreads();
        for (int c = 0; c < 8; c++) {
            for (int kh = 0; kh < 5; kh++) {
#pragma unroll
                for (int kw = 0; kw < 5; kw++) {
                    float v = xt[c][ty + kh][tx + kw];
                    unsigned long long vd = pk2(v, v);
                    const F4* wp = (const F4*)ws[c][kh * 5 + kw];
#pragma unroll
                    for (int j = 0; j < 7; j++) {
                        F4 w = wp[j];
                        fma2(acc.u[2 * j], vd, w.u[0]);
                        fma2(acc.u[2 * j + 1], vd, w.u[1]);
                    }
                }
            }
        }
    }
    const int y = ty0 + ty, x = tx0 + tx;
#pragma unroll
    for (int o = 0; o < 25; o++) {
        float v = acc.f[o] + offb[obase + o];
        offout[(b * 100 + obase + o) * NPIX + y * 128 + x] = v;
    }
}

// ---------------- deformable conv via mma.sync f16-split + BN + ReLU -------
// CTA: 64px x 256o, 256 thr (8 warps), grid (256, B).
// Warp tile 32px x 64o (wp = warp>>2, wo = warp&3). K = 128/tap, 50 taps.
// Smem float layout: sPy[3200] sPx[3200] sBNa[256] sBNb[256] Sh[4352] Sl[4352]
#define SM_SH 6912
#define SM_SL 11264
#define DEF_FLOATS 15616
__global__ void __launch_bounds__(256, 2) deform_hmma(
    const float* __restrict__ xh,    // NHWC [b][p][256]
    const float* __restrict__ off,   // NCHW [b][100][p]
    const uint2* __restrict__ BH, const uint2* __restrict__ BL,
    const float* __restrict__ bng, const float* __restrict__ bnb,
    const float* __restrict__ bnm, const float* __restrict__ bnv,
    float* __restrict__ yout) {
    extern __shared__ float sm[];
    float* sPy = sm;
    float* sPx = sm + 3200;
    float* sBNa = sm + 6400;
    float* sBNb = sm + 6656;
    uint32_t* Sh = (uint32_t*)(sm + SM_SH);   // 64px x 68 u32 (136 halves)
    uint32_t* Sl = (uint32_t*)(sm + SM_SL);

    const int tid = threadIdx.x;
    const int lane = tid & 31, warp = tid >> 5;
    const int b = blockIdx.y;
    const int row = blockIdx.x >> 1;
    const int px0 = (blockIdx.x & 1) << 6;

    // FMA-warp mapping
    const int wo = warp & 3;          // o-col: o base wo*64
    const int wp = warp >> 2;         // px-row: px base wp*32
    // sampler mapping (verified round-4 scheme)
    const int sh = warp & 1;
    const int cq = warp >> 1;
    const int lg = lane >> 3;
    const int lc = lane & 7;
    const int c0s = cq * 32 + lc * 4;

    // BN precompute (weights were scaled x64 at pack time)
    if (tid < 256) {
        float inv = bng[tid] * rsqrtf(bnv[tid] + 1e-5f);
        sBNa[tid] = inv * 0.015625f;
        sBNb[tid] = bnb[tid] - bnm[tid] * inv;
    }
    // bilinear coords for all 50 (g,k)
    for (int idx = tid; idx < 3200; idx += 256) {
        int gk = idx >> 6, p = idx & 63;
        int g = gk / 25, k = gk % 25;
        int kh = k / 5, kw = k % 5;
        int ch = b * 100 + g * 50 + 2 * k;
        float oy = off[(size_t)ch * NPIX + row * 128 + px0 + p];
        float ox = off[(size_t)(ch + 1) * NPIX + row * 128 + px0 + p];
        sPy[idx] = (float)(row + kh - 2) + oy;
        sPx[idx] = (float)(px0 + p + kw - 2) + ox;
    }

    float d[64];
#pragma unroll
    for (int q = 0; q < 64; q++) d[q] = 0.f;

    const float4 zero4 = make_float4(0.f, 0.f, 0.f, 0.f);
    // ldmatrix lane address bases (byte): row = lane&15, colblock = lane>>4
    const uint32_t shAddrH = smem_u32(Sh) + (lane & 15) * 272 + (lane >> 4) * 16;
    const uint32_t shAddrL = smem_u32(Sl) + (lane & 15) * 272 + (lane >> 4) * 16;

    for (int gk = 0; gk < 50; gk++) {
        const int g = (gk >= 25) ? 1 : 0;
        const float* xgb = xh + (size_t)b * NPIX * 256 + g * 128 + c0s;

        __syncthreads();   // previous tap's mma reads done; coords visible

        // ---- sample 64px x 128c -> Sh/Sl (fp16 hi/lo split) ----
#pragma unroll
        for (int j = 0; j < 8; j++) {
            const int p = sh * 32 + j * 4 + lg;
            const float py = sPy[gk * 64 + p];
            const float pv = sPx[gk * 64 + p];
            const float y0f = floorf(py), x0f = floorf(pv);
            const float wy1 = py - y0f, wx1 = pv - x0f;
            const float wy0 = 1.f - wy1, wx0 = 1.f - wx1;
            const float w00 = wy0 * wx0, w01 = wy0 * wx1;
            const float w10 = wy1 * wx0, w11 = wy1 * wx1;
            const int iy = (int)y0f, ix = (int)x0f;
            const bool vy0 = (iy >= 0) & (iy < 128);
            const bool vy1 = (iy >= -1) & (iy < 127);
            const bool vx0 = (ix >= 0) & (ix < 128);
            const bool vx1 = (ix >= -1) & (ix < 127);
            const long base = ((long)iy * 128 + ix) * 256;
            float4 va = (vy0 & vx0) ? *(const float4*)(xgb + base) : zero4;
            float4 vb = (vy0 & vx1) ? *(const float4*)(xgb + base + 256) : zero4;
            float4 vc = (vy1 & vx0) ? *(const float4*)(xgb + base + 128 * 256) : zero4;
            float4 vd4 = (vy1 & vx1) ? *(const float4*)(xgb + base + 128 * 256 + 256) : zero4;
            float r0 = w00 * va.x + w01 * vb.x + w10 * vc.x + w11 * vd4.x;
            float r1 = w00 * va.y + w01 * vb.y + w10 * vc.y + w11 * vd4.y;
            float r2 = w00 * va.z + w01 * vb.z + w10 * vc.z + w11 * vd4.z;
            float r3 = w00 * va.w + w01 * vb.w + w10 * vc.w + w11 * vd4.w;
            float h0 = __half2float(__float2half_rn(r0));
            float h1 = __half2float(__float2half_rn(r1));
            float h2 = __half2float(__float2half_rn(r2));
            float h3 = __half2float(__float2half_rn(r3));
            const int wi = p * 68 + (c0s >> 1);
            Sh[wi]     = packh(h0, h1);
            Sh[wi + 1] = packh(h2, h3);
            Sl[wi]     = packh(r0 - h0, r1 - h1);
            Sl[wi + 1] = packh(r2 - h2, r3 - h3);
        }
        __syncthreads();

        // ---- MMA: D[64px][256o] += A[64px][128c] * W[128c][256o] ----
        const uint2* BHt = BH + ((size_t)gk * 8 * 32 + wo * 8) * 32 + lane;
        const uint2* BLt = BL + ((size_t)gk * 8 * 32 + wo * 8) * 32 + lane;
#pragma unroll
        for (int s = 0; s < 8; s++) {
            uint32_t Ah[2][4], Al[2][4];
            ldm4(Ah[0], shAddrH + (wp * 32     ) * 272 + s * 32);
            ldm4(Ah[1], shAddrH + (wp * 32 + 16) * 272 + s * 32);
            ldm4(Al[0], shAddrL + (wp * 32     ) * 272 + s * 32);
            ldm4(Al[1], shAddrL + (wp * 32 + 16) * 272 + s * 32);
            const uint2* bh = BHt + (size_t)s * 1024;
            const uint2* bl = BLt + (size_t)s * 1024;
#pragma unroll
            for (int j2 = 0; j2 < 8; j2++) {
                uint2 Bh = bh[j2 * 32];
                uint2 Bl = bl[j2 * 32];
                float* d0 = &d[(0 * 8 + j2) * 4];
                float* d1 = &d[(1 * 8 + j2) * 4];
                mma16816(d0[0], d0[1], d0[2], d0[3], Ah[0], Bh.x, Bh.y);
                mma16816(d1[0], d1[1], d1[2], d1[3], Ah[1], Bh.x, Bh.y);
                mma16816(d0[0], d0[1], d0[2], d0[3], Al[0], Bh.x, Bh.y);
                mma16816(d1[0], d1[1], d1[2], d1[3], Al[1], Bh.x, Bh.y);
                mma16816(d0[0], d0[1], d0[2], d0[3], Ah[0], Bl.x, Bl.y);
                mma16816(d1[0], d1[1], d1[2], d1[3], Ah[1], Bl.x, Bl.y);
            }
        }
    }

    // ---- epilogue: BN + ReLU, scatter to NCHW ----
    const int g2 = lane >> 2, tig = lane & 3;
    const size_t outbase = (size_t)row * 128 + px0;
#pragma unroll
    for (int mt = 0; mt < 2; mt++) {
#pragma unroll
        for (int j2 = 0; j2 < 8; j2++) {
            const float* dd = &d[(mt * 8 + j2) * 4];
            const int pxl = wp * 32 + mt * 16 + g2;
            const int o = wo * 64 + j2 * 8 + 2 * tig;
            float a0 = sBNa[o], b0v = sBNb[o];
            float a1 = sBNa[o + 1], b1v = sBNb[o + 1];
            float* y0 = yout + ((size_t)(b * 256 + o)) * NPIX + outbase;
            float* y1 = yout + ((size_t)(b * 256 + o + 1)) * NPIX + outbase;
            y0[pxl]     = fmaxf(dd[0] * a0 + b0v, 0.f);
            y1[pxl]     = fmaxf(dd[1] * a1 + b1v, 0.f);
            y0[pxl + 8] = fmaxf(dd[2] * a0 + b0v, 0.f);
            y1[pxl + 8] = fmaxf(dd[3] * a1 + b1v, 0.f);
        }
    }
}

// ---------------- SE / pool / scale ----------------
__global__ void pool_kernel(const float* __restrict__ y, float* __restrict__ pool) {
    int bc = blockIdx.x;
    const float* plane = y + (size_t)bc * NPIX;
    float s = 0.f;
    for (int i = threadIdx.x; i < NPIX; i += 256) s += plane[i];
    __shared__ float red[256];
    red[threadIdx.x] = s;
    __syncthreads();
    for (int st = 128; st > 0; st >>= 1) {
        if (threadIdx.x < st) red[threadIdx.x] += red[threadIdx.x + st];
        __syncthreads();
    }
    if (threadIdx.x == 0) pool[bc] = red[0] * (1.f / NPIX);
}

__global__ void se_kernel(const float* __restrict__ pool,
                          const float* __restrict__ w1,
                          const float* __restrict__ w2,
                          float* __restrict__ scale) {
    int b = blockIdx.x;
    int tid = threadIdx.x;
    __shared__ float sp[256], shd[16];
    sp[tid] = pool[b * 256 + tid];
    __syncthreads();
    if (tid < 16) {
        float a = 0.f;
        for (int c = 0; c < 256; c++) a += sp[c] * w1[tid * 256 + c];
        shd[tid] = fmaxf(a, 0.f);
    }
    __syncthreads();
    float a = 0.f;
#pragma unroll
    for (int j = 0; j < 16; j++) a += shd[j] * w2[tid * 16 + j];
    scale[b * 256 + tid] = 1.f / (1.f + expf(-a));
}

__global__ void scale_kernel(float4* __restrict__ y, const float* __restrict__ sc) {
    int i = blockIdx.x * 256 + threadIdx.x;
    float s = sc[i >> 12];
    float4 v = y[i];
    v.x *= s; v.y *= s; v.z *= s; v.w *= s;
    y[i] = v;
}

// ---------------- final 1x1 conv + BN + ReLU (fma2, verified) -------------
__global__ void __launch_bounds__(256) final_kernel(
    const float* __restrict__ xin, const float* __restrict__ redT,
    const float* __restrict__ bng, const float* __restrict__ bnb,
    const float* __restrict__ bnm, const float* __restrict__ bnv,
    float* __restrict__ out) {
    const int tid = threadIdx.x;
    const int b = blockIdx.y;
    const int p0 = blockIdx.x * 64;
    const int px = tid & 63, og = tid >> 6;
    __shared__ __align__(16) float sX[8][64];
    __shared__ __align__(16) float sWf[8][128];
    __shared__ float sBN[256];
    if (tid < 128) {
        float inv = bng[tid] * rsqrtf(bnv[tid] + 1e-5f);
        sBN[tid] = inv;
        sBN[128 + tid] = bnb[tid] - bnm[tid] * inv;
    }
    union { unsigned long long u[16]; float f[32]; } acc;
#pragma unroll
    for (int j = 0; j < 16; j++) acc.u[j] = 0ull;

    for (int cb = 0; cb < 256; cb += 8) {
        __syncthreads();
        {
            int i = tid;
            sX[i >> 6][i & 63] = xin[((size_t)(b * 256 + cb + (i >> 6))) * NPIX + p0 + (i & 63)];
            i = tid + 256;
            sX[i >> 6][i & 63] = xin[((size_t)(b * 256 + cb + (i >> 6))) * NPIX + p0 + (i & 63)];
            for (int t = tid; t < 1024; t += 256)
                sWf[t >> 7][t & 127] = redT[(cb + (t >> 7)) * 128 + (t & 127)];
        }
        __syncthreads();
#pragma unroll
        for (int c = 0; c < 8; c++) {
            float xv = sX[c][px];
            unsigned long long xd = pk2(xv, xv);
            const F4* wp = (const F4*)&sWf[c][og * 32];
#pragma unroll
            for (int j = 0; j < 8; j++) {
                F4 w = wp[j];
                fma2(acc.u[2 * j],     xd, w.u[0]);
                fma2(acc.u[2 * j + 1], xd, w.u[1]);
            }
        }
    }
#pragma unroll
    for (int j = 0; j < 32; j++) {
        int o = og * 32 + j;
        float v = acc.f[j] * sBN[o] + sBN[128 + o];
        out[((size_t)(b * 128 + o)) * NPIX + p0 + px] = fmaxf(v, 0.f);
    }
}

// ---------------- launch ----------------
extern "C" void kernel_launch(void* const* d_in, const int* in_sizes, int n_in,
                              void* d_out, int out_size) {
    const float* bev1   = (const float*)d_in[0];
    const float* bev2   = (const float*)d_in[1];
    const float* off_w1 = (const float*)d_in[2];
    const float* off_b1 = (const float*)d_in[3];
    const float* dcn_w1 = (const float*)d_in[4];
    const float* bn1_g  = (const float*)d_in[5];
    const float* bn1_b  = (const float*)d_in[6];
    const float* bn1_m  = (const float*)d_in[7];
    const float* bn1_v  = (const float*)d_in[8];
    const float* se1_w1 = (const float*)d_in[9];
    const float* se1_w2 = (const float*)d_in[10];
    const float* off_w2 = (const float*)d_in[11];
    const float* off_b2 = (const float*)d_in[12];
    const float* dcn_w2 = (const float*)d_in[13];
    const float* bn2_g  = (const float*)d_in[14];
    const float* bn2_b  = (const float*)d_in[15];
    const float* bn2_m  = (const float*)d_in[16];
    const float* bn2_v  = (const float*)d_in[17];
    const float* se2_w1 = (const float*)d_in[18];
    const float* se2_w2 = (const float*)d_in[19];
    const float* red_w  = (const float*)d_in[20];
    const float* bn3_g  = (const float*)d_in[21];
    const float* bn3_b  = (const float*)d_in[22];
    const float* bn3_m  = (const float*)d_in[23];
    const float* bn3_v  = (const float*)d_in[24];

    float *A, *B, *C, *OFF, *OWT, *RT, *POOL, *SCALE;
    uint2 *BH, *BL;
    cudaGetSymbolAddress((void**)&A,    g_bufA);
    cudaGetSymbolAddress((void**)&B,    g_bufB);
    cudaGetSymbolAddress((void**)&C,    g_bufC);
    cudaGetSymbolAddress((void**)&OFF,  g_off);
    cudaGetSymbolAddress((void**)&BH,   g_bh);
    cudaGetSymbolAddress((void**)&BL,   g_bl);
    cudaGetSymbolAddress((void**)&OWT,  g_owT);
    cudaGetSymbolAddress((void**)&RT,   g_rT);
    cudaGetSymbolAddress((void**)&POOL, g_pool);
    cudaGetSymbolAddress((void**)&SCALE,g_scale);

    const int DEF_SMEM = DEF_FLOATS * 4;   // 62464 B
    cudaFuncSetAttribute(deform_hmma,
                         cudaFuncAttributeMaxDynamicSharedMemorySize, DEF_SMEM);

    // ---- stage 1 ----
    concat_nhwc<<<dim3(512, 8, 4), 256>>>(bev1, bev2, A, C);
    prep_weights<<<4102, 256>>>(dcn_w1, off_w1, BH, BL, OWT);
    offconv_kernel<<<dim3(64, 4, 4), 256>>>(A, OWT, off_b1, OFF);
    deform_hmma<<<dim3(256, 4), 256, DEF_SMEM>>>(C, OFF, BH, BL,
                                                 bn1_g, bn1_b, bn1_m, bn1_v, B);
    pool_kernel<<<1024, 256>>>(B, POOL);
    se_kernel<<<4, 256>>>(POOL, se1_w1, se1_w2, SCALE);
    scale_kernel<<<16384, 256>>>((float4*)B, SCALE);

    // ---- stage 2 ----
    to_nhwc<<<dim3(512, 8, 4), 256>>>(B, C);
    prep_weights<<<4102, 256>>>(dcn_w2, off_w2, BH, BL, OWT);
    offconv_kernel<<<dim3(64, 4, 4), 256>>>(B, OWT, off_b2, OFF);
    deform_hmma<<<dim3(256, 4), 256, DEF_SMEM>>>(C, OFF, BH, BL,
                                                 bn2_g, bn2_b, bn2_m, bn2_v, A);
    pool_kernel<<<1024, 256>>>(A, POOL);
    se_kernel<<<4, 256>>>(POOL, se2_w1, se2_w2, SCALE);
    scale_kernel<<<16384, 256>>>((float4*)A, SCALE);

    // ---- final ----
    transpose_redw<<<128, 256>>>(red_w, RT);
    final_kernel<<<dim3(256, 4), 256>>>(A, RT, bn3_g, bn3_b, bn3_m, bn3_v, (float*)d_out);
}

// round 8
// speedup vs baseline: 3.7686x; 1.7680x over previous
#include <cuda_runtime.h>
#include <cuda_fp16.h>
#include <math.h>
#include <stdint.h>

// ---------------- packed f32x2 helpers (final conv) ----------------
__device__ __forceinline__ unsigned long long pk2(float x, float y) {
    unsigned long long r;
    asm("mov.b64 %0, {%1, %2};" : "=l"(r) : "f"(x), "f"(y));
    return r;
}
__device__ __forceinline__ void fma2(unsigned long long& d,
                                     unsigned long long a, unsigned long long b) {
    asm("fma.rn.f32x2 %0, %1, %2, %0;" : "+l"(d) : "l"(a), "l"(b));
}
union F4 { float4 v; float f[4]; unsigned long long u[2]; };

// ---------------- mma.sync helpers ----------------
__device__ __forceinline__ void ldm4(uint32_t* r, uint32_t addr) {
    asm volatile("ldmatrix.sync.aligned.m8n8.x4.shared.b16 {%0,%1,%2,%3}, [%4];"
                 : "=r"(r[0]), "=r"(r[1]), "=r"(r[2]), "=r"(r[3]) : "r"(addr));
}
__device__ __forceinline__ void mma16816(float& d0, float& d1, float& d2, float& d3,
                                         const uint32_t* a, uint32_t b0, uint32_t b1) {
    asm volatile(
        "mma.sync.aligned.m16n8k16.row.col.f32.f16.f16.f32 "
        "{%0,%1,%2,%3}, {%4,%5,%6,%7}, {%8,%9}, {%0,%1,%2,%3};"
        : "+f"(d0), "+f"(d1), "+f"(d2), "+f"(d3)
        : "r"(a[0]), "r"(a[1]), "r"(a[2]), "r"(a[3]), "r"(b0), "r"(b1));
}
__device__ __forceinline__ uint32_t smem_u32(const void* p) {
    uint32_t a;
    asm("{ .reg .u64 t; cvta.to.shared.u64 t, %1; cvt.u32.u64 %0, t; }"
        : "=r"(a) : "l"(p));
    return a;
}
__device__ __forceinline__ uint32_t packh(float a, float b) {
    __half2 h = __halves2half2(__float2half_rn(a), __float2half_rn(b));
    return *(uint32_t*)&h;
}

// ---------------- scratch ----------------
#define NPIX 16384
__device__ __align__(16) float g_bufA[4 * 256 * NPIX];
__device__ __align__(16) float g_bufB[4 * 256 * NPIX];
__device__ __align__(16) float g_bufC[4 * 256 * NPIX];
__device__ __align__(16) float g_off [4 * 100 * NPIX];
__device__ __align__(16) uint2 g_bh  [50 * 8 * 32 * 32];   // dcn B frags hi
__device__ __align__(16) uint2 g_bl  [50 * 8 * 32 * 32];   // dcn B frags lo
__device__ __align__(16) uint2 g_obh [50 * 8 * 16 * 32];   // off B frags hi
__device__ __align__(16) uint2 g_obl [50 * 8 * 16 * 32];   // off B frags lo
__device__ __align__(16) float g_rT  [256 * 128];
__device__ float g_pool[1024];
__device__ float g_scale[1024];

// ---------------- fused concat -> NCHW A + NHWC C ----------------
__global__ void __launch_bounds__(256) concat_nhwc(
    const float* __restrict__ bev1, const float* __restrict__ bev2,
    float* __restrict__ A, float* __restrict__ C) {
    __shared__ float tile[32][33];
    const int bp = blockIdx.x, bc = blockIdx.y, b = blockIdx.z;
    const int tx = threadIdx.x & 31, ty = threadIdx.x >> 5;
    const float* src = ((bc < 4)
        ? bev1 + ((size_t)b * 128 + bc * 32) * NPIX
        : bev2 + ((size_t)b * 128 + (bc - 4) * 32) * NPIX) + bp * 32;
    float* adst = A + ((size_t)b * 256 + bc * 32) * NPIX + bp * 32;
#pragma unroll
    for (int r = 0; r < 4; r++) {
        int c = ty + r * 8;
        float v = src[(size_t)c * NPIX + tx];
        tile[c][tx] = v;
        adst[(size_t)c * NPIX + tx] = v;
    }
    __syncthreads();
    float* dst = C + ((size_t)b * NPIX + bp * 32) * 256 + bc * 32;
#pragma unroll
    for (int r = 0; r < 4; r++) {
        int p = ty + r * 8;
        dst[(size_t)p * 256 + tx] = tile[tx][p];
    }
}

__global__ void __launch_bounds__(256) to_nhwc(const float* __restrict__ in,
                                               float* __restrict__ outp) {
    __shared__ float tile[32][33];
    const int bp = blockIdx.x, bc = blockIdx.y, b = blockIdx.z;
    const int tx = threadIdx.x & 31, ty = threadIdx.x >> 5;
    const float* src = in + ((size_t)b * 256 + bc * 32) * NPIX + bp * 32;
#pragma unroll
    for (int r = 0; r < 4; r++) {
        int c = ty + r * 8;
        tile[c][tx] = src[(size_t)c * NPIX + tx];
    }
    __syncthreads();
    float* dst = outp + ((size_t)b * NPIX + bp * 32) * 256 + bc * 32;
#pragma unroll
    for (int r = 0; r < 4; r++) {
        int p = ty + r * 8;
        dst[(size_t)p * 256 + tx] = tile[tx][p];
    }
}

// ---------------- weight prep: dcn + off fragment packs ----------------
__global__ void prep_weights(const float* __restrict__ dcnw,
                             const float* __restrict__ offw,
                             uint2* __restrict__ BH, uint2* __restrict__ BL,
                             uint2* __restrict__ OBH, uint2* __restrict__ OBL) {
    int idx = blockIdx.x * 256 + threadIdx.x;
    if (idx < 409600) {
        const int t  = idx & 31;
        const int j  = (idx >> 5) & 31;
        const int s  = (idx >> 10) & 7;
        const int gk = idx >> 13;          // 0..49
        const int k = gk % 25, g = gk / 25;
        const int o = j * 8 + (t >> 2);
        const int c0 = s * 16 + 2 * (t & 3);
        float w0 = dcnw[o * 6400 + (g * 128 + c0    ) * 25 + k] * 64.f;
        float w1 = dcnw[o * 6400 + (g * 128 + c0 + 1) * 25 + k] * 64.f;
        float w8 = dcnw[o * 6400 + (g * 128 + c0 + 8) * 25 + k] * 64.f;
        float w9 = dcnw[o * 6400 + (g * 128 + c0 + 9) * 25 + k] * 64.f;
        float h0 = __half2float(__float2half_rn(w0));
        float h1 = __half2float(__float2half_rn(w1));
        float h8 = __half2float(__float2half_rn(w8));
        float h9 = __half2float(__float2half_rn(w9));
        BH[idx] = make_uint2(packh(h0, h1), packh(h8, h9));
        BL[idx] = make_uint2(packh(w0 - h0, w1 - h1), packh(w8 - h8, w9 - h9));
    } else if (idx < 614400) {
        const int i2 = idx - 409600;
        const int t  = i2 & 31;
        const int j  = (i2 >> 5) & 15;
        const int s  = (i2 >> 9) & 7;
        const int it = i2 >> 12;           // 0..49
        const int k = it >> 1, h = it & 1;
        const int o = j * 8 + (t >> 2);
        const int c0 = h * 128 + s * 16 + 2 * (t & 3);
        float w0 = 0.f, w1 = 0.f, w8 = 0.f, w9 = 0.f;
        if (o < 100) {
            w0 = offw[o * 6400 + (c0    ) * 25 + k] * 1024.f;
            w1 = offw[o * 6400 + (c0 + 1) * 25 + k] * 1024.f;
            w8 = offw[o * 6400 + (c0 + 8) * 25 + k] * 1024.f;
            w9 = offw[o * 6400 + (c0 + 9) * 25 + k] * 1024.f;
        }
        float h0 = __half2float(__float2half_rn(w0));
        float h1 = __half2float(__float2half_rn(w1));
        float h8 = __half2float(__float2half_rn(w8));
        float h9 = __half2float(__float2half_rn(w9));
        OBH[i2] = make_uint2(packh(h0, h1), packh(h8, h9));
        OBL[i2] = make_uint2(packh(w0 - h0, w1 - h1), packh(w8 - h8, w9 - h9));
    }
}

__global__ void transpose_redw(const float* __restrict__ w, float* __restrict__ dst) {
    int idx = blockIdx.x * 256 + threadIdx.x;
    int o = idx & 127;
    int c = idx >> 7;
    dst[idx] = w[o * 256 + c];
}

// ---------------- offset conv via mma.sync (implicit GEMM) ----------------
// CTA: 64px x 128o(100 used), 256 thr, grid (256, B). Warp tile 16px x 64o.
__global__ void __launch_bounds__(256, 2) offconv_hmma(
    const float* __restrict__ xh,    // NHWC [b][p][256]
    const uint2* __restrict__ OBH, const uint2* __restrict__ OBL,
    const float* __restrict__ offb,
    float* __restrict__ offout) {
    __shared__ uint32_t Sh[64 * 68];
    __shared__ uint32_t Sl[64 * 68];

    const int tid = threadIdx.x;
    const int lane = tid & 31, warp = tid >> 5;
    const int b = blockIdx.y;
    const int row = blockIdx.x >> 1;
    const int px0 = (blockIdx.x & 1) << 6;

    const int wo = warp & 1;          // o half: base wo*64
    const int wp = warp >> 1;         // px quarter: base wp*16
    // sampler mapping (same as deform)
    const int sh = warp & 1;
    const int cq = warp >> 1;
    const int lg = lane >> 3;
    const int c0s = cq * 32 + (lane & 7) * 4;

    float d[32];
#pragma unroll
    for (int q = 0; q < 32; q++) d[q] = 0.f;

    const float4 zero4 = make_float4(0.f, 0.f, 0.f, 0.f);
    const uint32_t shAddrH = smem_u32(Sh) + (lane & 15) * 272 + (lane >> 4) * 16;
    const uint32_t shAddrL = smem_u32(Sl) + (lane & 15) * 272 + (lane >> 4) * 16;
    const float* xb = xh + (size_t)b * NPIX * 256;

    for (int it = 0; it < 50; it++) {
        const int k = it >> 1, h = it & 1;
        const int kh = k / 5, kw = k % 5;
        const int gy = row + kh - 2;
        const bool vy = (gy >= 0) & (gy < 128);

        __syncthreads();   // previous iteration's mma reads done

        // ---- A tile: shifted NHWC read, fp16 hi/lo split ----
#pragma unroll
        for (int j = 0; j < 8; j++) {
            const int p = sh * 32 + j * 4 + lg;
            const int gx = px0 + p + kw - 2;
            float4 va = zero4;
            if (vy && gx >= 0 && gx < 128)
                va = *(const float4*)(xb + ((size_t)gy * 128 + gx) * 256 + h * 128 + c0s);
            float h0 = __half2float(__float2half_rn(va.x));
            float h1 = __half2float(__float2half_rn(va.y));
            float h2 = __half2float(__float2half_rn(va.z));
            float h3 = __half2float(__float2half_rn(va.w));
            const int wi = p * 68 + (c0s >> 1);
            Sh[wi]     = packh(h0, h1);
            Sh[wi + 1] = packh(h2, h3);
            Sl[wi]     = packh(va.x - h0, va.y - h1);
            Sl[wi + 1] = packh(va.z - h2, va.w - h3);
        }
        __syncthreads();

        // ---- MMA: D[64px][128o] += A[64px][128c] * W[128c][128o] ----
        const uint2* BHt = OBH + ((size_t)it * 8 * 16 + wo * 8) * 32 + lane;
        const uint2* BLt = OBL + ((size_t)it * 8 * 16 + wo * 8) * 32 + lane;
#pragma unroll
        for (int s = 0; s < 8; s++) {
            uint32_t Ah[4], Al[4];
            ldm4(Ah, shAddrH + (wp * 16) * 272 + s * 32);
            ldm4(Al, shAddrL + (wp * 16) * 272 + s * 32);
            const uint2* bh = BHt + (size_t)s * 512;
            const uint2* bl = BLt + (size_t)s * 512;
#pragma unroll
            for (int j2 = 0; j2 < 8; j2++) {
                uint2 Bh = bh[j2 * 32];
                uint2 Bl = bl[j2 * 32];
                float* dd = &d[j2 * 4];
                mma16816(dd[0], dd[1], dd[2], dd[3], Ah, Bh.x, Bh.y);
                mma16816(dd[0], dd[1], dd[2], dd[3], Al, Bh.x, Bh.y);
                mma16816(dd[0], dd[1], dd[2], dd[3], Ah, Bl.x, Bl.y);
            }
        }
    }

    // ---- epilogue: x(1/1024) + bias, write NCHW [b][100][pix] ----
    const int g2 = lane >> 2, tig = lane & 3;
    const int pxl = wp * 16 + g2;
    const size_t outbase = (size_t)row * 128 + px0;
#pragma unroll
    for (int j2 = 0; j2 < 8; j2++) {
        const int o = wo * 64 + j2 * 8 + 2 * tig;
        if (o < 100) {
            const float* dd = &d[j2 * 4];
            const float b0 = offb[o], b1 = offb[o + 1];
            float* y0 = offout + ((size_t)(b * 100 + o)) * NPIX + outbase;
            float* y1 = y0 + NPIX;
            y0[pxl]     = dd[0] * 0.0009765625f + b0;
            y1[pxl]     = dd[1] * 0.0009765625f + b1;
            y0[pxl + 8] = dd[2] * 0.0009765625f + b0;
            y1[pxl + 8] = dd[3] * 0.0009765625f + b1;
        }
    }
}

// ---------------- deformable conv via mma.sync f16-split + BN + ReLU -------
#define SM_SH 6912
#define SM_SL 11264
#define DEF_FLOATS 15616
__global__ void __launch_bounds__(256, 2) deform_hmma(
    const float* __restrict__ xh,    // NHWC [b][p][256]
    const float* __restrict__ off,   // NCHW [b][100][p]
    const uint2* __restrict__ BH, const uint2* __restrict__ BL,
    const float* __restrict__ bng, const float* __restrict__ bnb,
    const float* __restrict__ bnm, const float* __restrict__ bnv,
    float* __restrict__ yout) {
    extern __shared__ float sm[];
    float* sPy = sm;
    float* sPx = sm + 3200;
    float* sBNa = sm + 6400;
    float* sBNb = sm + 6656;
    uint32_t* Sh = (uint32_t*)(sm + SM_SH);
    uint32_t* Sl = (uint32_t*)(sm + SM_SL);

    const int tid = threadIdx.x;
    const int lane = tid & 31, warp = tid >> 5;
    const int b = blockIdx.y;
    const int row = blockIdx.x >> 1;
    const int px0 = (blockIdx.x & 1) << 6;

    const int wo = warp & 3;
    const int wp = warp >> 2;
    const int sh = warp & 1;
    const int cq = warp >> 1;
    const int lg = lane >> 3;
    const int c0s = cq * 32 + (lane & 7) * 4;

    if (tid < 256) {
        float inv = bng[tid] * rsqrtf(bnv[tid] + 1e-5f);
        sBNa[tid] = inv * 0.015625f;
        sBNb[tid] = bnb[tid] - bnm[tid] * inv;
    }
    for (int idx = tid; idx < 3200; idx += 256) {
        int gk = idx >> 6, p = idx & 63;
        int g = gk / 25, k = gk % 25;
        int kh = k / 5, kw = k % 5;
        int ch = b * 100 + g * 50 + 2 * k;
        float oy = off[(size_t)ch * NPIX + row * 128 + px0 + p];
        float ox = off[(size_t)(ch + 1) * NPIX + row * 128 + px0 + p];
        sPy[idx] = (float)(row + kh - 2) + oy;
        sPx[idx] = (float)(px0 + p + kw - 2) + ox;
    }

    float d[64];
#pragma unroll
    for (int q = 0; q < 64; q++) d[q] = 0.f;

    const float4 zero4 = make_float4(0.f, 0.f, 0.f, 0.f);
    const uint32_t shAddrH = smem_u32(Sh) + (lane & 15) * 272 + (lane >> 4) * 16;
    const uint32_t shAddrL = smem_u32(Sl) + (lane & 15) * 272 + (lane >> 4) * 16;

    for (int gk = 0; gk < 50; gk++) {
        const int g = (gk >= 25) ? 1 : 0;
        const float* xgb = xh + (size_t)b * NPIX * 256 + g * 128 + c0s;

        __syncthreads();

#pragma unroll
        for (int j = 0; j < 8; j++) {
            const int p = sh * 32 + j * 4 + lg;
            const float py = sPy[gk * 64 + p];
            const float pv = sPx[gk * 64 + p];
            const float y0f = floorf(py), x0f = floorf(pv);
            const float wy1 = py - y0f, wx1 = pv - x0f;
            const float wy0 = 1.f - wy1, wx0 = 1.f - wx1;
            const float w00 = wy0 * wx0, w01 = wy0 * wx1;
            const float w10 = wy1 * wx0, w11 = wy1 * wx1;
            const int iy = (int)y0f, ix = (int)x0f;
            const bool vy0 = (iy >= 0) & (iy < 128);
            const bool vy1 = (iy >= -1) & (iy < 127);
            const bool vx0 = (ix >= 0) & (ix < 128);
            const bool vx1 = (ix >= -1) & (ix < 127);
            const long base = ((long)iy * 128 + ix) * 256;
            float4 va = (vy0 & vx0) ? *(const float4*)(xgb + base) : zero4;
            float4 vb = (vy0 & vx1) ? *(const float4*)(xgb + base + 256) : zero4;
            float4 vc = (vy1 & vx0) ? *(const float4*)(xgb + base + 128 * 256) : zero4;
            float4 vd4 = (vy1 & vx1) ? *(const float4*)(xgb + base + 128 * 256 + 256) : zero4;
            float r0 = w00 * va.x + w01 * vb.x + w10 * vc.x + w11 * vd4.x;
            float r1 = w00 * va.y + w01 * vb.y + w10 * vc.y + w11 * vd4.y;
            float r2 = w00 * va.z + w01 * vb.z + w10 * vc.z + w11 * vd4.z;
            float r3 = w00 * va.w + w01 * vb.w + w10 * vc.w + w11 * vd4.w;
            float h0 = __half2float(__float2half_rn(r0));
            float h1 = __half2float(__float2half_rn(r1));
            float h2 = __half2float(__float2half_rn(r2));
            float h3 = __half2float(__float2half_rn(r3));
            const int wi = p * 68 + (c0s >> 1);
            Sh[wi]     = packh(h0, h1);
            Sh[wi + 1] = packh(h2, h3);
            Sl[wi]     = packh(r0 - h0, r1 - h1);
            Sl[wi + 1] = packh(r2 - h2, r3 - h3);
        }
        __syncthreads();

        const uint2* BHt = BH + ((size_t)gk * 8 * 32 + wo * 8) * 32 + lane;
        const uint2* BLt = BL + ((size_t)gk * 8 * 32 + wo * 8) * 32 + lane;
#pragma unroll
        for (int s = 0; s < 8; s++) {
            uint32_t Ah[2][4], Al[2][4];
            ldm4(Ah[0], shAddrH + (wp * 32     ) * 272 + s * 32);
            ldm4(Ah[1], shAddrH + (wp * 32 + 16) * 272 + s * 32);
            ldm4(Al[0], shAddrL + (wp * 32     ) * 272 + s * 32);
            ldm4(Al[1], shAddrL + (wp * 32 + 16) * 272 + s * 32);
            const uint2* bh = BHt + (size_t)s * 1024;
            const uint2* bl = BLt + (size_t)s * 1024;
#pragma unroll
            for (int j2 = 0; j2 < 8; j2++) {
                uint2 Bh = bh[j2 * 32];
                uint2 Bl = bl[j2 * 32];
                float* d0 = &d[(0 * 8 + j2) * 4];
                float* d1 = &d[(1 * 8 + j2) * 4];
                mma16816(d0[0], d0[1], d0[2], d0[3], Ah[0], Bh.x, Bh.y);
                mma16816(d1[0], d1[1], d1[2], d1[3], Ah[1], Bh.x, Bh.y);
                mma16816(d0[0], d0[1], d0[2], d0[3], Al[0], Bh.x, Bh.y);
                mma16816(d1[0], d1[1], d1[2], d1[3], Al[1], Bh.x, Bh.y);
                mma16816(d0[0], d0[1], d0[2], d0[3], Ah[0], Bl.x, Bl.y);
                mma16816(d1[0], d1[1], d1[2], d1[3], Ah[1], Bl.x, Bl.y);
            }
        }
    }

    const int g2 = lane >> 2, tig = lane & 3;
    const size_t outbase = (size_t)row * 128 + px0;
#pragma unroll
    for (int mt = 0; mt < 2; mt++) {
#pragma unroll
        for (int j2 = 0; j2 < 8; j2++) {
            const float* dd = &d[(mt * 8 + j2) * 4];
            const int pxl = wp * 32 + mt * 16 + g2;
            const int o = wo * 64 + j2 * 8 + 2 * tig;
            float a0 = sBNa[o], b0v = sBNb[o];
            float a1 = sBNa[o + 1], b1v = sBNb[o + 1];
            float* y0 = yout + ((size_t)(b * 256 + o)) * NPIX + outbase;
            float* y1 = yout + ((size_t)(b * 256 + o + 1)) * NPIX + outbase;
            y0[pxl]     = fmaxf(dd[0] * a0 + b0v, 0.f);
            y1[pxl]     = fmaxf(dd[1] * a1 + b1v, 0.f);
            y0[pxl + 8] = fmaxf(dd[2] * a0 + b0v, 0.f);
            y1[pxl + 8] = fmaxf(dd[3] * a1 + b1v, 0.f);
        }
    }
}

// ---------------- SE / pool / scale ----------------
__global__ void pool_kernel(const float* __restrict__ y, float* __restrict__ pool) {
    int bc = blockIdx.x;
    const float* plane = y + (size_t)bc * NPIX;
    float s = 0.f;
    for (int i = threadIdx.x; i < NPIX; i += 256) s += plane[i];
    __shared__ float red[256];
    red[threadIdx.x] = s;
    __syncthreads();
    for (int st = 128; st > 0; st >>= 1) {
        if (threadIdx.x < st) red[threadIdx.x] += red[threadIdx.x + st];
        __syncthreads();
    }
    if (threadIdx.x == 0) pool[bc] = red[0] * (1.f / NPIX);
}

__global__ void se_kernel(const float* __restrict__ pool,
                          const float* __restrict__ w1,
                          const float* __restrict__ w2,
                          float* __restrict__ scale) {
    int b = blockIdx.x;
    int tid = threadIdx.x;
    __shared__ float sp[256], shd[16];
    sp[tid] = pool[b * 256 + tid];
    __syncthreads();
    if (tid < 16) {
        float a = 0.f;
        for (int c = 0; c < 256; c++) a += sp[c] * w1[tid * 256 + c];
        shd[tid] = fmaxf(a, 0.f);
    }
    __syncthreads();
    float a = 0.f;
#pragma unroll
    for (int j = 0; j < 16; j++) a += shd[j] * w2[tid * 16 + j];
    scale[b * 256 + tid] = 1.f / (1.f + expf(-a));
}

__global__ void scale_kernel(float4* __restrict__ y, const float* __restrict__ sc) {
    int i = blockIdx.x * 256 + threadIdx.x;
    float s = sc[i >> 12];
    float4 v = y[i];
    v.x *= s; v.y *= s; v.z *= s; v.w *= s;
    y[i] = v;
}

// ---------------- final 1x1 conv + BN + ReLU (fma2) ----------------
__global__ void __launch_bounds__(256) final_kernel(
    const float* __restrict__ xin, const float* __restrict__ redT,
    const float* __restrict__ bng, const float* __restrict__ bnb,
    const float* __restrict__ bnm, const float* __restrict__ bnv,
    float* __restrict__ out) {
    const int tid = threadIdx.x;
    const int b = blockIdx.y;
    const int p0 = blockIdx.x * 64;
    const int px = tid & 63, og = tid >> 6;
    __shared__ __align__(16) float sX[8][64];
    __shared__ __align__(16) float sWf[8][128];
    __shared__ float sBN[256];
    if (tid < 128) {
        float inv = bng[tid] * rsqrtf(bnv[tid] + 1e-5f);
        sBN[tid] = inv;
        sBN[128 + tid] = bnb[tid] - bnm[tid] * inv;
    }
    union { unsigned long long u[16]; float f[32]; } acc;
#pragma unroll
    for (int j = 0; j < 16; j++) acc.u[j] = 0ull;

    for (int cb = 0; cb < 256; cb += 8) {
        __syncthreads();
        {
            int i = tid;
            sX[i >> 6][i & 63] = xin[((size_t)(b * 256 + cb + (i >> 6))) * NPIX + p0 + (i & 63)];
            i = tid + 256;
            sX[i >> 6][i & 63] = xin[((size_t)(b * 256 + cb + (i >> 6))) * NPIX + p0 + (i & 63)];
            for (int t = tid; t < 1024; t += 256)
                sWf[t >> 7][t & 127] = redT[(cb + (t >> 7)) * 128 + (t & 127)];
        }
        __syncthreads();
#pragma unroll
        for (int c = 0; c < 8; c++) {
            float xv = sX[c][px];
            unsigned long long xd = pk2(xv, xv);
            const F4* wp = (const F4*)&sWf[c][og * 32];
#pragma unroll
            for (int j = 0; j < 8; j++) {
                F4 w = wp[j];
                fma2(acc.u[2 * j],     xd, w.u[0]);
                fma2(acc.u[2 * j + 1], xd, w.u[1]);
            }
        }
    }
#pragma unroll
    for (int j = 0; j < 32; j++) {
        int o = og * 32 + j;
        float v = acc.f[j] * sBN[o] + sBN[128 + o];
        out[((size_t)(b * 128 + o)) * NPIX + p0 + px] = fmaxf(v, 0.f);
    }
}

// ---------------- launch ----------------
extern "C" void kernel_launch(void* const* d_in, const int* in_sizes, int n_in,
                              void* d_out, int out_size) {
    const float* bev1   = (const float*)d_in[0];
    const float* bev2   = (const float*)d_in[1];
    const float* off_w1 = (const float*)d_in[2];
    const float* off_b1 = (const float*)d_in[3];
    const float* dcn_w1 = (const float*)d_in[4];
    const float* bn1_g  = (const float*)d_in[5];
    const float* bn1_b  = (const float*)d_in[6];
    const float* bn1_m  = (const float*)d_in[7];
    const float* bn1_v  = (const float*)d_in[8];
    const float* se1_w1 = (const float*)d_in[9];
    const float* se1_w2 = (const float*)d_in[10];
    const float* off_w2 = (const float*)d_in[11];
    const float* off_b2 = (const float*)d_in[12];
    const float* dcn_w2 = (const float*)d_in[13];
    const float* bn2_g  = (const float*)d_in[14];
    const float* bn2_b  = (const float*)d_in[15];
    const float* bn2_m  = (const float*)d_in[16];
    const float* bn2_v  = (const float*)d_in[17];
    const float* se2_w1 = (const float*)d_in[18];
    const float* se2_w2 = (const float*)d_in[19];
    const float* red_w  = (const float*)d_in[20];
    const float* bn3_g  = (const float*)d_in[21];
    const float* bn3_b  = (const float*)d_in[22];
    const float* bn3_m  = (const float*)d_in[23];
    const float* bn3_v  = (const float*)d_in[24];

    float *A, *B, *C, *OFF, *RT, *POOL, *SCALE;
    uint2 *BH, *BL, *OBH, *OBL;
    cudaGetSymbolAddress((void**)&A,    g_bufA);
    cudaGetSymbolAddress((void**)&B,    g_bufB);
    cudaGetSymbolAddress((void**)&C,    g_bufC);
    cudaGetSymbolAddress((void**)&OFF,  g_off);
    cudaGetSymbolAddress((void**)&BH,   g_bh);
    cudaGetSymbolAddress((void**)&BL,   g_bl);
    cudaGetSymbolAddress((void**)&OBH,  g_obh);
    cudaGetSymbolAddress((void**)&OBL,  g_obl);
    cudaGetSymbolAddress((void**)&RT,   g_rT);
    cudaGetSymbolAddress((void**)&POOL, g_pool);
    cudaGetSymbolAddress((void**)&SCALE,g_scale);

    const int DEF_SMEM = DEF_FLOATS * 4;
    cudaFuncSetAttribute(deform_hmma,
                         cudaFuncAttributeMaxDynamicSharedMemorySize, DEF_SMEM);

    // ---- stage 1 ----
    concat_nhwc<<<dim3(512, 8, 4), 256>>>(bev1, bev2, A, C);
    prep_weights<<<2400, 256>>>(dcn_w1, off_w1, BH, BL, OBH, OBL);
    offconv_hmma<<<dim3(256, 4), 256>>>(C, OBH, OBL, off_b1, OFF);
    deform_hmma<<<dim3(256, 4), 256, DEF_SMEM>>>(C, OFF, BH, BL,
                                                 bn1_g, bn1_b, bn1_m, bn1_v, B);
    pool_kernel<<<1024, 256>>>(B, POOL);
    se_kernel<<<4, 256>>>(POOL, se1_w1, se1_w2, SCALE);
    scale_kernel<<<16384, 256>>>((float4*)B, SCALE);

    // ---- stage 2 ----
    to_nhwc<<<dim3(512, 8, 4), 256>>>(B, C);
    prep_weights<<<2400, 256>>>(dcn_w2, off_w2, BH, BL, OBH, OBL);
    offconv_hmma<<<dim3(256, 4), 256>>>(C, OBH, OBL, off_b2, OFF);
    deform_hmma<<<dim3(256, 4), 256, DEF_SMEM>>>(C, OFF, BH, BL,
                                                 bn2_g, bn2_b, bn2_m, bn2_v, A);
    pool_kernel<<<1024, 256>>>(A, POOL);
    se_kernel<<<4, 256>>>(POOL, se2_w1, se2_w2, SCALE);
    scale_kernel<<<16384, 256>>>((float4*)A, SCALE);

    // ---- final ----
    transpose_redw<<<128, 256>>>(red_w, RT);
    final_kernel<<<dim3(256, 4), 256>>>(A, RT, bn3_g, bn3_b, bn3_m, bn3_v, (float*)d_out);
}

// round 9
// speedup vs baseline: 4.1201x; 1.0933x over previous
#include <cuda_runtime.h>
#include <cuda_fp16.h>
#include <math.h>
#include <stdint.h>

// ---------------- packed f32x2 helpers (final conv) ----------------
__device__ __forceinline__ unsigned long long pk2(float x, float y) {
    unsigned long long r;
    asm("mov.b64 %0, {%1, %2};" : "=l"(r) : "f"(x), "f"(y));
    return r;
}
__device__ __forceinline__ void fma2(unsigned long long& d,
                                     unsigned long long a, unsigned long long b) {
    asm("fma.rn.f32x2 %0, %1, %2, %0;" : "+l"(d) : "l"(a), "l"(b));
}
union F4 { float4 v; float f[4]; unsigned long long u[2]; };

// ---------------- mma.sync helpers ----------------
__device__ __forceinline__ void ldm4(uint32_t* r, uint32_t addr) {
    asm volatile("ldmatrix.sync.aligned.m8n8.x4.shared.b16 {%0,%1,%2,%3}, [%4];"
                 : "=r"(r[0]), "=r"(r[1]), "=r"(r[2]), "=r"(r[3]) : "r"(addr));
}
__device__ __forceinline__ void mma16816(float& d0, float& d1, float& d2, float& d3,
                                         const uint32_t* a, uint32_t b0, uint32_t b1) {
    asm volatile(
        "mma.sync.aligned.m16n8k16.row.col.f32.f16.f16.f32 "
        "{%0,%1,%2,%3}, {%4,%5,%6,%7}, {%8,%9}, {%0,%1,%2,%3};"
        : "+f"(d0), "+f"(d1), "+f"(d2), "+f"(d3)
        : "r"(a[0]), "r"(a[1]), "r"(a[2]), "r"(a[3]), "r"(b0), "r"(b1));
}
__device__ __forceinline__ uint32_t smem_u32(const void* p) {
    uint32_t a;
    asm("{ .reg .u64 t; cvta.to.shared.u64 t, %1; cvt.u32.u64 %0, t; }"
        : "=r"(a) : "l"(p));
    return a;
}
__device__ __forceinline__ uint32_t packh(float a, float b) {
    __half2 h = __halves2half2(__float2half_rn(a), __float2half_rn(b));
    return *(uint32_t*)&h;
}

// ---------------- scratch ----------------
#define NPIX 16384
__device__ __align__(16) float g_bufA[4 * 256 * NPIX];
__device__ __align__(16) float g_bufB[4 * 256 * NPIX];
__device__ __align__(16) float g_bufC[4 * 256 * NPIX];
__device__ __align__(16) float g_off [4 * 100 * NPIX];
__device__ __align__(16) uint2 g_bh  [50 * 8 * 32 * 32];   // dcn B frags hi
__device__ __align__(16) uint2 g_bl  [50 * 8 * 32 * 32];   // dcn B frags lo
__device__ __align__(16) uint2 g_obh [50 * 8 * 16 * 32];   // off B frags hi
__device__ __align__(16) uint2 g_obl [50 * 8 * 16 * 32];   // off B frags lo
__device__ __align__(16) float g_rT  [256 * 128];
__device__ float g_pool[1024];
__device__ float g_scale[1024];

// ---------------- fused concat -> NCHW A + NHWC C ----------------
__global__ void __launch_bounds__(256) concat_nhwc(
    const float* __restrict__ bev1, const float* __restrict__ bev2,
    float* __restrict__ A, float* __restrict__ C) {
    __shared__ float tile[32][33];
    const int bp = blockIdx.x, bc = blockIdx.y, b = blockIdx.z;
    const int tx = threadIdx.x & 31, ty = threadIdx.x >> 5;
    const float* src = ((bc < 4)
        ? bev1 + ((size_t)b * 128 + bc * 32) * NPIX
        : bev2 + ((size_t)b * 128 + (bc - 4) * 32) * NPIX) + bp * 32;
    float* adst = A + ((size_t)b * 256 + bc * 32) * NPIX + bp * 32;
#pragma unroll
    for (int r = 0; r < 4; r++) {
        int c = ty + r * 8;
        float v = src[(size_t)c * NPIX + tx];
        tile[c][tx] = v;
        adst[(size_t)c * NPIX + tx] = v;
    }
    __syncthreads();
    float* dst = C + ((size_t)b * NPIX + bp * 32) * 256 + bc * 32;
#pragma unroll
    for (int r = 0; r < 4; r++) {
        int p = ty + r * 8;
        dst[(size_t)p * 256 + tx] = tile[tx][p];
    }
}

__global__ void __launch_bounds__(256) to_nhwc(const float* __restrict__ in,
                                               float* __restrict__ outp) {
    __shared__ float tile[32][33];
    const int bp = blockIdx.x, bc = blockIdx.y, b = blockIdx.z;
    const int tx = threadIdx.x & 31, ty = threadIdx.x >> 5;
    const float* src = in + ((size_t)b * 256 + bc * 32) * NPIX + bp * 32;
#pragma unroll
    for (int r = 0; r < 4; r++) {
        int c = ty + r * 8;
        tile[c][tx] = src[(size_t)c * NPIX + tx];
    }
    __syncthreads();
    float* dst = outp + ((size_t)b * NPIX + bp * 32) * 256 + bc * 32;
#pragma unroll
    for (int r = 0; r < 4; r++) {
        int p = ty + r * 8;
        dst[(size_t)p * 256 + tx] = tile[tx][p];
    }
}

// ---------------- weight prep: dcn + off fragment packs ----------------
__global__ void prep_weights(const float* __restrict__ dcnw,
                             const float* __restrict__ offw,
                             uint2* __restrict__ BH, uint2* __restrict__ BL,
                             uint2* __restrict__ OBH, uint2* __restrict__ OBL) {
    int idx = blockIdx.x * 256 + threadIdx.x;
    if (idx < 409600) {
        const int t  = idx & 31;
        const int j  = (idx >> 5) & 31;
        const int s  = (idx >> 10) & 7;
        const int gk = idx >> 13;          // 0..49
        const int k = gk % 25, g = gk / 25;
        const int o = j * 8 + (t >> 2);
        const int c0 = s * 16 + 2 * (t & 3);
        float w0 = dcnw[o * 6400 + (g * 128 + c0    ) * 25 + k] * 64.f;
        float w1 = dcnw[o * 6400 + (g * 128 + c0 + 1) * 25 + k] * 64.f;
        float w8 = dcnw[o * 6400 + (g * 128 + c0 + 8) * 25 + k] * 64.f;
        float w9 = dcnw[o * 6400 + (g * 128 + c0 + 9) * 25 + k] * 64.f;
        float h0 = __half2float(__float2half_rn(w0));
        float h1 = __half2float(__float2half_rn(w1));
        float h8 = __half2float(__float2half_rn(w8));
        float h9 = __half2float(__float2half_rn(w9));
        BH[idx] = make_uint2(packh(h0, h1), packh(h8, h9));
        BL[idx] = make_uint2(packh(w0 - h0, w1 - h1), packh(w8 - h8, w9 - h9));
    } else if (idx < 614400) {
        const int i2 = idx - 409600;
        const int t  = i2 & 31;
        const int j  = (i2 >> 5) & 15;
        const int s  = (i2 >> 9) & 7;
        const int it = i2 >> 12;           // 0..49
        const int k = it >> 1, h = it & 1;
        const int o = j * 8 + (t >> 2);
        const int c0 = h * 128 + s * 16 + 2 * (t & 3);
        float w0 = 0.f, w1 = 0.f, w8 = 0.f, w9 = 0.f;
        if (o < 100) {
            w0 = offw[o * 6400 + (c0    ) * 25 + k] * 1024.f;
            w1 = offw[o * 6400 + (c0 + 1) * 25 + k] * 1024.f;
            w8 = offw[o * 6400 + (c0 + 8) * 25 + k] * 1024.f;
            w9 = offw[o * 6400 + (c0 + 9) * 25 + k] * 1024.f;
        }
        float h0 = __half2float(__float2half_rn(w0));
        float h1 = __half2float(__float2half_rn(w1));
        float h8 = __half2float(__float2half_rn(w8));
        float h9 = __half2float(__float2half_rn(w9));
        OBH[i2] = make_uint2(packh(h0, h1), packh(h8, h9));
        OBL[i2] = make_uint2(packh(w0 - h0, w1 - h1), packh(w8 - h8, w9 - h9));
    }
}

__global__ void transpose_redw(const float* __restrict__ w, float* __restrict__ dst) {
    int idx = blockIdx.x * 256 + threadIdx.x;
    int o = idx & 127;
    int c = idx >> 7;
    dst[idx] = w[o * 256 + c];
}

// ---------------- offset conv via mma.sync (2-product split) ----------------
// CTA: 64px x 128o(100 used), 256 thr, grid (256, B). Warp tile 16px x 64o.
__global__ void __launch_bounds__(256, 2) offconv_hmma(
    const float* __restrict__ xh,    // NHWC [b][p][256]
    const uint2* __restrict__ OBH, const uint2* __restrict__ OBL,
    const float* __restrict__ offb,
    float* __restrict__ offout) {
    __shared__ __align__(16) uint32_t Sh[64 * 68];
    __shared__ __align__(16) uint32_t Sl[64 * 68];

    const int tid = threadIdx.x;
    const int lane = tid & 31, warp = tid >> 5;
    const int b = blockIdx.y;
    const int row = blockIdx.x >> 1;
    const int px0 = (blockIdx.x & 1) << 6;

    const int wo = warp & 1;
    const int wp = warp >> 1;
    const int sh = warp & 1;
    const int cq = warp >> 1;
    const int lg = lane >> 3;
    const int c0s = cq * 32 + (lane & 7) * 4;

    float d[32];
#pragma unroll
    for (int q = 0; q < 32; q++) d[q] = 0.f;

    const float4 zero4 = make_float4(0.f, 0.f, 0.f, 0.f);
    const uint32_t shAddrH = smem_u32(Sh) + (lane & 15) * 272 + (lane >> 4) * 16;
    const uint32_t shAddrL = smem_u32(Sl) + (lane & 15) * 272 + (lane >> 4) * 16;
    const float* xb = xh + (size_t)b * NPIX * 256;

    for (int it = 0; it < 50; it++) {
        const int k = it >> 1, h = it & 1;
        const int kh = k / 5, kw = k % 5;
        const int gy = row + kh - 2;
        const bool vy = (gy >= 0) & (gy < 128);

        __syncthreads();

#pragma unroll
        for (int j = 0; j < 8; j++) {
            const int p = sh * 32 + j * 4 + lg;
            const int gx = px0 + p + kw - 2;
            float4 va = zero4;
            if (vy && gx >= 0 && gx < 128)
                va = *(const float4*)(xb + ((size_t)gy * 128 + gx) * 256 + h * 128 + c0s);
            float h0 = __half2float(__float2half_rn(va.x));
            float h1 = __half2float(__float2half_rn(va.y));
            float h2 = __half2float(__float2half_rn(va.z));
            float h3 = __half2float(__float2half_rn(va.w));
            const int wi = p * 68 + (c0s >> 1);
            *(uint2*)&Sh[wi] = make_uint2(packh(h0, h1), packh(h2, h3));
            *(uint2*)&Sl[wi] = make_uint2(packh(va.x - h0, va.y - h1),
                                          packh(va.z - h2, va.w - h3));
        }
        __syncthreads();

        // ---- MMA (2 products: AhBh + AlBh) ----
        const uint2* BHt = OBH + ((size_t)it * 8 * 16 + wo * 8) * 32 + lane;
#pragma unroll
        for (int s = 0; s < 8; s++) {
            uint32_t Ah[4], Al[4];
            ldm4(Ah, shAddrH + (wp * 16) * 272 + s * 32);
            ldm4(Al, shAddrL + (wp * 16) * 272 + s * 32);
            const uint2* bh = BHt + (size_t)s * 512;
#pragma unroll
            for (int j2 = 0; j2 < 8; j2++) {
                uint2 Bh = bh[j2 * 32];
                float* dd = &d[j2 * 4];
                mma16816(dd[0], dd[1], dd[2], dd[3], Ah, Bh.x, Bh.y);
                mma16816(dd[0], dd[1], dd[2], dd[3], Al, Bh.x, Bh.y);
            }
        }
    }

    const int g2 = lane >> 2, tig = lane & 3;
    const int pxl = wp * 16 + g2;
    const size_t outbase = (size_t)row * 128 + px0;
#pragma unroll
    for (int j2 = 0; j2 < 8; j2++) {
        const int o = wo * 64 + j2 * 8 + 2 * tig;
        if (o < 100) {
            const float* dd = &d[j2 * 4];
            const float b0 = offb[o], b1 = offb[o + 1];
            float* y0 = offout + ((size_t)(b * 100 + o)) * NPIX + outbase;
            float* y1 = y0 + NPIX;
            y0[pxl]     = dd[0] * 0.0009765625f + b0;
            y1[pxl]     = dd[1] * 0.0009765625f + b1;
            y0[pxl + 8] = dd[2] * 0.0009765625f + b0;
            y1[pxl + 8] = dd[3] * 0.0009765625f + b1;
        }
    }
}

// ---------------- deformable conv via mma.sync f16-split + BN + ReLU -------
#define SM_SH 6912
#define SM_SL 11264
#define DEF_FLOATS 15616
__global__ void __launch_bounds__(256, 2) deform_hmma(
    const float* __restrict__ xh,    // NHWC [b][p][256]
    const float* __restrict__ off,   // NCHW [b][100][p]
    const uint2* __restrict__ BH, const uint2* __restrict__ BL,
    const float* __restrict__ bng, const float* __restrict__ bnb,
    const float* __restrict__ bnm, const float* __restrict__ bnv,
    float* __restrict__ yout) {
    extern __shared__ float sm[];
    float* sPy = sm;
    float* sPx = sm + 3200;
    float* sBNa = sm + 6400;
    float* sBNb = sm + 6656;
    uint32_t* Sh = (uint32_t*)(sm + SM_SH);
    uint32_t* Sl = (uint32_t*)(sm + SM_SL);

    const int tid = threadIdx.x;
    const int lane = tid & 31, warp = tid >> 5;
    const int b = blockIdx.y;
    const int row = blockIdx.x >> 1;
    const int px0 = (blockIdx.x & 1) << 6;

    const int wo = warp & 3;
    const int wp = warp >> 2;
    const int sh = warp & 1;
    const int cq = warp >> 1;
    const int lg = lane >> 3;
    const int c0s = cq * 32 + (lane & 7) * 4;

    if (tid < 256) {
        float inv = bng[tid] * rsqrtf(bnv[tid] + 1e-5f);
        sBNa[tid] = inv * 0.015625f;
        sBNb[tid] = bnb[tid] - bnm[tid] * inv;
    }
    for (int idx = tid; idx < 3200; idx += 256) {
        int gk = idx >> 6, p = idx & 63;
        int g = gk / 25, k = gk % 25;
        int kh = k / 5, kw = k % 5;
        int ch = b * 100 + g * 50 + 2 * k;
        float oy = off[(size_t)ch * NPIX + row * 128 + px0 + p];
        float ox = off[(size_t)(ch + 1) * NPIX + row * 128 + px0 + p];
        sPy[idx] = (float)(row + kh - 2) + oy;
        sPx[idx] = (float)(px0 + p + kw - 2) + ox;
    }

    float d[64];
#pragma unroll
    for (int q = 0; q < 64; q++) d[q] = 0.f;

    const float4 zero4 = make_float4(0.f, 0.f, 0.f, 0.f);
    const uint32_t shAddrH = smem_u32(Sh) + (lane & 15) * 272 + (lane >> 4) * 16;
    const uint32_t shAddrL = smem_u32(Sl) + (lane & 15) * 272 + (lane >> 4) * 16;

    for (int gk = 0; gk < 50; gk++) {
        const int g = (gk >= 25) ? 1 : 0;
        const float* xgb = xh + (size_t)b * NPIX * 256 + g * 128 + c0s;

        __syncthreads();

#pragma unroll
        for (int j = 0; j < 8; j++) {
            const int p = sh * 32 + j * 4 + lg;
            const float py = sPy[gk * 64 + p];
            const float pv = sPx[gk * 64 + p];
            const float y0f = floorf(py), x0f = floorf(pv);
            const float wy1 = py - y0f, wx1 = pv - x0f;
            const float wy0 = 1.f - wy1, wx0 = 1.f - wx1;
            const float w00 = wy0 * wx0, w01 = wy0 * wx1;
            const float w10 = wy1 * wx0, w11 = wy1 * wx1;
            const int iy = (int)y0f, ix = (int)x0f;
            const bool vy0 = (iy >= 0) & (iy < 128);
            const bool vy1 = (iy >= -1) & (iy < 127);
            const bool vx0 = (ix >= 0) & (ix < 128);
            const bool vx1 = (ix >= -1) & (ix < 127);
            const long base = ((long)iy * 128 + ix) * 256;
            float4 va = (vy0 & vx0) ? *(const float4*)(xgb + base) : zero4;
            float4 vb = (vy0 & vx1) ? *(const float4*)(xgb + base + 256) : zero4;
            float4 vc = (vy1 & vx0) ? *(const float4*)(xgb + base + 128 * 256) : zero4;
            float4 vd4 = (vy1 & vx1) ? *(const float4*)(xgb + base + 128 * 256 + 256) : zero4;
            float r0 = w00 * va.x + w01 * vb.x + w10 * vc.x + w11 * vd4.x;
            float r1 = w00 * va.y + w01 * vb.y + w10 * vc.y + w11 * vd4.y;
            float r2 = w00 * va.z + w01 * vb.z + w10 * vc.z + w11 * vd4.z;
            float r3 = w00 * va.w + w01 * vb.w + w10 * vc.w + w11 * vd4.w;
            float h0 = __half2float(__float2half_rn(r0));
            float h1 = __half2float(__float2half_rn(r1));
            float h2 = __half2float(__float2half_rn(r2));
            float h3 = __half2float(__float2half_rn(r3));
            const int wi = p * 68 + (c0s >> 1);
            *(uint2*)&Sh[wi] = make_uint2(packh(h0, h1), packh(h2, h3));
            *(uint2*)&Sl[wi] = make_uint2(packh(r0 - h0, r1 - h1),
                                          packh(r2 - h2, r3 - h3));
        }
        __syncthreads();

        const uint2* BHt = BH + ((size_t)gk * 8 * 32 + wo * 8) * 32 + lane;
        const uint2* BLt = BL + ((size_t)gk * 8 * 32 + wo * 8) * 32 + lane;
#pragma unroll
        for (int s = 0; s < 8; s++) {
            uint32_t Ah[2][4], Al[2][4];
            ldm4(Ah[0], shAddrH + (wp * 32     ) * 272 + s * 32);
            ldm4(Ah[1], shAddrH + (wp * 32 + 16) * 272 + s * 32);
            ldm4(Al[0], shAddrL + (wp * 32     ) * 272 + s * 32);
            ldm4(Al[1], shAddrL + (wp * 32 + 16) * 272 + s * 32);
            const uint2* bh = BHt + (size_t)s * 1024;
            const uint2* bl = BLt + (size_t)s * 1024;
#pragma unroll
            for (int j2 = 0; j2 < 8; j2++) {
                uint2 Bh = bh[j2 * 32];
                uint2 Bl = bl[j2 * 32];
                float* d0 = &d[(0 * 8 + j2) * 4];
                float* d1 = &d[(1 * 8 + j2) * 4];
                mma16816(d0[0], d0[1], d0[2], d0[3], Ah[0], Bh.x, Bh.y);
                mma16816(d1[0], d1[1], d1[2], d1[3], Ah[1], Bh.x, Bh.y);
                mma16816(d0[0], d0[1], d0[2], d0[3], Al[0], Bh.x, Bh.y);
                mma16816(d1[0], d1[1], d1[2], d1[3], Al[1], Bh.x, Bh.y);
                mma16816(d0[0], d0[1], d0[2], d0[3], Ah[0], Bl.x, Bl.y);
                mma16816(d1[0], d1[1], d1[2], d1[3], Ah[1], Bl.x, Bl.y);
            }
        }
    }

    const int g2 = lane >> 2, tig = lane & 3;
    const size_t outbase = (size_t)row * 128 + px0;
#pragma unroll
    for (int mt = 0; mt < 2; mt++) {
#pragma unroll
        for (int j2 = 0; j2 < 8; j2++) {
            const float* dd = &d[(mt * 8 + j2) * 4];
            const int pxl = wp * 32 + mt * 16 + g2;
            const int o = wo * 64 + j2 * 8 + 2 * tig;
            float a0 = sBNa[o], b0v = sBNb[o];
            float a1 = sBNa[o + 1], b1v = sBNb[o + 1];
            float* y0 = yout + ((size_t)(b * 256 + o)) * NPIX + outbase;
            float* y1 = yout + ((size_t)(b * 256 + o + 1)) * NPIX + outbase;
            y0[pxl]     = fmaxf(dd[0] * a0 + b0v, 0.f);
            y1[pxl]     = fmaxf(dd[1] * a1 + b1v, 0.f);
            y0[pxl + 8] = fmaxf(dd[2] * a0 + b0v, 0.f);
            y1[pxl + 8] = fmaxf(dd[3] * a1 + b1v, 0.f);
        }
    }
}

// ---------------- SE / pool / scale ----------------
__global__ void pool_kernel(const float* __restrict__ y, float* __restrict__ pool) {
    int bc = blockIdx.x;
    const float* plane = y + (size_t)bc * NPIX;
    float s = 0.f;
    for (int i = threadIdx.x; i < NPIX; i += 256) s += plane[i];
    __shared__ float red[256];
    red[threadIdx.x] = s;
    __syncthreads();
    for (int st = 128; st > 0; st >>= 1) {
        if (threadIdx.x < st) red[threadIdx.x] += red[threadIdx.x + st];
        __syncthreads();
    }
    if (threadIdx.x == 0) pool[bc] = red[0] * (1.f / NPIX);
}

__global__ void se_kernel(const float* __restrict__ pool,
                          const float* __restrict__ w1,
                          const float* __restrict__ w2,
                          float* __restrict__ scale) {
    int b = blockIdx.x;
    int tid = threadIdx.x;
    __shared__ float sp[256], shd[16];
    sp[tid] = pool[b * 256 + tid];
    __syncthreads();
    if (tid < 16) {
        float a = 0.f;
        for (int c = 0; c < 256; c++) a += sp[c] * w1[tid * 256 + c];
        shd[tid] = fmaxf(a, 0.f);
    }
    __syncthreads();
    float a = 0.f;
#pragma unroll
    for (int j = 0; j < 16; j++) a += shd[j] * w2[tid * 16 + j];
    scale[b * 256 + tid] = 1.f / (1.f + expf(-a));
}

__global__ void scale_kernel(float4* __restrict__ y, const float* __restrict__ sc) {
    int i = blockIdx.x * 256 + threadIdx.x;
    float s = sc[i >> 12];
    float4 v = y[i];
    v.x *= s; v.y *= s; v.z *= s; v.w *= s;
    y[i] = v;
}

// ---------------- final 1x1 conv + BN + ReLU (fma2) ----------------
__global__ void __launch_bounds__(256) final_kernel(
    const float* __restrict__ xin, const float* __restrict__ redT,
    const float* __restrict__ bng, const float* __restrict__ bnb,
    const float* __restrict__ bnm, const float* __restrict__ bnv,
    float* __restrict__ out) {
    const int tid = threadIdx.x;
    const int b = blockIdx.y;
    const int p0 = blockIdx.x * 64;
    const int px = tid & 63, og = tid >> 6;
    __shared__ __align__(16) float sX[8][64];
    __shared__ __align__(16) float sWf[8][128];
    __shared__ float sBN[256];
    if (tid < 128) {
        float inv = bng[tid] * rsqrtf(bnv[tid] + 1e-5f);
        sBN[tid] = inv;
        sBN[128 + tid] = bnb[tid] - bnm[tid] * inv;
    }
    union { unsigned long long u[16]; float f[32]; } acc;
#pragma unroll
    for (int j = 0; j < 16; j++) acc.u[j] = 0ull;

    for (int cb = 0; cb < 256; cb += 8) {
        __syncthreads();
        {
            int i = tid;
            sX[i >> 6][i & 63] = xin[((size_t)(b * 256 + cb + (i >> 6))) * NPIX + p0 + (i & 63)];
            i = tid + 256;
            sX[i >> 6][i & 63] = xin[((size_t)(b * 256 + cb + (i >> 6))) * NPIX + p0 + (i & 63)];
            for (int t = tid; t < 1024; t += 256)
                sWf[t >> 7][t & 127] = redT[(cb + (t >> 7)) * 128 + (t & 127)];
        }
        __syncthreads();
#pragma unroll
        for (int c = 0; c < 8; c++) {
            float xv = sX[c][px];
            unsigned long long xd = pk2(xv, xv);
            const F4* wp = (const F4*)&sWf[c][og * 32];
#pragma unroll
            for (int j = 0; j < 8; j++) {
                F4 w = wp[j];
                fma2(acc.u[2 * j],     xd, w.u[0]);
                fma2(acc.u[2 * j + 1], xd, w.u[1]);
            }
        }
    }
#pragma unroll
    for (int j = 0; j < 32; j++) {
        int o = og * 32 + j;
        float v = acc.f[j] * sBN[o] + sBN[128 + o];
        out[((size_t)(b * 128 + o)) * NPIX + p0 + px] = fmaxf(v, 0.f);
    }
}

// ---------------- launch ----------------
extern "C" void kernel_launch(void* const* d_in, const int* in_sizes, int n_in,
                              void* d_out, int out_size) {
    const float* bev1   = (const float*)d_in[0];
    const float* bev2   = (const float*)d_in[1];
    const float* off_w1 = (const float*)d_in[2];
    const float* off_b1 = (const float*)d_in[3];
    const float* dcn_w1 = (const float*)d_in[4];
    const float* bn1_g  = (const float*)d_in[5];
    const float* bn1_b  = (const float*)d_in[6];
    const float* bn1_m  = (const float*)d_in[7];
    const float* bn1_v  = (const float*)d_in[8];
    const float* se1_w1 = (const float*)d_in[9];
    const float* se1_w2 = (const float*)d_in[10];
    const float* off_w2 = (const float*)d_in[11];
    const float* off_b2 = (const float*)d_in[12];
    const float* dcn_w2 = (const float*)d_in[13];
    const float* bn2_g  = (const float*)d_in[14];
    const float* bn2_b  = (const float*)d_in[15];
    const float* bn2_m  = (const float*)d_in[16];
    const float* bn2_v  = (const float*)d_in[17];
    const float* se2_w1 = (const float*)d_in[18];
    const float* se2_w2 = (const float*)d_in[19];
    const float* red_w  = (const float*)d_in[20];
    const float* bn3_g  = (const float*)d_in[21];
    const float* bn3_b  = (const float*)d_in[22];
    const float* bn3_m  = (const float*)d_in[23];
    const float* bn3_v  = (const float*)d_in[24];

    float *A, *B, *C, *OFF, *RT, *POOL, *SCALE;
    uint2 *BH, *BL, *OBH, *OBL;
    cudaGetSymbolAddress((void**)&A,    g_bufA);
    cudaGetSymbolAddress((void**)&B,    g_bufB);
    cudaGetSymbolAddress((void**)&C,    g_bufC);
    cudaGetSymbolAddress((void**)&OFF,  g_off);
    cudaGetSymbolAddress((void**)&BH,   g_bh);
    cudaGetSymbolAddress((void**)&BL,   g_bl);
    cudaGetSymbolAddress((void**)&OBH,  g_obh);
    cudaGetSymbolAddress((void**)&OBL,  g_obl);
    cudaGetSymbolAddress((void**)&RT,   g_rT);
    cudaGetSymbolAddress((void**)&POOL, g_pool);
    cudaGetSymbolAddress((void**)&SCALE,g_scale);

    const int DEF_SMEM = DEF_FLOATS * 4;
    cudaFuncSetAttribute(deform_hmma,
                         cudaFuncAttributeMaxDynamicSharedMemorySize, DEF_SMEM);

    // ---- stage 1 ----
    concat_nhwc<<<dim3(512, 8, 4), 256>>>(bev1, bev2, A, C);
    prep_weights<<<2400, 256>>>(dcn_w1, off_w1, BH, BL, OBH, OBL);
    offconv_hmma<<<dim3(256, 4), 256>>>(C, OBH, OBL, off_b1, OFF);
    deform_hmma<<<dim3(256, 4), 256, DEF_SMEM>>>(C, OFF, BH, BL,
                                                 bn1_g, bn1_b, bn1_m, bn1_v, B);
    pool_kernel<<<1024, 256>>>(B, POOL);
    se_kernel<<<4, 256>>>(POOL, se1_w1, se1_w2, SCALE);
    scale_kernel<<<16384, 256>>>((float4*)B, SCALE);

    // ---- stage 2 ----
    to_nhwc<<<dim3(512, 8, 4), 256>>>(B, C);
    prep_weights<<<2400, 256>>>(dcn_w2, off_w2, BH, BL, OBH, OBL);
    offconv_hmma<<<dim3(256, 4), 256>>>(C, OBH, OBL, off_b2, OFF);
    deform_hmma<<<dim3(256, 4), 256, DEF_SMEM>>>(C, OFF, BH, BL,
                                                 bn2_g, bn2_b, bn2_m, bn2_v, A);
    pool_kernel<<<1024, 256>>>(A, POOL);
    se_kernel<<<4, 256>>>(POOL, se2_w1, se2_w2, SCALE);
    scale_kernel<<<16384, 256>>>((float4*)A, SCALE);

    // ---- final ----
    transpose_redw<<<128, 256>>>(red_w, RT);
    final_kernel<<<dim3(256, 4), 256>>>(A, RT, bn3_g, bn3_b, bn3_m, bn3_v, (float*)d_out);
}

// round 10
// speedup vs baseline: 4.1500x; 1.0073x over previous
#include <cuda_runtime.h>
#include <cuda_fp16.h>
#include <math.h>
#include <stdint.h>

// ---------------- packed f32x2 helpers (final conv) ----------------
__device__ __forceinline__ unsigned long long pk2(float x, float y) {
    unsigned long long r;
    asm("mov.b64 %0, {%1, %2};" : "=l"(r) : "f"(x), "f"(y));
    return r;
}
__device__ __forceinline__ void fma2(unsigned long long& d,
                                     unsigned long long a, unsigned long long b) {
    asm("fma.rn.f32x2 %0, %1, %2, %0;" : "+l"(d) : "l"(a), "l"(b));
}
union F4 { float4 v; float f[4]; unsigned long long u[2]; };

// ---------------- mma.sync helpers ----------------
__device__ __forceinline__ void ldm4(uint32_t* r, uint32_t addr) {
    asm volatile("ldmatrix.sync.aligned.m8n8.x4.shared.b16 {%0,%1,%2,%3}, [%4];"
                 : "=r"(r[0]), "=r"(r[1]), "=r"(r[2]), "=r"(r[3]) : "r"(addr));
}
__device__ __forceinline__ void mma16816(float& d0, float& d1, float& d2, float& d3,
                                         const uint32_t* a, uint32_t b0, uint32_t b1) {
    asm volatile(
        "mma.sync.aligned.m16n8k16.row.col.f32.f16.f16.f32 "
        "{%0,%1,%2,%3}, {%4,%5,%6,%7}, {%8,%9}, {%0,%1,%2,%3};"
        : "+f"(d0), "+f"(d1), "+f"(d2), "+f"(d3)
        : "r"(a[0]), "r"(a[1]), "r"(a[2]), "r"(a[3]), "r"(b0), "r"(b1));
}
__device__ __forceinline__ uint32_t smem_u32(const void* p) {
    uint32_t a;
    asm("{ .reg .u64 t; cvta.to.shared.u64 t, %1; cvt.u32.u64 %0, t; }"
        : "=r"(a) : "l"(p));
    return a;
}
__device__ __forceinline__ uint32_t packh(float a, float b) {
    __half2 h = __halves2half2(__float2half_rn(a), __float2half_rn(b));
    return *(uint32_t*)&h;
}

// single extern smem symbol shared by kernels
extern __shared__ float smext[];

// ---------------- scratch ----------------
#define NPIX 16384
__device__ __align__(16) float g_bufA[4 * 256 * NPIX];
__device__ __align__(16) float g_bufB[4 * 256 * NPIX];
__device__ __align__(16) float g_bufC[4 * 256 * NPIX];
__device__ __align__(16) float g_off [4 * 100 * NPIX];
__device__ __align__(16) uint2 g_bh  [50 * 8 * 32 * 32];
__device__ __align__(16) uint2 g_bl  [50 * 8 * 32 * 32];
__device__ __align__(16) uint2 g_obh [50 * 8 * 16 * 32];
__device__ __align__(16) uint2 g_obl [50 * 8 * 16 * 32];
__device__ __align__(16) float g_rT  [256 * 128];
__device__ float g_pool[1024];
__device__ float g_scale[1024];

// ---------------- fused concat -> NCHW A + NHWC C ----------------
__global__ void __launch_bounds__(256) concat_nhwc(
    const float* __restrict__ bev1, const float* __restrict__ bev2,
    float* __restrict__ A, float* __restrict__ C) {
    __shared__ float tile[32][33];
    const int bp = blockIdx.x, bc = blockIdx.y, b = blockIdx.z;
    const int tx = threadIdx.x & 31, ty = threadIdx.x >> 5;
    const float* src = ((bc < 4)
        ? bev1 + ((size_t)b * 128 + bc * 32) * NPIX
        : bev2 + ((size_t)b * 128 + (bc - 4) * 32) * NPIX) + bp * 32;
    float* adst = A + ((size_t)b * 256 + bc * 32) * NPIX + bp * 32;
#pragma unroll
    for (int r = 0; r < 4; r++) {
        int c = ty + r * 8;
        float v = src[(size_t)c * NPIX + tx];
        tile[c][tx] = v;
        adst[(size_t)c * NPIX + tx] = v;
    }
    __syncthreads();
    float* dst = C + ((size_t)b * NPIX + bp * 32) * 256 + bc * 32;
#pragma unroll
    for (int r = 0; r < 4; r++) {
        int p = ty + r * 8;
        dst[(size_t)p * 256 + tx] = tile[tx][p];
    }
}

// ---------------- NCHW -> NHWC transpose with fused SE scale --------------
__global__ void __launch_bounds__(256) to_nhwc_scaled(
    const float* __restrict__ in, const float* __restrict__ sc,
    float* __restrict__ outp) {
    __shared__ float tile[32][33];
    __shared__ float sSc[32];
    const int bp = blockIdx.x, bc = blockIdx.y, b = blockIdx.z;
    const int tx = threadIdx.x & 31, ty = threadIdx.x >> 5;
    if (threadIdx.x < 32) sSc[threadIdx.x] = sc[b * 256 + bc * 32 + threadIdx.x];
    const float* src = in + ((size_t)b * 256 + bc * 32) * NPIX + bp * 32;
#pragma unroll
    for (int r = 0; r < 4; r++) {
        int c = ty + r * 8;
        tile[c][tx] = src[(size_t)c * NPIX + tx];
    }
    __syncthreads();
    float* dst = outp + ((size_t)b * NPIX + bp * 32) * 256 + bc * 32;
    const float s = sSc[tx];
#pragma unroll
    for (int r = 0; r < 4; r++) {
        int p = ty + r * 8;
        dst[(size_t)p * 256 + tx] = tile[tx][p] * s;
    }
}

// ---------------- weight prep: dcn + off fragment packs ----------------
__global__ void prep_weights(const float* __restrict__ dcnw,
                             const float* __restrict__ offw,
                             uint2* __restrict__ BH, uint2* __restrict__ BL,
                             uint2* __restrict__ OBH, uint2* __restrict__ OBL) {
    int idx = blockIdx.x * 256 + threadIdx.x;
    if (idx < 409600) {
        const int t  = idx & 31;
        const int j  = (idx >> 5) & 31;
        const int s  = (idx >> 10) & 7;
        const int gk = idx >> 13;
        const int k = gk % 25, g = gk / 25;
        const int o = j * 8 + (t >> 2);
        const int c0 = s * 16 + 2 * (t & 3);
        float w0 = dcnw[o * 6400 + (g * 128 + c0    ) * 25 + k] * 64.f;
        float w1 = dcnw[o * 6400 + (g * 128 + c0 + 1) * 25 + k] * 64.f;
        float w8 = dcnw[o * 6400 + (g * 128 + c0 + 8) * 25 + k] * 64.f;
        float w9 = dcnw[o * 6400 + (g * 128 + c0 + 9) * 25 + k] * 64.f;
        float h0 = __half2float(__float2half_rn(w0));
        float h1 = __half2float(__float2half_rn(w1));
        float h8 = __half2float(__float2half_rn(w8));
        float h9 = __half2float(__float2half_rn(w9));
        BH[idx] = make_uint2(packh(h0, h1), packh(h8, h9));
        BL[idx] = make_uint2(packh(w0 - h0, w1 - h1), packh(w8 - h8, w9 - h9));
    } else if (idx < 614400) {
        const int i2 = idx - 409600;
        const int t  = i2 & 31;
        const int j  = (i2 >> 5) & 15;
        const int s  = (i2 >> 9) & 7;
        const int it = i2 >> 12;
        const int k = it >> 1, h = it & 1;
        const int o = j * 8 + (t >> 2);
        const int c0 = h * 128 + s * 16 + 2 * (t & 3);
        float w0 = 0.f, w1 = 0.f, w8 = 0.f, w9 = 0.f;
        if (o < 100) {
            w0 = offw[o * 6400 + (c0    ) * 25 + k] * 1024.f;
            w1 = offw[o * 6400 + (c0 + 1) * 25 + k] * 1024.f;
            w8 = offw[o * 6400 + (c0 + 8) * 25 + k] * 1024.f;
            w9 = offw[o * 6400 + (c0 + 9) * 25 + k] * 1024.f;
        }
        float h0 = __half2float(__float2half_rn(w0));
        float h1 = __half2float(__float2half_rn(w1));
        float h8 = __half2float(__float2half_rn(w8));
        float h9 = __half2float(__float2half_rn(w9));
        OBH[i2] = make_uint2(packh(h0, h1), packh(h8, h9));
        OBL[i2] = make_uint2(packh(w0 - h0, w1 - h1), packh(w8 - h8, w9 - h9));
    }
}

__global__ void transpose_redw(const float* __restrict__ w, float* __restrict__ dst) {
    int idx = blockIdx.x * 256 + threadIdx.x;
    int o = idx & 127;
    int c = idx >> 7;
    dst[idx] = w[o * 256 + c];
}

// ---------------- offset conv via mma.sync (double-buffered) ----------------
// dynamic smem: uint32 Sbuf[2][8704]  (Sh then Sl per buffer) = 69,632 B
__global__ void __launch_bounds__(256, 2) offconv_hmma(
    const float* __restrict__ xh,
    const uint2* __restrict__ OBH, const uint2* __restrict__ OBL,
    const float* __restrict__ offb,
    float* __restrict__ offout) {
    uint32_t* Sbuf = (uint32_t*)smext;

    const int tid = threadIdx.x;
    const int lane = tid & 31, warp = tid >> 5;
    const int b = blockIdx.y;
    const int row = blockIdx.x >> 1;
    const int px0 = (blockIdx.x & 1) << 6;

    const int wo = warp & 1;
    const int wp = warp >> 1;
    const int sh = warp & 1;
    const int cq = warp >> 1;
    const int lg = lane >> 3;
    const int c0s = cq * 32 + (lane & 7) * 4;

    float d[32];
#pragma unroll
    for (int q = 0; q < 32; q++) d[q] = 0.f;

    const float4 zero4 = make_float4(0.f, 0.f, 0.f, 0.f);
    const uint32_t sbase = smem_u32(Sbuf);
    const uint32_t lanePat = (lane & 15) * 272 + (lane >> 4) * 16;
    const float* xb = xh + (size_t)b * NPIX * 256;

    auto sample_tap = [&](int it2, uint32_t* ShB, uint32_t* SlB) {
        const int k2 = it2 >> 1, h2 = it2 & 1;
        const int kh2 = k2 / 5, kw2 = k2 % 5;
        const int gy2 = row + kh2 - 2;
        const bool vy2 = (gy2 >= 0) & (gy2 < 128);
#pragma unroll
        for (int j = 0; j < 8; j++) {
            const int p = sh * 32 + j * 4 + lg;
            const int gx = px0 + p + kw2 - 2;
            float4 va = zero4;
            if (vy2 && gx >= 0 && gx < 128)
                va = *(const float4*)(xb + ((size_t)gy2 * 128 + gx) * 256 + h2 * 128 + c0s);
            float h0 = __half2float(__float2half_rn(va.x));
            float h1 = __half2float(__float2half_rn(va.y));
            float h2f = __half2float(__float2half_rn(va.z));
            float h3 = __half2float(__float2half_rn(va.w));
            const int wi = p * 68 + (c0s >> 1);
            *(uint2*)&ShB[wi] = make_uint2(packh(h0, h1), packh(h2f, h3));
            *(uint2*)&SlB[wi] = make_uint2(packh(va.x - h0, va.y - h1),
                                           packh(va.z - h2f, va.w - h3));
        }
    };

    sample_tap(0, Sbuf, Sbuf + 4352);
    __syncthreads();

    for (int it = 0; it < 50; it++) {
        const int cur = it & 1;
        if (it < 49) {
            uint32_t* nb = Sbuf + (cur ^ 1) * 8704;
            sample_tap(it + 1, nb, nb + 4352);
        }
        const uint32_t aH = sbase + cur * 34816 + lanePat;
        const uint32_t aL = aH + 17408;
        const uint2* BHt = OBH + ((size_t)it * 8 * 16 + wo * 8) * 32 + lane;
#pragma unroll
        for (int s = 0; s < 8; s++) {
            uint32_t Ah[4], Al[4];
            ldm4(Ah, aH + (wp * 16) * 272 + s * 32);
            ldm4(Al, aL + (wp * 16) * 272 + s * 32);
            const uint2* bh = BHt + (size_t)s * 512;
#pragma unroll
            for (int j2 = 0; j2 < 8; j2++) {
                uint2 Bh = bh[j2 * 32];
                float* dd = &d[j2 * 4];
                mma16816(dd[0], dd[1], dd[2], dd[3], Ah, Bh.x, Bh.y);
                mma16816(dd[0], dd[1], dd[2], dd[3], Al, Bh.x, Bh.y);
            }
        }
        __syncthreads();
    }

    const int g2 = lane >> 2, tig = lane & 3;
    const int pxl = wp * 16 + g2;
    const size_t outbase = (size_t)row * 128 + px0;
#pragma unroll
    for (int j2 = 0; j2 < 8; j2++) {
        const int o = wo * 64 + j2 * 8 + 2 * tig;
        if (o < 100) {
            const float* dd = &d[j2 * 4];
            const float b0 = offb[o], b1 = offb[o + 1];
            float* y0 = offout + ((size_t)(b * 100 + o)) * NPIX + outbase;
            float* y1 = y0 + NPIX;
            y0[pxl]     = dd[0] * 0.0009765625f + b0;
            y1[pxl]     = dd[1] * 0.0009765625f + b1;
            y0[pxl + 8] = dd[2] * 0.0009765625f + b0;
            y1[pxl + 8] = dd[3] * 0.0009765625f + b1;
        }
    }
}

// ---------------- deformable conv via mma.sync (double-buffered) -----------
// smem floats: sPy[3200] sPx[3200] sBNa[256] sBNb[256] | u32 Sbuf[2][8704]
#define DEF_SMEM_BYTES ((6912 + 17408) * 4)
__global__ void __launch_bounds__(256, 2) deform_hmma(
    const float* __restrict__ xh,
    const float* __restrict__ off,
    const uint2* __restrict__ BH, const uint2* __restrict__ BL,
    const float* __restrict__ bng, const float* __restrict__ bnb,
    const float* __restrict__ bnm, const float* __restrict__ bnv,
    float* __restrict__ yout) {
    float* sPy = smext;
    float* sPx = smext + 3200;
    float* sBNa = smext + 6400;
    float* sBNb = smext + 6656;
    uint32_t* Sbuf = (uint32_t*)(smext + 6912);

    const int tid = threadIdx.x;
    const int lane = tid & 31, warp = tid >> 5;
    const int b = blockIdx.y;
    const int row = blockIdx.x >> 1;
    const int px0 = (blockIdx.x & 1) << 6;

    const int wo = warp & 3;
    const int wp = warp >> 2;
    const int sh = warp & 1;
    const int cq = warp >> 1;
    const int lg = lane >> 3;
    const int c0s = cq * 32 + (lane & 7) * 4;

    if (tid < 256) {
        float inv = bng[tid] * rsqrtf(bnv[tid] + 1e-5f);
        sBNa[tid] = inv * 0.015625f;
        sBNb[tid] = bnb[tid] - bnm[tid] * inv;
    }
    for (int idx = tid; idx < 3200; idx += 256) {
        int gk = idx >> 6, p = idx & 63;
        int g = gk / 25, k = gk % 25;
        int kh = k / 5, kw = k % 5;
        int ch = b * 100 + g * 50 + 2 * k;
        float oy = off[(size_t)ch * NPIX + row * 128 + px0 + p];
        float ox = off[(size_t)(ch + 1) * NPIX + row * 128 + px0 + p];
        sPy[idx] = (float)(row + kh - 2) + oy;
        sPx[idx] = (float)(px0 + p + kw - 2) + ox;
    }
    __syncthreads();   // coords/BN visible before first sample

    float d[64];
#pragma unroll
    for (int q = 0; q < 64; q++) d[q] = 0.f;

    const float4 zero4 = make_float4(0.f, 0.f, 0.f, 0.f);
    const uint32_t sbase = smem_u32(Sbuf);
    const uint32_t lanePat = (lane & 15) * 272 + (lane >> 4) * 16;

    auto sample_tap = [&](int gk2, uint32_t* ShB, uint32_t* SlB) {
        const int gs = (gk2 >= 25) ? 1 : 0;
        const float* xgb = xh + (size_t)b * NPIX * 256 + gs * 128 + c0s;
#pragma unroll
        for (int j = 0; j < 8; j++) {
            const int p = sh * 32 + j * 4 + lg;
            const float py = sPy[gk2 * 64 + p];
            const float pv = sPx[gk2 * 64 + p];
            const float y0f = floorf(py), x0f = floorf(pv);
            const float wy1 = py - y0f, wx1 = pv - x0f;
            const float wy0 = 1.f - wy1, wx0 = 1.f - wx1;
            const float w00 = wy0 * wx0, w01 = wy0 * wx1;
            const float w10 = wy1 * wx0, w11 = wy1 * wx1;
            const int iy = (int)y0f, ix = (int)x0f;
            const bool vy0 = (iy >= 0) & (iy < 128);
            const bool vy1 = (iy >= -1) & (iy < 127);
            const bool vx0 = (ix >= 0) & (ix < 128);
            const bool vx1 = (ix >= -1) & (ix < 127);
            const long base = ((long)iy * 128 + ix) * 256;
            float4 va = (vy0 & vx0) ? *(const float4*)(xgb + base) : zero4;
            float4 vb = (vy0 & vx1) ? *(const float4*)(xgb + base + 256) : zero4;
            float4 vc = (vy1 & vx0) ? *(const float4*)(xgb + base + 128 * 256) : zero4;
            float4 vd4 = (vy1 & vx1) ? *(const float4*)(xgb + base + 128 * 256 + 256) : zero4;
            float r0 = w00 * va.x + w01 * vb.x + w10 * vc.x + w11 * vd4.x;
            float r1 = w00 * va.y + w01 * vb.y + w10 * vc.y + w11 * vd4.y;
            float r2 = w00 * va.z + w01 * vb.z + w10 * vc.z + w11 * vd4.z;
            float r3 = w00 * va.w + w01 * vb.w + w10 * vc.w + w11 * vd4.w;
            float h0 = __half2float(__float2half_rn(r0));
            float h1 = __half2float(__float2half_rn(r1));
            float h2f = __half2float(__float2half_rn(r2));
            float h3 = __half2float(__float2half_rn(r3));
            const int wi = p * 68 + (c0s >> 1);
            *(uint2*)&ShB[wi] = make_uint2(packh(h0, h1), packh(h2f, h3));
            *(uint2*)&SlB[wi] = make_uint2(packh(r0 - h0, r1 - h1),
                                           packh(r2 - h2f, r3 - h3));
        }
    };

    sample_tap(0, Sbuf, Sbuf + 4352);
    __syncthreads();

    for (int gk = 0; gk < 50; gk++) {
        const int cur = gk & 1;
        if (gk < 49) {
            uint32_t* nb = Sbuf + (cur ^ 1) * 8704;
            sample_tap(gk + 1, nb, nb + 4352);
        }
        const uint32_t aH = sbase + cur * 34816 + lanePat;
        const uint32_t aL = aH + 17408;
        const uint2* BHt = BH + ((size_t)gk * 8 * 32 + wo * 8) * 32 + lane;
        const uint2* BLt = BL + ((size_t)gk * 8 * 32 + wo * 8) * 32 + lane;
#pragma unroll
        for (int s = 0; s < 8; s++) {
            uint32_t Ah[2][4], Al[2][4];
            ldm4(Ah[0], aH + (wp * 32     ) * 272 + s * 32);
            ldm4(Ah[1], aH + (wp * 32 + 16) * 272 + s * 32);
            ldm4(Al[0], aL + (wp * 32     ) * 272 + s * 32);
            ldm4(Al[1], aL + (wp * 32 + 16) * 272 + s * 32);
            const uint2* bh = BHt + (size_t)s * 1024;
            const uint2* bl = BLt + (size_t)s * 1024;
#pragma unroll
            for (int j2 = 0; j2 < 8; j2++) {
                uint2 Bh = bh[j2 * 32];
                uint2 Bl = bl[j2 * 32];
                float* d0 = &d[(0 * 8 + j2) * 4];
                float* d1 = &d[(1 * 8 + j2) * 4];
                mma16816(d0[0], d0[1], d0[2], d0[3], Ah[0], Bh.x, Bh.y);
                mma16816(d1[0], d1[1], d1[2], d1[3], Ah[1], Bh.x, Bh.y);
                mma16816(d0[0], d0[1], d0[2], d0[3], Al[0], Bh.x, Bh.y);
                mma16816(d1[0], d1[1], d1[2], d1[3], Al[1], Bh.x, Bh.y);
                mma16816(d0[0], d0[1], d0[2], d0[3], Ah[0], Bl.x, Bl.y);
                mma16816(d1[0], d1[1], d1[2], d1[3], Ah[1], Bl.x, Bl.y);
            }
        }
        __syncthreads();
    }

    const int ge = lane >> 2, tig = lane & 3;
    const size_t outbase = (size_t)row * 128 + px0;
#pragma unroll
    for (int mt = 0; mt < 2; mt++) {
#pragma unroll
        for (int j2 = 0; j2 < 8; j2++) {
            const float* dd = &d[(mt * 8 + j2) * 4];
            const int pxl = wp * 32 + mt * 16 + ge;
            const int o = wo * 64 + j2 * 8 + 2 * tig;
            float a0 = sBNa[o], b0v = sBNb[o];
            float a1 = sBNa[o + 1], b1v = sBNb[o + 1];
            float* y0 = yout + ((size_t)(b * 256 + o)) * NPIX + outbase;
            float* y1 = yout + ((size_t)(b * 256 + o + 1)) * NPIX + outbase;
            y0[pxl]     = fmaxf(dd[0] * a0 + b0v, 0.f);
            y1[pxl]     = fmaxf(dd[1] * a1 + b1v, 0.f);
            y0[pxl + 8] = fmaxf(dd[2] * a0 + b0v, 0.f);
            y1[pxl + 8] = fmaxf(dd[3] * a1 + b1v, 0.f);
        }
    }
}

// ---------------- SE / pool ----------------
__global__ void pool_kernel(const float* __restrict__ y, float* __restrict__ pool) {
    int bc = blockIdx.x;
    const float* plane = y + (size_t)bc * NPIX;
    float s = 0.f;
    for (int i = threadIdx.x; i < NPIX; i += 256) s += plane[i];
    __shared__ float red[256];
    red[threadIdx.x] = s;
    __syncthreads();
    for (int st = 128; st > 0; st >>= 1) {
        if (threadIdx.x < st) red[threadIdx.x] += red[threadIdx.x + st];
        __syncthreads();
    }
    if (threadIdx.x == 0) pool[bc] = red[0] * (1.f / NPIX);
}

__global__ void se_kernel(const float* __restrict__ pool,
                          const float* __restrict__ w1,
                          const float* __restrict__ w2,
                          float* __restrict__ scale) {
    int b = blockIdx.x;
    int tid = threadIdx.x;
    __shared__ float sp[256], shd[16];
    sp[tid] = pool[b * 256 + tid];
    __syncthreads();
    if (tid < 16) {
        float a = 0.f;
        for (int c = 0; c < 256; c++) a += sp[c] * w1[tid * 256 + c];
        shd[tid] = fmaxf(a, 0.f);
    }
    __syncthreads();
    float a = 0.f;
#pragma unroll
    for (int j = 0; j < 16; j++) a += shd[j] * w2[tid * 16 + j];
    scale[b * 256 + tid] = 1.f / (1.f + expf(-a));
}

// ---------------- final 1x1 conv + fused SE scale + BN + ReLU (fma2) ------
__global__ void __launch_bounds__(256) final_kernel(
    const float* __restrict__ xin, const float* __restrict__ sc,
    const float* __restrict__ redT,
    const float* __restrict__ bng, const float* __restrict__ bnb,
    const float* __restrict__ bnm, const float* __restrict__ bnv,
    float* __restrict__ out) {
    const int tid = threadIdx.x;
    const int b = blockIdx.y;
    const int p0 = blockIdx.x * 64;
    const int px = tid & 63, og = tid >> 6;
    __shared__ __align__(16) float sX[8][64];
    __shared__ __align__(16) float sWf[8][128];
    __shared__ float sBN[256];
    __shared__ float sSc[256];
    if (tid < 128) {
        float inv = bng[tid] * rsqrtf(bnv[tid] + 1e-5f);
        sBN[tid] = inv;
        sBN[128 + tid] = bnb[tid] - bnm[tid] * inv;
    }
    sSc[tid] = sc[b * 256 + tid];
    union { unsigned long long u[16]; float f[32]; } acc;
#pragma unroll
    for (int j = 0; j < 16; j++) acc.u[j] = 0ull;

    for (int cb = 0; cb < 256; cb += 8) {
        __syncthreads();
        {
            int i = tid;
            sX[i >> 6][i & 63] = xin[((size_t)(b * 256 + cb + (i >> 6))) * NPIX + p0 + (i & 63)]
                                 * sSc[cb + (i >> 6)];
            i = tid + 256;
            sX[i >> 6][i & 63] = xin[((size_t)(b * 256 + cb + (i >> 6))) * NPIX + p0 + (i & 63)]
                                 * sSc[cb + (i >> 6)];
            for (int t = tid; t < 1024; t += 256)
                sWf[t >> 7][t & 127] = redT[(cb + (t >> 7)) * 128 + (t & 127)];
        }
        __syncthreads();
#pragma unroll
        for (int c = 0; c < 8; c++) {
            float xv = sX[c][px];
            unsigned long long xd = pk2(xv, xv);
            const F4* wp = (const F4*)&sWf[c][og * 32];
#pragma unroll
            for (int j = 0; j < 8; j++) {
                F4 w = wp[j];
                fma2(acc.u[2 * j],     xd, w.u[0]);
                fma2(acc.u[2 * j + 1], xd, w.u[1]);
            }
        }
    }
#pragma unroll
    for (int j = 0; j < 32; j++) {
        int o = og * 32 + j;
        float v = acc.f[j] * sBN[o] + sBN[128 + o];
        out[((size_t)(b * 128 + o)) * NPIX + p0 + px] = fmaxf(v, 0.f);
    }
}

// ---------------- launch ----------------
extern "C" void kernel_launch(void* const* d_in, const int* in_sizes, int n_in,
                              void* d_out, int out_size) {
    const float* bev1   = (const float*)d_in[0];
    const float* bev2   = (const float*)d_in[1];
    const float* off_w1 = (const float*)d_in[2];
    const float* off_b1 = (const float*)d_in[3];
    const float* dcn_w1 = (const float*)d_in[4];
    const float* bn1_g  = (const float*)d_in[5];
    const float* bn1_b  = (const float*)d_in[6];
    const float* bn1_m  = (const float*)d_in[7];
    const float* bn1_v  = (const float*)d_in[8];
    const float* se1_w1 = (const float*)d_in[9];
    const float* se1_w2 = (const float*)d_in[10];
    const float* off_w2 = (const float*)d_in[11];
    const float* off_b2 = (const float*)d_in[12];
    const float* dcn_w2 = (const float*)d_in[13];
    const float* bn2_g  = (const float*)d_in[14];
    const float* bn2_b  = (const float*)d_in[15];
    const float* bn2_m  = (const float*)d_in[16];
    const float* bn2_v  = (const float*)d_in[17];
    const float* se2_w1 = (const float*)d_in[18];
    const float* se2_w2 = (const float*)d_in[19];
    const float* red_w  = (const float*)d_in[20];
    const float* bn3_g  = (const float*)d_in[21];
    const float* bn3_b  = (const float*)d_in[22];
    const float* bn3_m  = (const float*)d_in[23];
    const float* bn3_v  = (const float*)d_in[24];

    float *A, *B, *C, *OFF, *RT, *POOL, *SCALE;
    uint2 *BH, *BL, *OBH, *OBL;
    cudaGetSymbolAddress((void**)&A,    g_bufA);
    cudaGetSymbolAddress((void**)&B,    g_bufB);
    cudaGetSymbolAddress((void**)&C,    g_bufC);
    cudaGetSymbolAddress((void**)&OFF,  g_off);
    cudaGetSymbolAddress((void**)&BH,   g_bh);
    cudaGetSymbolAddress((void**)&BL,   g_bl);
    cudaGetSymbolAddress((void**)&OBH,  g_obh);
    cudaGetSymbolAddress((void**)&OBL,  g_obl);
    cudaGetSymbolAddress((void**)&RT,   g_rT);
    cudaGetSymbolAddress((void**)&POOL, g_pool);
    cudaGetSymbolAddress((void**)&SCALE,g_scale);

    const int OFF_SMEM = 2 * 8704 * 4;          // 69,632 B
    cudaFuncSetAttribute(offconv_hmma,
                         cudaFuncAttributeMaxDynamicSharedMemorySize, OFF_SMEM);
    cudaFuncSetAttribute(deform_hmma,
                         cudaFuncAttributeMaxDynamicSharedMemorySize, DEF_SMEM_BYTES);

    // ---- stage 1 ----
    concat_nhwc<<<dim3(512, 8, 4), 256>>>(bev1, bev2, A, C);
    prep_weights<<<2400, 256>>>(dcn_w1, off_w1, BH, BL, OBH, OBL);
    offconv_hmma<<<dim3(256, 4), 256, OFF_SMEM>>>(C, OBH, OBL, off_b1, OFF);
    deform_hmma<<<dim3(256, 4), 256, DEF_SMEM_BYTES>>>(C, OFF, BH, BL,
                                                 bn1_g, bn1_b, bn1_m, bn1_v, B);
    pool_kernel<<<1024, 256>>>(B, POOL);
    se_kernel<<<4, 256>>>(POOL, se1_w1, se1_w2, SCALE);

    // ---- stage 2 (scale1 fused into to_nhwc) ----
    to_nhwc_scaled<<<dim3(512, 8, 4), 256>>>(B, SCALE, C);
    prep_weights<<<2400, 256>>>(dcn_w2, off_w2, BH, BL, OBH, OBL);
    offconv_hmma<<<dim3(256, 4), 256, OFF_SMEM>>>(C, OBH, OBL, off_b2, OFF);
    deform_hmma<<<dim3(256, 4), 256, DEF_SMEM_BYTES>>>(C, OFF, BH, BL,
                                                 bn2_g, bn2_b, bn2_m, bn2_v, A);
    pool_kernel<<<1024, 256>>>(A, POOL);
    se_kernel<<<4, 256>>>(POOL, se2_w1, se2_w2, SCALE);

    // ---- final (scale2 fused) ----
    transpose_redw<<<128, 256>>>(red_w, RT);
    final_kernel<<<dim3(256, 4), 256>>>(A, SCALE, RT, bn3_g, bn3_b, bn3_m, bn3_v,
                                        (float*)d_out);
}

// round 12
// speedup vs baseline: 5.0041x; 1.2058x over previous
#include <cuda_runtime.h>
#include <cuda_fp16.h>
#include <math.h>
#include <stdint.h>

// ---------------- packed f32x2 helpers (final conv) ----------------
__device__ __forceinline__ unsigned long long pk2(float x, float y) {
    unsigned long long r;
    asm("mov.b64 %0, {%1, %2};" : "=l"(r) : "f"(x), "f"(y));
    return r;
}
__device__ __forceinline__ void fma2(unsigned long long& d,
                                     unsigned long long a, unsigned long long b) {
    asm("fma.rn.f32x2 %0, %1, %2, %0;" : "+l"(d) : "l"(a), "l"(b));
}
union F4 { float4 v; float f[4]; unsigned long long u[2]; };

// ---------------- mma.sync helpers ----------------
__device__ __forceinline__ void ldm4(uint32_t* r, uint32_t addr) {
    asm volatile("ldmatrix.sync.aligned.m8n8.x4.shared.b16 {%0,%1,%2,%3}, [%4];"
                 : "=r"(r[0]), "=r"(r[1]), "=r"(r[2]), "=r"(r[3]) : "r"(addr));
}
__device__ __forceinline__ void mma16816(float& d0, float& d1, float& d2, float& d3,
                                         const uint32_t* a, uint32_t b0, uint32_t b1) {
    asm volatile(
        "mma.sync.aligned.m16n8k16.row.col.f32.f16.f16.f32 "
        "{%0,%1,%2,%3}, {%4,%5,%6,%7}, {%8,%9}, {%0,%1,%2,%3};"
        : "+f"(d0), "+f"(d1), "+f"(d2), "+f"(d3)
        : "r"(a[0]), "r"(a[1]), "r"(a[2]), "r"(a[3]), "r"(b0), "r"(b1));
}
__device__ __forceinline__ uint32_t smem_u32(const void* p) {
    uint32_t a;
    asm("{ .reg .u64 t; cvta.to.shared.u64 t, %1; cvt.u32.u64 %0, t; }"
        : "=r"(a) : "l"(p));
    return a;
}
__device__ __forceinline__ uint32_t packh(float a, float b) {
    __half2 h = __halves2half2(__float2half_rn(a), __float2half_rn(b));
    return *(uint32_t*)&h;
}

// single extern smem symbol shared by kernels
extern __shared__ float smext[];

// ---------------- scratch ----------------
#define NPIX 16384
__device__ __align__(16) float g_bufA[4 * 256 * NPIX];
__device__ __align__(16) float g_bufB[4 * 256 * NPIX];
__device__ __align__(16) float g_bufC[4 * 256 * NPIX];
__device__ __align__(16) float g_off [4 * 100 * NPIX];
__device__ __align__(16) uint2 g_bh  [50 * 8 * 32 * 32];
__device__ __align__(16) uint2 g_obh [50 * 8 * 16 * 32];
__device__ __align__(16) uint2 g_obl [50 * 8 * 16 * 32];
__device__ __align__(16) float g_rT  [256 * 128];
__device__ float g_pool[1024];
__device__ float g_scale[1024];

// ---------------- fused concat -> NCHW A + NHWC C ----------------
__global__ void __launch_bounds__(256) concat_nhwc(
    const float* __restrict__ bev1, const float* __restrict__ bev2,
    float* __restrict__ A, float* __restrict__ C) {
    __shared__ float tile[32][33];
    const int bp = blockIdx.x, bc = blockIdx.y, b = blockIdx.z;
    const int tx = threadIdx.x & 31, ty = threadIdx.x >> 5;
    const float* src = ((bc < 4)
        ? bev1 + ((size_t)b * 128 + bc * 32) * NPIX
        : bev2 + ((size_t)b * 128 + (bc - 4) * 32) * NPIX) + bp * 32;
    float* adst = A + ((size_t)b * 256 + bc * 32) * NPIX + bp * 32;
#pragma unroll
    for (int r = 0; r < 4; r++) {
        int c = ty + r * 8;
        float v = src[(size_t)c * NPIX + tx];
        tile[c][tx] = v;
        adst[(size_t)c * NPIX + tx] = v;
    }
    __syncthreads();
    float* dst = C + ((size_t)b * NPIX + bp * 32) * 256 + bc * 32;
#pragma unroll
    for (int r = 0; r < 4; r++) {
        int p = ty + r * 8;
        dst[(size_t)p * 256 + tx] = tile[tx][p];
    }
}

// ---------------- NCHW -> NHWC transpose with fused SE scale --------------
__global__ void __launch_bounds__(256) to_nhwc_scaled(
    const float* __restrict__ in, const float* __restrict__ sc,
    float* __restrict__ outp) {
    __shared__ float tile[32][33];
    __shared__ float sSc[32];
    const int bp = blockIdx.x, bc = blockIdx.y, b = blockIdx.z;
    const int tx = threadIdx.x & 31, ty = threadIdx.x >> 5;
    if (threadIdx.x < 32) sSc[threadIdx.x] = sc[b * 256 + bc * 32 + threadIdx.x];
    const float* src = in + ((size_t)b * 256 + bc * 32) * NPIX + bp * 32;
#pragma unroll
    for (int r = 0; r < 4; r++) {
        int c = ty + r * 8;
        tile[c][tx] = src[(size_t)c * NPIX + tx];
    }
    __syncthreads();
    float* dst = outp + ((size_t)b * NPIX + bp * 32) * 256 + bc * 32;
    const float s = sSc[tx];
#pragma unroll
    for (int r = 0; r < 4; r++) {
        int p = ty + r * 8;
        dst[(size_t)p * 256 + tx] = tile[tx][p] * s;
    }
}

// ---------------- weight prep: dcn hi + off hi/lo fragment packs -----------
__global__ void prep_weights(const float* __restrict__ dcnw,
                             const float* __restrict__ offw,
                             uint2* __restrict__ BH,
                             uint2* __restrict__ OBH, uint2* __restrict__ OBL) {
    int idx = blockIdx.x * 256 + threadIdx.x;
    if (idx < 409600) {
        const int t  = idx & 31;
        const int j  = (idx >> 5) & 31;
        const int s  = (idx >> 10) & 7;
        const int gk = idx >> 13;
        const int k = gk % 25, g = gk / 25;
        const int o = j * 8 + (t >> 2);
        const int c0 = s * 16 + 2 * (t & 3);
        float w0 = dcnw[o * 6400 + (g * 128 + c0    ) * 25 + k] * 64.f;
        float w1 = dcnw[o * 6400 + (g * 128 + c0 + 1) * 25 + k] * 64.f;
        float w8 = dcnw[o * 6400 + (g * 128 + c0 + 8) * 25 + k] * 64.f;
        float w9 = dcnw[o * 6400 + (g * 128 + c0 + 9) * 25 + k] * 64.f;
        BH[idx] = make_uint2(packh(__half2float(__float2half_rn(w0)),
                                   __half2float(__float2half_rn(w1))),
                             packh(__half2float(__float2half_rn(w8)),
                                   __half2float(__float2half_rn(w9))));
    } else if (idx < 614400) {
        const int i2 = idx - 409600;
        const int t  = i2 & 31;
        const int j  = (i2 >> 5) & 15;
        const int s  = (i2 >> 9) & 7;
        const int it = i2 >> 12;
        const int k = it >> 1, h = it & 1;
        const int o = j * 8 + (t >> 2);
        const int c0 = h * 128 + s * 16 + 2 * (t & 3);
        float w0 = 0.f, w1 = 0.f, w8 = 0.f, w9 = 0.f;
        if (o < 100) {
            w0 = offw[o * 6400 + (c0    ) * 25 + k] * 1024.f;
            w1 = offw[o * 6400 + (c0 + 1) * 25 + k] * 1024.f;
            w8 = offw[o * 6400 + (c0 + 8) * 25 + k] * 1024.f;
            w9 = offw[o * 6400 + (c0 + 9) * 25 + k] * 1024.f;
        }
        float h0 = __half2float(__float2half_rn(w0));
        float h1 = __half2float(__float2half_rn(w1));
        float h8 = __half2float(__float2half_rn(w8));
        float h9 = __half2float(__float2half_rn(w9));
        OBH[i2] = make_uint2(packh(h0, h1), packh(h8, h9));
        OBL[i2] = make_uint2(packh(w0 - h0, w1 - h1), packh(w8 - h8, w9 - h9));
    }
}

__global__ void transpose_redw(const float* __restrict__ w, float* __restrict__ dst) {
    int idx = blockIdx.x * 256 + threadIdx.x;
    int o = idx & 127;
    int c = idx >> 7;
    dst[idx] = w[o * 256 + c];
}

// ---------------- offset conv via mma.sync (double-buffered) ----------------
__global__ void __launch_bounds__(256, 2) offconv_hmma(
    const float* __restrict__ xh,
    const uint2* __restrict__ OBH, const uint2* __restrict__ OBL,
    const float* __restrict__ offb,
    float* __restrict__ offout) {
    uint32_t* Sbuf = (uint32_t*)smext;

    const int tid = threadIdx.x;
    const int lane = tid & 31, warp = tid >> 5;
    const int b = blockIdx.y;
    const int row = blockIdx.x >> 1;
    const int px0 = (blockIdx.x & 1) << 6;

    const int wo = warp & 1;
    const int wp = warp >> 1;
    const int sh = warp & 1;
    const int cq = warp >> 1;
    const int lg = lane >> 3;
    const int c0s = cq * 32 + (lane & 7) * 4;

    float d[32];
#pragma unroll
    for (int q = 0; q < 32; q++) d[q] = 0.f;

    const float4 zero4 = make_float4(0.f, 0.f, 0.f, 0.f);
    const uint32_t sbase = smem_u32(Sbuf);
    const uint32_t lanePat = (lane & 15) * 272 + (lane >> 4) * 16;
    const float* xb = xh + (size_t)b * NPIX * 256;

    auto sample_tap = [&](int it2, uint32_t* ShB, uint32_t* SlB) {
        const int k2 = it2 >> 1, h2 = it2 & 1;
        const int kh2 = k2 / 5, kw2 = k2 % 5;
        const int gy2 = row + kh2 - 2;
        const bool vy2 = (gy2 >= 0) & (gy2 < 128);
#pragma unroll
        for (int j = 0; j < 8; j++) {
            const int p = sh * 32 + j * 4 + lg;
            const int gx = px0 + p + kw2 - 2;
            float4 va = zero4;
            if (vy2 && gx >= 0 && gx < 128)
                va = *(const float4*)(xb + ((size_t)gy2 * 128 + gx) * 256 + h2 * 128 + c0s);
            float h0 = __half2float(__float2half_rn(va.x));
            float h1 = __half2float(__float2half_rn(va.y));
            float h2f = __half2float(__float2half_rn(va.z));
            float h3 = __half2float(__float2half_rn(va.w));
            const int wi = p * 68 + (c0s >> 1);
            *(uint2*)&ShB[wi] = make_uint2(packh(h0, h1), packh(h2f, h3));
            *(uint2*)&SlB[wi] = make_uint2(packh(va.x - h0, va.y - h1),
                                           packh(va.z - h2f, va.w - h3));
        }
    };

    sample_tap(0, Sbuf, Sbuf + 4352);
    __syncthreads();

    for (int it = 0; it < 50; it++) {
        const int cur = it & 1;
        if (it < 49) {
            uint32_t* nb = Sbuf + (cur ^ 1) * 8704;
            sample_tap(it + 1, nb, nb + 4352);
        }
        const uint32_t aH = sbase + cur * 34816 + lanePat;
        const uint32_t aL = aH + 17408;
        const uint2* BHt = OBH + ((size_t)it * 8 * 16 + wo * 8) * 32 + lane;
#pragma unroll
        for (int s = 0; s < 8; s++) {
            uint32_t Ah[4], Al[4];
            ldm4(Ah, aH + (wp * 16) * 272 + s * 32);
            ldm4(Al, aL + (wp * 16) * 272 + s * 32);
            const uint2* bh = BHt + (size_t)s * 512;
#pragma unroll
            for (int j2 = 0; j2 < 8; j2++) {
                uint2 Bh = bh[j2 * 32];
                float* dd = &d[j2 * 4];
                mma16816(dd[0], dd[1], dd[2], dd[3], Ah, Bh.x, Bh.y);
                mma16816(dd[0], dd[1], dd[2], dd[3], Al, Bh.x, Bh.y);
            }
        }
        __syncthreads();
    }

    const int g2 = lane >> 2, tig = lane & 3;
    const int pxl = wp * 16 + g2;
    const size_t outbase = (size_t)row * 128 + px0;
#pragma unroll
    for (int j2 = 0; j2 < 8; j2++) {
        const int o = wo * 64 + j2 * 8 + 2 * tig;
        if (o < 100) {
            const float* dd = &d[j2 * 4];
            const float b0 = offb[o], b1 = offb[o + 1];
            float* y0 = offout + ((size_t)(b * 100 + o)) * NPIX + outbase;
            float* y1 = y0 + NPIX;
            y0[pxl]     = dd[0] * 0.0009765625f + b0;
            y1[pxl]     = dd[1] * 0.0009765625f + b1;
            y0[pxl + 8] = dd[2] * 0.0009765625f + b0;
            y1[pxl + 8] = dd[3] * 0.0009765625f + b1;
        }
    }
}

// ---------------- deformable conv via mma.sync (2-product split) -----------
// smem floats: sPy[3200] sPx[3200] sBNa[256] sBNb[256] | u32 Sbuf[2][8704]
#define DEF_SMEM_BYTES ((6912 + 17408) * 4)
__global__ void __launch_bounds__(256, 2) deform_hmma(
    const float* __restrict__ xh,
    const float* __restrict__ off,
    const uint2* __restrict__ BH,
    const float* __restrict__ bng, const float* __restrict__ bnb,
    const float* __restrict__ bnm, const float* __restrict__ bnv,
    float* __restrict__ yout) {
    float* sPy = smext;
    float* sPx = smext + 3200;
    float* sBNa = smext + 6400;
    float* sBNb = smext + 6656;
    uint32_t* Sbuf = (uint32_t*)(smext + 6912);

    const int tid = threadIdx.x;
    const int lane = tid & 31, warp = tid >> 5;
    const int b = blockIdx.y;
    const int row = blockIdx.x >> 1;
    const int px0 = (blockIdx.x & 1) << 6;

    const int wo = warp & 3;
    const int wp = warp >> 2;
    const int sh = warp & 1;
    const int cq = warp >> 1;
    const int lg = lane >> 3;
    const int c0s = cq * 32 + (lane & 7) * 4;

    if (tid < 256) {
        float inv = bng[tid] * rsqrtf(bnv[tid] + 1e-5f);
        sBNa[tid] = inv * 0.015625f;
        sBNb[tid] = bnb[tid] - bnm[tid] * inv;
    }
    for (int idx = tid; idx < 3200; idx += 256) {
        int gk = idx >> 6, p = idx & 63;
        int g = gk / 25, k = gk % 25;
        int kh = k / 5, kw = k % 5;
        int ch = b * 100 + g * 50 + 2 * k;
        float oy = off[(size_t)ch * NPIX + row * 128 + px0 + p];
        float ox = off[(size_t)(ch + 1) * NPIX + row * 128 + px0 + p];
        sPy[idx] = (float)(row + kh - 2) + oy;
        sPx[idx] = (float)(px0 + p + kw - 2) + ox;
    }
    __syncthreads();

    float d[64];
#pragma unroll
    for (int q = 0; q < 64; q++) d[q] = 0.f;

    const float4 zero4 = make_float4(0.f, 0.f, 0.f, 0.f);
    const uint32_t sbase = smem_u32(Sbuf);
    const uint32_t lanePat = (lane & 15) * 272 + (lane >> 4) * 16;

    auto sample_tap = [&](int gk2, uint32_t* ShB, uint32_t* SlB) {
        const int gs = (gk2 >= 25) ? 1 : 0;
        const float* xgb = xh + (size_t)b * NPIX * 256 + gs * 128 + c0s;
#pragma unroll
        for (int j = 0; j < 8; j++) {
            const int p = sh * 32 + j * 4 + lg;
            const float py = sPy[gk2 * 64 + p];
            const float pv = sPx[gk2 * 64 + p];
            const float y0f = floorf(py), x0f = floorf(pv);
            const float wy1 = py - y0f, wx1 = pv - x0f;
            const float wy0 = 1.f - wy1, wx0 = 1.f - wx1;
            const float w00 = wy0 * wx0, w01 = wy0 * wx1;
            const float w10 = wy1 * wx0, w11 = wy1 * wx1;
            const int iy = (int)y0f, ix = (int)x0f;
            const bool vy0 = (iy >= 0) & (iy < 128);
            const bool vy1 = (iy >= -1) & (iy < 127);
            const bool vx0 = (ix >= 0) & (ix < 128);
            const bool vx1 = (ix >= -1) & (ix < 127);
            const long base = ((long)iy * 128 + ix) * 256;
            float4 va = (vy0 & vx0) ? *(const float4*)(xgb + base) : zero4;
            float4 vb = (vy0 & vx1) ? *(const float4*)(xgb + base + 256) : zero4;
            float4 vc = (vy1 & vx0) ? *(const float4*)(xgb + base + 128 * 256) : zero4;
            float4 vd4 = (vy1 & vx1) ? *(const float4*)(xgb + base + 128 * 256 + 256) : zero4;
            float r0 = w00 * va.x + w01 * vb.x + w10 * vc.x + w11 * vd4.x;
            float r1 = w00 * va.y + w01 * vb.y + w10 * vc.y + w11 * vd4.y;
            float r2 = w00 * va.z + w01 * vb.z + w10 * vc.z + w11 * vd4.z;
            float r3 = w00 * va.w + w01 * vb.w + w10 * vc.w + w11 * vd4.w;
            float h0 = __half2float(__float2half_rn(r0));
            float h1 = __half2float(__float2half_rn(r1));
            float h2f = __half2float(__float2half_rn(r2));
            float h3 = __half2float(__float2half_rn(r3));
            const int wi = p * 68 + (c0s >> 1);
            *(uint2*)&ShB[wi] = make_uint2(packh(h0, h1), packh(h2f, h3));
            *(uint2*)&SlB[wi] = make_uint2(packh(r0 - h0, r1 - h1),
                                           packh(r2 - h2f, r3 - h3));
        }
    };

    sample_tap(0, Sbuf, Sbuf + 4352);
    __syncthreads();

    for (int gk = 0; gk < 50; gk++) {
        const int cur = gk & 1;
        if (gk < 49) {
            uint32_t* nb = Sbuf + (cur ^ 1) * 8704;
            sample_tap(gk + 1, nb, nb + 4352);
        }
        const uint32_t aH = sbase + cur * 34816 + lanePat;
        const uint32_t aL = aH + 17408;
        const uint2* BHt = BH + ((size_t)gk * 8 * 32 + wo * 8) * 32 + lane;
#pragma unroll
        for (int s = 0; s < 8; s++) {
            uint32_t Ah[2][4], Al[2][4];
            ldm4(Ah[0], aH + (wp * 32     ) * 272 + s * 32);
            ldm4(Ah[1], aH + (wp * 32 + 16) * 272 + s * 32);
            ldm4(Al[0], aL + (wp * 32     ) * 272 + s * 32);
            ldm4(Al[1], aL + (wp * 32 + 16) * 272 + s * 32);
            const uint2* bh = BHt + (size_t)s * 1024;
#pragma unroll
            for (int j2 = 0; j2 < 8; j2++) {
                uint2 Bh = bh[j2 * 32];
                float* d0 = &d[(0 * 8 + j2) * 4];
                float* d1 = &d[(1 * 8 + j2) * 4];
                mma16816(d0[0], d0[1], d0[2], d0[3], Ah[0], Bh.x, Bh.y);
                mma16816(d1[0], d1[1], d1[2], d1[3], Ah[1], Bh.x, Bh.y);
                mma16816(d0[0], d0[1], d0[2], d0[3], Al[0], Bh.x, Bh.y);
                mma16816(d1[0], d1[1], d1[2], d1[3], Al[1], Bh.x, Bh.y);
            }
        }
        __syncthreads();
    }

    const int ge = lane >> 2, tig = lane & 3;
    const size_t outbase = (size_t)row * 128 + px0;
#pragma unroll
    for (int mt = 0; mt < 2; mt++) {
#pragma unroll
        for (int j2 = 0; j2 < 8; j2++) {
            const float* dd = &d[(mt * 8 + j2) * 4];
            const int pxl = wp * 32 + mt * 16 + ge;
            const int o = wo * 64 + j2 * 8 + 2 * tig;
            float a0 = sBNa[o], b0v = sBNb[o];
            float a1 = sBNa[o + 1], b1v = sBNb[o + 1];
            float* y0 = yout + ((size_t)(b * 256 + o)) * NPIX + outbase;
            float* y1 = yout + ((size_t)(b * 256 + o + 1)) * NPIX + outbase;
            y0[pxl]     = fmaxf(dd[0] * a0 + b0v, 0.f);
            y1[pxl]     = fmaxf(dd[1] * a1 + b1v, 0.f);
            y0[pxl + 8] = fmaxf(dd[2] * a0 + b0v, 0.f);
            y1[pxl + 8] = fmaxf(dd[3] * a1 + b1v, 0.f);
        }
    }
}

// ---------------- SE / pool ----------------
__global__ void pool_kernel(const float* __restrict__ y, float* __restrict__ pool) {
    int bc = blockIdx.x;
    const float* plane = y + (size_t)bc * NPIX;
    float s = 0.f;
    for (int i = threadIdx.x; i < NPIX; i += 256) s += plane[i];
    __shared__ float red[256];
    red[threadIdx.x] = s;
    __syncthreads();
    for (int st = 128; st > 0; st >>= 1) {
        if (threadIdx.x < st) red[threadIdx.x] += red[threadIdx.x + st];
        __syncthreads();
    }
    if (threadIdx.x == 0) pool[bc] = red[0] * (1.f / NPIX);
}

__global__ void se_kernel(const float* __restrict__ pool,
                          const float* __restrict__ w1,
                          const float* __restrict__ w2,
                          float* __restrict__ scale) {
    int b = blockIdx.x;
    int tid = threadIdx.x;
    __shared__ float sp[256], shd[16];
    sp[tid] = pool[b * 256 + tid];
    __syncthreads();
    if (tid < 16) {
        float a = 0.f;
        for (int c = 0; c < 256; c++) a += sp[c] * w1[tid * 256 + c];
        shd[tid] = fmaxf(a, 0.f);
    }
    __syncthreads();
    float a = 0.f;
#pragma unroll
    for (int j = 0; j < 16; j++) a += shd[j] * w2[tid * 16 + j];
    scale[b * 256 + tid] = 1.f / (1.f + expf(-a));
}

// ---------------- final 1x1 conv + fused SE scale + BN + ReLU (fma2) ------
__global__ void __launch_bounds__(256) final_kernel(
    const float* __restrict__ xin, const float* __restrict__ sc,
    const float* __restrict__ redT,
    const float* __restrict__ bng, const float* __restrict__ bnb,
    const float* __restrict__ bnm, const float* __restrict__ bnv,
    float* __restrict__ out) {
    const int tid = threadIdx.x;
    const int b = blockIdx.y;
    const int p0 = blockIdx.x * 64;
    const int px = tid & 63, og = tid >> 6;
    __shared__ __align__(16) float sX[8][64];
    __shared__ __align__(16) float sWf[8][128];
    __shared__ float sBN[256];
    __shared__ float sSc[256];
    if (tid < 128) {
        float inv = bng[tid] * rsqrtf(bnv[tid] + 1e-5f);
        sBN[tid] = inv;
        sBN[128 + tid] = bnb[tid] - bnm[tid] * inv;
    }
    sSc[tid] = sc[b * 256 + tid];
    union { unsigned long long u[16]; float f[32]; } acc;
#pragma unroll
    for (int j = 0; j < 16; j++) acc.u[j] = 0ull;

    for (int cb = 0; cb < 256; cb += 8) {
        __syncthreads();
        {
            int i = tid;
            sX[i >> 6][i & 63] = xin[((size_t)(b * 256 + cb + (i >> 6))) * NPIX + p0 + (i & 63)]
                                 * sSc[cb + (i >> 6)];
            i = tid + 256;
            sX[i >> 6][i & 63] = xin[((size_t)(b * 256 + cb + (i >> 6))) * NPIX + p0 + (i & 63)]
                                 * sSc[cb + (i >> 6)];
            for (int t = tid; t < 1024; t += 256)
                sWf[t >> 7][t & 127] = redT[(cb + (t >> 7)) * 128 + (t & 127)];
        }
        __syncthreads();
#pragma unroll
        for (int c = 0; c < 8; c++) {
            float xv = sX[c][px];
            unsigned long long xd = pk2(xv, xv);
            const F4* wp = (const F4*)&sWf[c][og * 32];
#pragma unroll
            for (int j = 0; j < 8; j++) {
                F4 w = wp[j];
                fma2(acc.u[2 * j],     xd, w.u[0]);
                fma2(acc.u[2 * j + 1], xd, w.u[1]);
            }
        }
    }
#pragma unroll
    for (int j = 0; j < 32; j++) {
        int o = og * 32 + j;
        float v = acc.f[j] * sBN[o] + sBN[128 + o];
        out[((size_t)(b * 128 + o)) * NPIX + p0 + px] = fmaxf(v, 0.f);
    }
}

// ---------------- launch ----------------
extern "C" void kernel_launch(void* const* d_in, const int* in_sizes, int n_in,
                              void* d_out, int out_size) {
    const float* bev1   = (const float*)d_in[0];
    const float* bev2   = (const float*)d_in[1];
    const float* off_w1 = (const float*)d_in[2];
    const float* off_b1 = (const float*)d_in[3];
    const float* dcn_w1 = (const float*)d_in[4];
    const float* bn1_g  = (const float*)d_in[5];
    const float* bn1_b  = (const float*)d_in[6];
    const float* bn1_m  = (const float*)d_in[7];
    const float* bn1_v  = (const float*)d_in[8];
    const float* se1_w1 = (const float*)d_in[9];
    const float* se1_w2 = (const float*)d_in[10];
    const float* off_w2 = (const float*)d_in[11];
    const float* off_b2 = (const float*)d_in[12];
    const float* dcn_w2 = (const float*)d_in[13];
    const float* bn2_g  = (const float*)d_in[14];
    const float* bn2_b  = (const float*)d_in[15];
    const float* bn2_m  = (const float*)d_in[16];
    const float* bn2_v  = (const float*)d_in[17];
    const float* se2_w1 = (const float*)d_in[18];
    const float* se2_w2 = (const float*)d_in[19];
    const float* red_w  = (const float*)d_in[20];
    const float* bn3_g  = (const float*)d_in[21];
    const float* bn3_b  = (const float*)d_in[22];
    const float* bn3_m  = (const float*)d_in[23];
    const float* bn3_v  = (const float*)d_in[24];

    float *A, *B, *C, *OFF, *RT, *POOL, *SCALE;
    uint2 *BH, *OBH, *OBL;
    cudaGetSymbolAddress((void**)&A,    g_bufA);
    cudaGetSymbolAddress((void**)&B,    g_bufB);
    cudaGetSymbolAddress((void**)&C,    g_bufC);
    cudaGetSymbolAddress((void**)&OFF,  g_off);
    cudaGetSymbolAddress((void**)&BH,   g_bh);
    cudaGetSymbolAddress((void**)&OBH,  g_obh);
    cudaGetSymbolAddress((void**)&OBL,  g_obl);
    cudaGetSymbolAddress((void**)&RT,   g_rT);
    cudaGetSymbolAddress((void**)&POOL, g_pool);
    cudaGetSymbolAddress((void**)&SCALE,g_scale);

    const int OFF_SMEM = 2 * 8704 * 4;          // 69,632 B
    cudaFuncSetAttribute(offconv_hmma,
                         cudaFuncAttributeMaxDynamicSharedMemorySize, OFF_SMEM);
    cudaFuncSetAttribute(deform_hmma,
                         cudaFuncAttributeMaxDynamicSharedMemorySize, DEF_SMEM_BYTES);

    // ---- stage 1 ----
    concat_nhwc<<<dim3(512, 8, 4), 256>>>(bev1, bev2, A, C);
    prep_weights<<<2400, 256>>>(dcn_w1, off_w1, BH, OBH, OBL);
    offconv_hmma<<<dim3(256, 4), 256, OFF_SMEM>>>(C, OBH, OBL, off_b1, OFF);
    deform_hmma<<<dim3(256, 4), 256, DEF_SMEM_BYTES>>>(C, OFF, BH,
                                                 bn1_g, bn1_b, bn1_m, bn1_v, B);
    pool_kernel<<<1024, 256>>>(B, POOL);
    se_kernel<<<4, 256>>>(POOL, se1_w1, se1_w2, SCALE);

    // ---- stage 2 (scale1 fused into to_nhwc) ----
    to_nhwc_scaled<<<dim3(512, 8, 4), 256>>>(B, SCALE, C);
    prep_weights<<<2400, 256>>>(dcn_w2, off_w2, BH, OBH, OBL);
    offconv_hmma<<<dim3(256, 4), 256, OFF_SMEM>>>(C, OBH, OBL, off_b2, OFF);
    deform_hmma<<<dim3(256, 4), 256, DEF_SMEM_BYTES>>>(C, OFF, BH,
                                                 bn2_g, bn2_b, bn2_m, bn2_v, A);
    pool_kernel<<<1024, 256>>>(A, POOL);
    se_kernel<<<4, 256>>>(POOL, se2_w1, se2_w2, SCALE);

    // ---- final (scale2 fused) ----
    transpose_redw<<<128, 256>>>(red_w, RT);
    final_kernel<<<dim3(256, 4), 256>>>(A, SCALE, RT, bn3_g, bn3_b, bn3_m, bn3_v,
                                        (float*)d_out);
}

// round 13
// speedup vs baseline: 5.5593x; 1.1110x over previous
#include <cuda_runtime.h>
#include <cuda_fp16.h>
#include <math.h>
#include <stdint.h>

// ---------------- packed f32x2 helpers (final conv) ----------------
__device__ __forceinline__ unsigned long long pk2(float x, float y) {
    unsigned long long r;
    asm("mov.b64 %0, {%1, %2};" : "=l"(r) : "f"(x), "f"(y));
    return r;
}
__device__ __forceinline__ void fma2(unsigned long long& d,
                                     unsigned long long a, unsigned long long b) {
    asm("fma.rn.f32x2 %0, %1, %2, %0;" : "+l"(d) : "l"(a), "l"(b));
}
union F4 { float4 v; float f[4]; unsigned long long u[2]; };

// ---------------- mma.sync helpers ----------------
__device__ __forceinline__ void ldm4(uint32_t* r, uint32_t addr) {
    asm volatile("ldmatrix.sync.aligned.m8n8.x4.shared.b16 {%0,%1,%2,%3}, [%4];"
                 : "=r"(r[0]), "=r"(r[1]), "=r"(r[2]), "=r"(r[3]) : "r"(addr));
}
__device__ __forceinline__ void mma16816(float& d0, float& d1, float& d2, float& d3,
                                         const uint32_t* a, uint32_t b0, uint32_t b1) {
    asm volatile(
        "mma.sync.aligned.m16n8k16.row.col.f32.f16.f16.f32 "
        "{%0,%1,%2,%3}, {%4,%5,%6,%7}, {%8,%9}, {%0,%1,%2,%3};"
        : "+f"(d0), "+f"(d1), "+f"(d2), "+f"(d3)
        : "r"(a[0]), "r"(a[1]), "r"(a[2]), "r"(a[3]), "r"(b0), "r"(b1));
}
__device__ __forceinline__ uint32_t smem_u32(const void* p) {
    uint32_t a;
    asm("{ .reg .u64 t; cvta.to.shared.u64 t, %1; cvt.u32.u64 %0, t; }"
        : "=r"(a) : "l"(p));
    return a;
}
__device__ __forceinline__ uint32_t packh(float a, float b) {
    __half2 h = __halves2half2(__float2half_rn(a), __float2half_rn(b));
    return *(uint32_t*)&h;
}

// single extern smem symbol shared by kernels
extern __shared__ float smext[];

// ---------------- scratch ----------------
#define NPIX 16384
__device__ __align__(16) float g_bufA[4 * 256 * NPIX];
__device__ __align__(16) float g_bufB[4 * 256 * NPIX];
__device__ __align__(16) float g_bufC[4 * 256 * NPIX];
__device__ __align__(16) float g_off [4 * 100 * NPIX];
__device__ __align__(16) uint2 g_bh  [50 * 8 * 32 * 32];
__device__ __align__(16) uint2 g_obh [50 * 8 * 16 * 32];
__device__ __align__(16) float g_rT  [256 * 128];
__device__ float g_pool[1024];
__device__ float g_scale[1024];

// ---------------- fused concat -> NCHW A + NHWC C ----------------
__global__ void __launch_bounds__(256) concat_nhwc(
    const float* __restrict__ bev1, const float* __restrict__ bev2,
    float* __restrict__ A, float* __restrict__ C) {
    __shared__ float tile[32][33];
    const int bp = blockIdx.x, bc = blockIdx.y, b = blockIdx.z;
    const int tx = threadIdx.x & 31, ty = threadIdx.x >> 5;
    const float* src = ((bc < 4)
        ? bev1 + ((size_t)b * 128 + bc * 32) * NPIX
        : bev2 + ((size_t)b * 128 + (bc - 4) * 32) * NPIX) + bp * 32;
    float* adst = A + ((size_t)b * 256 + bc * 32) * NPIX + bp * 32;
#pragma unroll
    for (int r = 0; r < 4; r++) {
        int c = ty + r * 8;
        float v = src[(size_t)c * NPIX + tx];
        tile[c][tx] = v;
        adst[(size_t)c * NPIX + tx] = v;
    }
    __syncthreads();
    float* dst = C + ((size_t)b * NPIX + bp * 32) * 256 + bc * 32;
#pragma unroll
    for (int r = 0; r < 4; r++) {
        int p = ty + r * 8;
        dst[(size_t)p * 256 + tx] = tile[tx][p];
    }
}

// ---------------- NCHW -> NHWC transpose with fused SE scale --------------
__global__ void __launch_bounds__(256) to_nhwc_scaled(
    const float* __restrict__ in, const float* __restrict__ sc,
    float* __restrict__ outp) {
    __shared__ float tile[32][33];
    __shared__ float sSc[32];
    const int bp = blockIdx.x, bc = blockIdx.y, b = blockIdx.z;
    const int tx = threadIdx.x & 31, ty = threadIdx.x >> 5;
    if (threadIdx.x < 32) sSc[threadIdx.x] = sc[b * 256 + bc * 32 + threadIdx.x];
    const float* src = in + ((size_t)b * 256 + bc * 32) * NPIX + bp * 32;
#pragma unroll
    for (int r = 0; r < 4; r++) {
        int c = ty + r * 8;
        tile[c][tx] = src[(size_t)c * NPIX + tx];
    }
    __syncthreads();
    float* dst = outp + ((size_t)b * NPIX + bp * 32) * 256 + bc * 32;
    const float s = sSc[tx];
#pragma unroll
    for (int r = 0; r < 4; r++) {
        int p = ty + r * 8;
        dst[(size_t)p * 256 + tx] = tile[tx][p] * s;
    }
}

// ---------------- weight prep: dcn hi + off hi fragment packs --------------
__global__ void prep_weights(const float* __restrict__ dcnw,
                             const float* __restrict__ offw,
                             uint2* __restrict__ BH,
                             uint2* __restrict__ OBH) {
    int idx = blockIdx.x * 256 + threadIdx.x;
    if (idx < 409600) {
        const int t  = idx & 31;
        const int j  = (idx >> 5) & 31;
        const int s  = (idx >> 10) & 7;
        const int gk = idx >> 13;
        const int k = gk % 25, g = gk / 25;
        const int o = j * 8 + (t >> 2);
        const int c0 = s * 16 + 2 * (t & 3);
        float w0 = dcnw[o * 6400 + (g * 128 + c0    ) * 25 + k] * 64.f;
        float w1 = dcnw[o * 6400 + (g * 128 + c0 + 1) * 25 + k] * 64.f;
        float w8 = dcnw[o * 6400 + (g * 128 + c0 + 8) * 25 + k] * 64.f;
        float w9 = dcnw[o * 6400 + (g * 128 + c0 + 9) * 25 + k] * 64.f;
        BH[idx] = make_uint2(packh(__half2float(__float2half_rn(w0)),
                                   __half2float(__float2half_rn(w1))),
                             packh(__half2float(__float2half_rn(w8)),
                                   __half2float(__float2half_rn(w9))));
    } else if (idx < 614400) {
        const int i2 = idx - 409600;
        const int t  = i2 & 31;
        const int j  = (i2 >> 5) & 15;
        const int s  = (i2 >> 9) & 7;
        const int it = i2 >> 12;
        const int k = it >> 1, h = it & 1;
        const int o = j * 8 + (t >> 2);
        const int c0 = h * 128 + s * 16 + 2 * (t & 3);
        float w0 = 0.f, w1 = 0.f, w8 = 0.f, w9 = 0.f;
        if (o < 100) {
            w0 = offw[o * 6400 + (c0    ) * 25 + k] * 1024.f;
            w1 = offw[o * 6400 + (c0 + 1) * 25 + k] * 1024.f;
            w8 = offw[o * 6400 + (c0 + 8) * 25 + k] * 1024.f;
            w9 = offw[o * 6400 + (c0 + 9) * 25 + k] * 1024.f;
        }
        OBH[i2] = make_uint2(packh(__half2float(__float2half_rn(w0)),
                                   __half2float(__float2half_rn(w1))),
                             packh(__half2float(__float2half_rn(w8)),
                                   __half2float(__float2half_rn(w9))));
    }
}

__global__ void transpose_redw(const float* __restrict__ w, float* __restrict__ dst) {
    int idx = blockIdx.x * 256 + threadIdx.x;
    int o = idx & 127;
    int c = idx >> 7;
    dst[idx] = w[o * 256 + c];
}

// ---------------- offset conv via mma.sync (fp16, single product) ----------
// dynamic smem: uint32 Sbuf[2][4352] = 34,816 B
__global__ void __launch_bounds__(256, 2) offconv_hmma(
    const float* __restrict__ xh,
    const uint2* __restrict__ OBH,
    const float* __restrict__ offb,
    float* __restrict__ offout) {
    uint32_t* Sbuf = (uint32_t*)smext;

    const int tid = threadIdx.x;
    const int lane = tid & 31, warp = tid >> 5;
    const int b = blockIdx.y;
    const int row = blockIdx.x >> 1;
    const int px0 = (blockIdx.x & 1) << 6;

    const int wo = warp & 1;
    const int wp = warp >> 1;
    const int sh = warp & 1;
    const int cq = warp >> 1;
    const int lg = lane >> 3;
    const int c0s = cq * 32 + (lane & 7) * 4;

    float d[32];
#pragma unroll
    for (int q = 0; q < 32; q++) d[q] = 0.f;

    const float4 zero4 = make_float4(0.f, 0.f, 0.f, 0.f);
    const uint32_t sbase = smem_u32(Sbuf);
    const uint32_t lanePat = (lane & 15) * 272 + (lane >> 4) * 16;
    const float* xb = xh + (size_t)b * NPIX * 256;

    auto sample_tap = [&](int it2, uint32_t* ShB) {
        const int k2 = it2 >> 1, h2 = it2 & 1;
        const int kh2 = k2 / 5, kw2 = k2 % 5;
        const int gy2 = row + kh2 - 2;
        const bool vy2 = (gy2 >= 0) & (gy2 < 128);
#pragma unroll
        for (int j = 0; j < 8; j++) {
            const int p = sh * 32 + j * 4 + lg;
            const int gx = px0 + p + kw2 - 2;
            float4 va = zero4;
            if (vy2 && gx >= 0 && gx < 128)
                va = *(const float4*)(xb + ((size_t)gy2 * 128 + gx) * 256 + h2 * 128 + c0s);
            const int wi = p * 68 + (c0s >> 1);
            *(uint2*)&ShB[wi] = make_uint2(packh(va.x, va.y), packh(va.z, va.w));
        }
    };

    sample_tap(0, Sbuf);
    __syncthreads();

    for (int it = 0; it < 50; it++) {
        const int cur = it & 1;
        if (it < 49) sample_tap(it + 1, Sbuf + (cur ^ 1) * 4352);
        const uint32_t aH = sbase + cur * 17408 + lanePat;
        const uint2* BHt = OBH + ((size_t)it * 8 * 16 + wo * 8) * 32 + lane;
#pragma unroll
        for (int s = 0; s < 8; s++) {
            uint32_t Ah[4];
            ldm4(Ah, aH + (wp * 16) * 272 + s * 32);
            const uint2* bh = BHt + (size_t)s * 512;
#pragma unroll
            for (int j2 = 0; j2 < 8; j2++) {
                uint2 Bh = bh[j2 * 32];
                float* dd = &d[j2 * 4];
                mma16816(dd[0], dd[1], dd[2], dd[3], Ah, Bh.x, Bh.y);
            }
        }
        __syncthreads();
    }

    const int g2 = lane >> 2, tig = lane & 3;
    const int pxl = wp * 16 + g2;
    const size_t outbase = (size_t)row * 128 + px0;
#pragma unroll
    for (int j2 = 0; j2 < 8; j2++) {
        const int o = wo * 64 + j2 * 8 + 2 * tig;
        if (o < 100) {
            const float* dd = &d[j2 * 4];
            const float b0 = offb[o], b1 = offb[o + 1];
            float* y0 = offout + ((size_t)(b * 100 + o)) * NPIX + outbase;
            float* y1 = y0 + NPIX;
            y0[pxl]     = dd[0] * 0.0009765625f + b0;
            y1[pxl]     = dd[1] * 0.0009765625f + b1;
            y0[pxl + 8] = dd[2] * 0.0009765625f + b0;
            y1[pxl + 8] = dd[3] * 0.0009765625f + b1;
        }
    }
}

// ---------------- deformable conv via mma.sync (2-product split) -----------
// smem floats: sPy[3200] sPx[3200] sBNa[256] sBNb[256] | u32 Sbuf[2][8704]
#define DEF_SMEM_BYTES ((6912 + 17408) * 4)
__global__ void __launch_bounds__(256, 2) deform_hmma(
    const float* __restrict__ xh,
    const float* __restrict__ off,
    const uint2* __restrict__ BH,
    const float* __restrict__ bng, const float* __restrict__ bnb,
    const float* __restrict__ bnm, const float* __restrict__ bnv,
    float* __restrict__ yout) {
    float* sPy = smext;
    float* sPx = smext + 3200;
    float* sBNa = smext + 6400;
    float* sBNb = smext + 6656;
    uint32_t* Sbuf = (uint32_t*)(smext + 6912);

    const int tid = threadIdx.x;
    const int lane = tid & 31, warp = tid >> 5;
    const int b = blockIdx.y;
    const int row = blockIdx.x >> 1;
    const int px0 = (blockIdx.x & 1) << 6;

    const int wo = warp & 3;
    const int wp = warp >> 2;
    const int sh = warp & 1;
    const int cq = warp >> 1;
    const int lg = lane >> 3;
    const int c0s = cq * 32 + (lane & 7) * 4;

    if (tid < 256) {
        float inv = bng[tid] * rsqrtf(bnv[tid] + 1e-5f);
        sBNa[tid] = inv * 0.015625f;
        sBNb[tid] = bnb[tid] - bnm[tid] * inv;
    }
    for (int idx = tid; idx < 3200; idx += 256) {
        int gk = idx >> 6, p = idx & 63;
        int g = gk / 25, k = gk % 25;
        int kh = k / 5, kw = k % 5;
        int ch = b * 100 + g * 50 + 2 * k;
        float oy = off[(size_t)ch * NPIX + row * 128 + px0 + p];
        float ox = off[(size_t)(ch + 1) * NPIX + row * 128 + px0 + p];
        sPy[idx] = (float)(row + kh - 2) + oy;
        sPx[idx] = (float)(px0 + p + kw - 2) + ox;
    }
    __syncthreads();

    float d[64];
#pragma unroll
    for (int q = 0; q < 64; q++) d[q] = 0.f;

    const float4 zero4 = make_float4(0.f, 0.f, 0.f, 0.f);
    const uint32_t sbase = smem_u32(Sbuf);
    const uint32_t lanePat = (lane & 15) * 272 + (lane >> 4) * 16;

    auto sample_tap = [&](int gk2, uint32_t* ShB, uint32_t* SlB) {
        const int gs = (gk2 >= 25) ? 1 : 0;
        const float* xgb = xh + (size_t)b * NPIX * 256 + gs * 128 + c0s;
#pragma unroll
        for (int j = 0; j < 8; j++) {
            const int p = sh * 32 + j * 4 + lg;
            const float py = sPy[gk2 * 64 + p];
            const float pv = sPx[gk2 * 64 + p];
            const float y0f = floorf(py), x0f = floorf(pv);
            const float wy1 = py - y0f, wx1 = pv - x0f;
            const float wy0 = 1.f - wy1, wx0 = 1.f - wx1;
            const float w00 = wy0 * wx0, w01 = wy0 * wx1;
            const float w10 = wy1 * wx0, w11 = wy1 * wx1;
            const int iy = (int)y0f, ix = (int)x0f;
            const bool vy0 = (iy >= 0) & (iy < 128);
            const bool vy1 = (iy >= -1) & (iy < 127);
            const bool vx0 = (ix >= 0) & (ix < 128);
            const bool vx1 = (ix >= -1) & (ix < 127);
            const long base = ((long)iy * 128 + ix) * 256;
            float4 va = (vy0 & vx0) ? *(const float4*)(xgb + base) : zero4;
            float4 vb = (vy0 & vx1) ? *(const float4*)(xgb + base + 256) : zero4;
            float4 vc = (vy1 & vx0) ? *(const float4*)(xgb + base + 128 * 256) : zero4;
            float4 vd4 = (vy1 & vx1) ? *(const float4*)(xgb + base + 128 * 256 + 256) : zero4;
            float r0 = w00 * va.x + w01 * vb.x + w10 * vc.x + w11 * vd4.x;
            float r1 = w00 * va.y + w01 * vb.y + w10 * vc.y + w11 * vd4.y;
            float r2 = w00 * va.z + w01 * vb.z + w10 * vc.z + w11 * vd4.z;
            float r3 = w00 * va.w + w01 * vb.w + w10 * vc.w + w11 * vd4.w;
            float h0 = __half2float(__float2half_rn(r0));
            float h1 = __half2float(__float2half_rn(r1));
            float h2f = __half2float(__float2half_rn(r2));
            float h3 = __half2float(__float2half_rn(r3));
            const int wi = p * 68 + (c0s >> 1);
            *(uint2*)&ShB[wi] = make_uint2(packh(h0, h1), packh(h2f, h3));
            *(uint2*)&SlB[wi] = make_uint2(packh(r0 - h0, r1 - h1),
                                           packh(r2 - h2f, r3 - h3));
        }
    };

    sample_tap(0, Sbuf, Sbuf + 4352);
    __syncthreads();

    for (int gk = 0; gk < 50; gk++) {
        const int cur = gk & 1;
        if (gk < 49) {
            uint32_t* nb = Sbuf + (cur ^ 1) * 8704;
            sample_tap(gk + 1, nb, nb + 4352);
        }
        const uint32_t aH = sbase + cur * 34816 + lanePat;
        const uint32_t aL = aH + 17408;
        const uint2* BHt = BH + ((size_t)gk * 8 * 32 + wo * 8) * 32 + lane;
#pragma unroll
        for (int s = 0; s < 8; s++) {
            uint32_t Ah[2][4], Al[2][4];
            ldm4(Ah[0], aH + (wp * 32     ) * 272 + s * 32);
            ldm4(Ah[1], aH + (wp * 32 + 16) * 272 + s * 32);
            ldm4(Al[0], aL + (wp * 32     ) * 272 + s * 32);
            ldm4(Al[1], aL + (wp * 32 + 16) * 272 + s * 32);
            const uint2* bh = BHt + (size_t)s * 1024;
#pragma unroll
            for (int j2 = 0; j2 < 8; j2++) {
                uint2 Bh = bh[j2 * 32];
                float* d0 = &d[(0 * 8 + j2) * 4];
                float* d1 = &d[(1 * 8 + j2) * 4];
                mma16816(d0[0], d0[1], d0[2], d0[3], Ah[0], Bh.x, Bh.y);
                mma16816(d1[0], d1[1], d1[2], d1[3], Ah[1], Bh.x, Bh.y);
                mma16816(d0[0], d0[1], d0[2], d0[3], Al[0], Bh.x, Bh.y);
                mma16816(d1[0], d1[1], d1[2], d1[3], Al[1], Bh.x, Bh.y);
            }
        }
        __syncthreads();
    }

    const int ge = lane >> 2, tig = lane & 3;
    const size_t outbase = (size_t)row * 128 + px0;
#pragma unroll
    for (int mt = 0; mt < 2; mt++) {
#pragma unroll
        for (int j2 = 0; j2 < 8; j2++) {
            const float* dd = &d[(mt * 8 + j2) * 4];
            const int pxl = wp * 32 + mt * 16 + ge;
            const int o = wo * 64 + j2 * 8 + 2 * tig;
            float a0 = sBNa[o], b0v = sBNb[o];
            float a1 = sBNa[o + 1], b1v = sBNb[o + 1];
            float* y0 = yout + ((size_t)(b * 256 + o)) * NPIX + outbase;
            float* y1 = yout + ((size_t)(b * 256 + o + 1)) * NPIX + outbase;
            y0[pxl]     = fmaxf(dd[0] * a0 + b0v, 0.f);
            y1[pxl]     = fmaxf(dd[1] * a1 + b1v, 0.f);
            y0[pxl + 8] = fmaxf(dd[2] * a0 + b0v, 0.f);
            y1[pxl + 8] = fmaxf(dd[3] * a1 + b1v, 0.f);
        }
    }
}

// ---------------- SE / pool ----------------
__global__ void pool_kernel(const float* __restrict__ y, float* __restrict__ pool) {
    int bc = blockIdx.x;
    const float* plane = y + (size_t)bc * NPIX;
    float s = 0.f;
    for (int i = threadIdx.x; i < NPIX; i += 256) s += plane[i];
    __shared__ float red[256];
    red[threadIdx.x] = s;
    __syncthreads();
    for (int st = 128; st > 0; st >>= 1) {
        if (threadIdx.x < st) red[threadIdx.x] += red[threadIdx.x + st];
        __syncthreads();
    }
    if (threadIdx.x == 0) pool[bc] = red[0] * (1.f / NPIX);
}

__global__ void se_kernel(const float* __restrict__ pool,
                          const float* __restrict__ w1,
                          const float* __restrict__ w2,
                          float* __restrict__ scale) {
    int b = blockIdx.x;
    int tid = threadIdx.x;
    __shared__ float sp[256], shd[16];
    sp[tid] = pool[b * 256 + tid];
    __syncthreads();
    if (tid < 16) {
        float a = 0.f;
        for (int c = 0; c < 256; c++) a += sp[c] * w1[tid * 256 + c];
        shd[tid] = fmaxf(a, 0.f);
    }
    __syncthreads();
    float a = 0.f;
#pragma unroll
    for (int j = 0; j < 16; j++) a += shd[j] * w2[tid * 16 + j];
    scale[b * 256 + tid] = 1.f / (1.f + expf(-a));
}

// ---------------- final 1x1 conv + fused SE scale + BN + ReLU (fma2) ------
__global__ void __launch_bounds__(256) final_kernel(
    const float* __restrict__ xin, const float* __restrict__ sc,
    const float* __restrict__ redT,
    const float* __restrict__ bng, const float* __restrict__ bnb,
    const float* __restrict__ bnm, const float* __restrict__ bnv,
    float* __restrict__ out) {
    const int tid = threadIdx.x;
    const int b = blockIdx.y;
    const int p0 = blockIdx.x * 64;
    const int px = tid & 63, og = tid >> 6;
    __shared__ __align__(16) float sX[8][64];
    __shared__ __align__(16) float sWf[8][128];
    __shared__ float sBN[256];
    __shared__ float sSc[256];
    if (tid < 128) {
        float inv = bng[tid] * rsqrtf(bnv[tid] + 1e-5f);
        sBN[tid] = inv;
        sBN[128 + tid] = bnb[tid] - bnm[tid] * inv;
    }
    sSc[tid] = sc[b * 256 + tid];
    union { unsigned long long u[16]; float f[32]; } acc;
#pragma unroll
    for (int j = 0; j < 16; j++) acc.u[j] = 0ull;

    for (int cb = 0; cb < 256; cb += 8) {
        __syncthreads();
        {
            int i = tid;
            sX[i >> 6][i & 63] = xin[((size_t)(b * 256 + cb + (i >> 6))) * NPIX + p0 + (i & 63)]
                                 * sSc[cb + (i >> 6)];
            i = tid + 256;
            sX[i >> 6][i & 63] = xin[((size_t)(b * 256 + cb + (i >> 6))) * NPIX + p0 + (i & 63)]
                                 * sSc[cb + (i >> 6)];
            for (int t = tid; t < 1024; t += 256)
                sWf[t >> 7][t & 127] = redT[(cb + (t >> 7)) * 128 + (t & 127)];
        }
        __syncthreads();
#pragma unroll
        for (int c = 0; c < 8; c++) {
            float xv = sX[c][px];
            unsigned long long xd = pk2(xv, xv);
            const F4* wp = (const F4*)&sWf[c][og * 32];
#pragma unroll
            for (int j = 0; j < 8; j++) {
                F4 w = wp[j];
                fma2(acc.u[2 * j],     xd, w.u[0]);
                fma2(acc.u[2 * j + 1], xd, w.u[1]);
            }
        }
    }
#pragma unroll
    for (int j = 0; j < 32; j++) {
        int o = og * 32 + j;
        float v = acc.f[j] * sBN[o] + sBN[128 + o];
        out[((size_t)(b * 128 + o)) * NPIX + p0 + px] = fmaxf(v, 0.f);
    }
}

// ---------------- launch ----------------
extern "C" void kernel_launch(void* const* d_in, const int* in_sizes, int n_in,
                              void* d_out, int out_size) {
    const float* bev1   = (const float*)d_in[0];
    const float* bev2   = (const float*)d_in[1];
    const float* off_w1 = (const float*)d_in[2];
    const float* off_b1 = (const float*)d_in[3];
    const float* dcn_w1 = (const float*)d_in[4];
    const float* bn1_g  = (const float*)d_in[5];
    const float* bn1_b  = (const float*)d_in[6];
    const float* bn1_m  = (const float*)d_in[7];
    const float* bn1_v  = (const float*)d_in[8];
    const float* se1_w1 = (const float*)d_in[9];
    const float* se1_w2 = (const float*)d_in[10];
    const float* off_w2 = (const float*)d_in[11];
    const float* off_b2 = (const float*)d_in[12];
    const float* dcn_w2 = (const float*)d_in[13];
    const float* bn2_g  = (const float*)d_in[14];
    const float* bn2_b  = (const float*)d_in[15];
    const float* bn2_m  = (const float*)d_in[16];
    const float* bn2_v  = (const float*)d_in[17];
    const float* se2_w1 = (const float*)d_in[18];
    const float* se2_w2 = (const float*)d_in[19];
    const float* red_w  = (const float*)d_in[20];
    const float* bn3_g  = (const float*)d_in[21];
    const float* bn3_b  = (const float*)d_in[22];
    const float* bn3_m  = (const float*)d_in[23];
    const float* bn3_v  = (const float*)d_in[24];

    float *A, *B, *C, *OFF, *RT, *POOL, *SCALE;
    uint2 *BH, *OBH;
    cudaGetSymbolAddress((void**)&A,    g_bufA);
    cudaGetSymbolAddress((void**)&B,    g_bufB);
    cudaGetSymbolAddress((void**)&C,    g_bufC);
    cudaGetSymbolAddress((void**)&OFF,  g_off);
    cudaGetSymbolAddress((void**)&BH,   g_bh);
    cudaGetSymbolAddress((void**)&OBH,  g_obh);
    cudaGetSymbolAddress((void**)&RT,   g_rT);
    cudaGetSymbolAddress((void**)&POOL, g_pool);
    cudaGetSymbolAddress((void**)&SCALE,g_scale);

    const int OFF_SMEM = 2 * 4352 * 4;          // 34,816 B
    cudaFuncSetAttribute(offconv_hmma,
                         cudaFuncAttributeMaxDynamicSharedMemorySize, OFF_SMEM);
    cudaFuncSetAttribute(deform_hmma,
                         cudaFuncAttributeMaxDynamicSharedMemorySize, DEF_SMEM_BYTES);

    // ---- stage 1 ----
    concat_nhwc<<<dim3(512, 8, 4), 256>>>(bev1, bev2, A, C);
    prep_weights<<<2400, 256>>>(dcn_w1, off_w1, BH, OBH);
    offconv_hmma<<<dim3(256, 4), 256, OFF_SMEM>>>(C, OBH, off_b1, OFF);
    deform_hmma<<<dim3(256, 4), 256, DEF_SMEM_BYTES>>>(C, OFF, BH,
                                                 bn1_g, bn1_b, bn1_m, bn1_v, B);
    pool_kernel<<<1024, 256>>>(B, POOL);
    se_kernel<<<4, 256>>>(POOL, se1_w1, se1_w2, SCALE);

    // ---- stage 2 (scale1 fused into to_nhwc) ----
    to_nhwc_scaled<<<dim3(512, 8, 4), 256>>>(B, SCALE, C);
    prep_weights<<<2400, 256>>>(dcn_w2, off_w2, BH, OBH);
    offconv_hmma<<<dim3(256, 4), 256, OFF_SMEM>>>(C, OBH, off_b2, OFF);
    deform_hmma<<<dim3(256, 4), 256, DEF_SMEM_BYTES>>>(C, OFF, BH,
                                                 bn2_g, bn2_b, bn2_m, bn2_v, A);
    pool_kernel<<<1024, 256>>>(A, POOL);
    se_kernel<<<4, 256>>>(POOL, se2_w1, se2_w2, SCALE);

    // ---- final (scale2 fused) ----
    transpose_redw<<<128, 256>>>(red_w, RT);
    final_kernel<<<dim3(256, 4), 256>>>(A, SCALE, RT, bn3_g, bn3_b, bn3_m, bn3_v,
                                        (float*)d_out);
}

// round 14
// speedup vs baseline: 5.5856x; 1.0047x over previous
#include <cuda_runtime.h>
#include <cuda_fp16.h>
#include <math.h>
#include <stdint.h>

// ---------------- packed f32x2 helpers (final conv) ----------------
__device__ __forceinline__ unsigned long long pk2(float x, float y) {
    unsigned long long r;
    asm("mov.b64 %0, {%1, %2};" : "=l"(r) : "f"(x), "f"(y));
    return r;
}
__device__ __forceinline__ void fma2(unsigned long long& d,
                                     unsigned long long a, unsigned long long b) {
    asm("fma.rn.f32x2 %0, %1, %2, %0;" : "+l"(d) : "l"(a), "l"(b));
}
union F4 { float4 v; float f[4]; unsigned long long u[2]; };

// ---------------- mma.sync helpers ----------------
__device__ __forceinline__ void ldm4(uint32_t* r, uint32_t addr) {
    asm volatile("ldmatrix.sync.aligned.m8n8.x4.shared.b16 {%0,%1,%2,%3}, [%4];"
                 : "=r"(r[0]), "=r"(r[1]), "=r"(r[2]), "=r"(r[3]) : "r"(addr));
}
__device__ __forceinline__ void mma16816(float& d0, float& d1, float& d2, float& d3,
                                         const uint32_t* a, uint32_t b0, uint32_t b1) {
    asm volatile(
        "mma.sync.aligned.m16n8k16.row.col.f32.f16.f16.f32 "
        "{%0,%1,%2,%3}, {%4,%5,%6,%7}, {%8,%9}, {%0,%1,%2,%3};"
        : "+f"(d0), "+f"(d1), "+f"(d2), "+f"(d3)
        : "r"(a[0]), "r"(a[1]), "r"(a[2]), "r"(a[3]), "r"(b0), "r"(b1));
}
__device__ __forceinline__ uint32_t smem_u32(const void* p) {
    uint32_t a;
    asm("{ .reg .u64 t; cvta.to.shared.u64 t, %1; cvt.u32.u64 %0, t; }"
        : "=r"(a) : "l"(p));
    return a;
}
__device__ __forceinline__ uint32_t packh(float a, float b) {
    __half2 h = __halves2half2(__float2half_rn(a), __float2half_rn(b));
    return *(uint32_t*)&h;
}

// single extern smem symbol shared by kernels
extern __shared__ float smext[];

// ---------------- scratch ----------------
#define NPIX 16384
__device__ __align__(16) float  g_bufA[4 * 256 * NPIX];
__device__ __align__(16) float  g_bufB[4 * 256 * NPIX];
__device__ __align__(16) __half g_bufC[4 * 256 * NPIX];   // NHWC fp16
__device__ __align__(16) float  g_off [4 * 100 * NPIX];
__device__ __align__(16) uint2  g_bh  [50 * 8 * 32 * 32];
__device__ __align__(16) uint2  g_obh [50 * 8 * 16 * 32];
__device__ __align__(16) float  g_rT  [256 * 128];
__device__ float g_pool[1024];
__device__ float g_scale[1024];

// ---------------- concat -> NHWC fp16 C (dead NCHW store removed) ----------
__global__ void __launch_bounds__(256) concat_nhwc(
    const float* __restrict__ bev1, const float* __restrict__ bev2,
    __half* __restrict__ C) {
    __shared__ float tile[32][33];
    const int bp = blockIdx.x, bc = blockIdx.y, b = blockIdx.z;
    const int tx = threadIdx.x & 31, ty = threadIdx.x >> 5;
    const float* src = ((bc < 4)
        ? bev1 + ((size_t)b * 128 + bc * 32) * NPIX
        : bev2 + ((size_t)b * 128 + (bc - 4) * 32) * NPIX) + bp * 32;
#pragma unroll
    for (int r = 0; r < 4; r++) {
        int c = ty + r * 8;
        tile[c][tx] = src[(size_t)c * NPIX + tx];
    }
    __syncthreads();
    __half* dst = C + ((size_t)b * NPIX + bp * 32) * 256 + bc * 32;
#pragma unroll
    for (int r = 0; r < 4; r++) {
        int p = ty + r * 8;
        dst[(size_t)p * 256 + tx] = __float2half_rn(tile[tx][p]);
    }
}

// ---------------- NCHW -> NHWC fp16 transpose with fused SE scale ----------
__global__ void __launch_bounds__(256) to_nhwc_scaled(
    const float* __restrict__ in, const float* __restrict__ sc,
    __half* __restrict__ outp) {
    __shared__ float tile[32][33];
    __shared__ float sSc[32];
    const int bp = blockIdx.x, bc = blockIdx.y, b = blockIdx.z;
    const int tx = threadIdx.x & 31, ty = threadIdx.x >> 5;
    if (threadIdx.x < 32) sSc[threadIdx.x] = sc[b * 256 + bc * 32 + threadIdx.x];
    const float* src = in + ((size_t)b * 256 + bc * 32) * NPIX + bp * 32;
#pragma unroll
    for (int r = 0; r < 4; r++) {
        int c = ty + r * 8;
        tile[c][tx] = src[(size_t)c * NPIX + tx];
    }
    __syncthreads();
    __half* dst = outp + ((size_t)b * NPIX + bp * 32) * 256 + bc * 32;
    const float s = sSc[tx];
#pragma unroll
    for (int r = 0; r < 4; r++) {
        int p = ty + r * 8;
        dst[(size_t)p * 256 + tx] = __float2half_rn(tile[tx][p] * s);
    }
}

// ---------------- weight prep: dcn hi + off hi fragment packs --------------
__global__ void prep_weights(const float* __restrict__ dcnw,
                             const float* __restrict__ offw,
                             uint2* __restrict__ BH,
                             uint2* __restrict__ OBH) {
    int idx = blockIdx.x * 256 + threadIdx.x;
    if (idx < 409600) {
        const int t  = idx & 31;
        const int j  = (idx >> 5) & 31;
        const int s  = (idx >> 10) & 7;
        const int gk = idx >> 13;
        const int k = gk % 25, g = gk / 25;
        const int o = j * 8 + (t >> 2);
        const int c0 = s * 16 + 2 * (t & 3);
        float w0 = dcnw[o * 6400 + (g * 128 + c0    ) * 25 + k] * 64.f;
        float w1 = dcnw[o * 6400 + (g * 128 + c0 + 1) * 25 + k] * 64.f;
        float w8 = dcnw[o * 6400 + (g * 128 + c0 + 8) * 25 + k] * 64.f;
        float w9 = dcnw[o * 6400 + (g * 128 + c0 + 9) * 25 + k] * 64.f;
        BH[idx] = make_uint2(packh(__half2float(__float2half_rn(w0)),
                                   __half2float(__float2half_rn(w1))),
                             packh(__half2float(__float2half_rn(w8)),
                                   __half2float(__float2half_rn(w9))));
    } else if (idx < 614400) {
        const int i2 = idx - 409600;
        const int t  = i2 & 31;
        const int j  = (i2 >> 5) & 15;
        const int s  = (i2 >> 9) & 7;
        const int it = i2 >> 12;
        const int k = it >> 1, h = it & 1;
        const int o = j * 8 + (t >> 2);
        const int c0 = h * 128 + s * 16 + 2 * (t & 3);
        float w0 = 0.f, w1 = 0.f, w8 = 0.f, w9 = 0.f;
        if (o < 100) {
            w0 = offw[o * 6400 + (c0    ) * 25 + k] * 1024.f;
            w1 = offw[o * 6400 + (c0 + 1) * 25 + k] * 1024.f;
            w8 = offw[o * 6400 + (c0 + 8) * 25 + k] * 1024.f;
            w9 = offw[o * 6400 + (c0 + 9) * 25 + k] * 1024.f;
        }
        OBH[i2] = make_uint2(packh(__half2float(__float2half_rn(w0)),
                                   __half2float(__float2half_rn(w1))),
                             packh(__half2float(__float2half_rn(w8)),
                                   __half2float(__float2half_rn(w9))));
    }
}

__global__ void transpose_redw(const float* __restrict__ w, float* __restrict__ dst) {
    int idx = blockIdx.x * 256 + threadIdx.x;
    int o = idx & 127;
    int c = idx >> 7;
    dst[idx] = w[o * 256 + c];
}

// ---------------- offset conv via mma.sync (fp16 in, single product) -------
// dynamic smem: uint32 Sbuf[2][4352] = 34,816 B
__global__ void __launch_bounds__(256, 2) offconv_hmma(
    const __half* __restrict__ xh,   // NHWC fp16 [b][p][256]
    const uint2* __restrict__ OBH,
    const float* __restrict__ offb,
    float* __restrict__ offout) {
    uint32_t* Sbuf = (uint32_t*)smext;

    const int tid = threadIdx.x;
    const int lane = tid & 31, warp = tid >> 5;
    const int b = blockIdx.y;
    const int row = blockIdx.x >> 1;
    const int px0 = (blockIdx.x & 1) << 6;

    const int wo = warp & 1;
    const int wp = warp >> 1;
    const int sh = warp & 1;
    const int cq = warp >> 1;
    const int lg = lane >> 3;
    const int c0s = cq * 32 + (lane & 7) * 4;

    float d[32];
#pragma unroll
    for (int q = 0; q < 32; q++) d[q] = 0.f;

    const uint32_t sbase = smem_u32(Sbuf);
    const uint32_t lanePat = (lane & 15) * 272 + (lane >> 4) * 16;
    const __half* xb = xh + (size_t)b * NPIX * 256;

    auto sample_tap = [&](int it2, uint32_t* ShB) {
        const int k2 = it2 >> 1, h2 = it2 & 1;
        const int kh2 = k2 / 5, kw2 = k2 % 5;
        const int gy2 = row + kh2 - 2;
        const bool vy2 = (gy2 >= 0) & (gy2 < 128);
#pragma unroll
        for (int j = 0; j < 8; j++) {
            const int p = sh * 32 + j * 4 + lg;
            const int gx = px0 + p + kw2 - 2;
            uint2 va = make_uint2(0u, 0u);
            if (vy2 && gx >= 0 && gx < 128)
                va = *(const uint2*)(xb + ((size_t)gy2 * 128 + gx) * 256 + h2 * 128 + c0s);
            *(uint2*)&ShB[p * 68 + (c0s >> 1)] = va;
        }
    };

    sample_tap(0, Sbuf);
    __syncthreads();

    for (int it = 0; it < 50; it++) {
        const int cur = it & 1;
        if (it < 49) sample_tap(it + 1, Sbuf + (cur ^ 1) * 4352);
        const uint32_t aH = sbase + cur * 17408 + lanePat;
        const uint2* BHt = OBH + ((size_t)it * 8 * 16 + wo * 8) * 32 + lane;
#pragma unroll
        for (int s = 0; s < 8; s++) {
            uint32_t Ah[4];
            ldm4(Ah, aH + (wp * 16) * 272 + s * 32);
            const uint2* bh = BHt + (size_t)s * 512;
#pragma unroll
            for (int j2 = 0; j2 < 8; j2++) {
                uint2 Bh = bh[j2 * 32];
                float* dd = &d[j2 * 4];
                mma16816(dd[0], dd[1], dd[2], dd[3], Ah, Bh.x, Bh.y);
            }
        }
        __syncthreads();
    }

    const int g2 = lane >> 2, tig = lane & 3;
    const int pxl = wp * 16 + g2;
    const size_t outbase = (size_t)row * 128 + px0;
#pragma unroll
    for (int j2 = 0; j2 < 8; j2++) {
        const int o = wo * 64 + j2 * 8 + 2 * tig;
        if (o < 100) {
            const float* dd = &d[j2 * 4];
            const float b0 = offb[o], b1 = offb[o + 1];
            float* y0 = offout + ((size_t)(b * 100 + o)) * NPIX + outbase;
            float* y1 = y0 + NPIX;
            y0[pxl]     = dd[0] * 0.0009765625f + b0;
            y1[pxl]     = dd[1] * 0.0009765625f + b1;
            y0[pxl + 8] = dd[2] * 0.0009765625f + b0;
            y1[pxl + 8] = dd[3] * 0.0009765625f + b1;
        }
    }
}

// ---------------- deformable conv via mma.sync (fp16 in, 2-product) --------
// smem floats: sPy[3200] sPx[3200] sBNa[256] sBNb[256] | u32 Sbuf[2][8704]
#define DEF_SMEM_BYTES ((6912 + 17408) * 4)
__global__ void __launch_bounds__(256, 2) deform_hmma(
    const __half* __restrict__ xh,   // NHWC fp16 [b][p][256]
    const float* __restrict__ off,
    const uint2* __restrict__ BH,
    const float* __restrict__ bng, const float* __restrict__ bnb,
    const float* __restrict__ bnm, const float* __restrict__ bnv,
    float* __restrict__ yout) {
    float* sPy = smext;
    float* sPx = smext + 3200;
    float* sBNa = smext + 6400;
    float* sBNb = smext + 6656;
    uint32_t* Sbuf = (uint32_t*)(smext + 6912);

    const int tid = threadIdx.x;
    const int lane = tid & 31, warp = tid >> 5;
    const int b = blockIdx.y;
    const int row = blockIdx.x >> 1;
    const int px0 = (blockIdx.x & 1) << 6;

    const int wo = warp & 3;
    const int wp = warp >> 2;
    const int sh = warp & 1;
    const int cq = warp >> 1;
    const int lg = lane >> 3;
    const int c0s = cq * 32 + (lane & 7) * 4;

    if (tid < 256) {
        float inv = bng[tid] * rsqrtf(bnv[tid] + 1e-5f);
        sBNa[tid] = inv * 0.015625f;
        sBNb[tid] = bnb[tid] - bnm[tid] * inv;
    }
    for (int idx = tid; idx < 3200; idx += 256) {
        int gk = idx >> 6, p = idx & 63;
        int g = gk / 25, k = gk % 25;
        int kh = k / 5, kw = k % 5;
        int ch = b * 100 + g * 50 + 2 * k;
        float oy = off[(size_t)ch * NPIX + row * 128 + px0 + p];
        float ox = off[(size_t)(ch + 1) * NPIX + row * 128 + px0 + p];
        sPy[idx] = (float)(row + kh - 2) + oy;
        sPx[idx] = (float)(px0 + p + kw - 2) + ox;
    }
    __syncthreads();

    float d[64];
#pragma unroll
    for (int q = 0; q < 64; q++) d[q] = 0.f;

    const uint32_t sbase = smem_u32(Sbuf);
    const uint32_t lanePat = (lane & 15) * 272 + (lane >> 4) * 16;

    auto sample_tap = [&](int gk2, uint32_t* ShB, uint32_t* SlB) {
        const int gs = (gk2 >= 25) ? 1 : 0;
        const __half* xgb = xh + (size_t)b * NPIX * 256 + gs * 128 + c0s;
#pragma unroll
        for (int j = 0; j < 8; j++) {
            const int p = sh * 32 + j * 4 + lg;
            const float py = sPy[gk2 * 64 + p];
            const float pv = sPx[gk2 * 64 + p];
            const float y0f = floorf(py), x0f = floorf(pv);
            const float wy1 = py - y0f, wx1 = pv - x0f;
            const float wy0 = 1.f - wy1, wx0 = 1.f - wx1;
            const float w00 = wy0 * wx0, w01 = wy0 * wx1;
            const float w10 = wy1 * wx0, w11 = wy1 * wx1;
            const int iy = (int)y0f, ix = (int)x0f;
            const bool vy0 = (iy >= 0) & (iy < 128);
            const bool vy1 = (iy >= -1) & (iy < 127);
            const bool vx0 = (ix >= 0) & (ix < 128);
            const bool vx1 = (ix >= -1) & (ix < 127);
            const long base = ((long)iy * 128 + ix) * 256;
            const uint2 z2 = make_uint2(0u, 0u);
            uint2 ua = (vy0 & vx0) ? *(const uint2*)(xgb + base) : z2;
            uint2 ub = (vy0 & vx1) ? *(const uint2*)(xgb + base + 256) : z2;
            uint2 uc = (vy1 & vx0) ? *(const uint2*)(xgb + base + 128 * 256) : z2;
            uint2 ud = (vy1 & vx1) ? *(const uint2*)(xgb + base + 128 * 256 + 256) : z2;
            float2 a01 = __half22float2(*(__half2*)&ua.x);
            float2 a23 = __half22float2(*(__half2*)&ua.y);
            float2 b01 = __half22float2(*(__half2*)&ub.x);
            float2 b23 = __half22float2(*(__half2*)&ub.y);
            float2 c01 = __half22float2(*(__half2*)&uc.x);
            float2 c23 = __half22float2(*(__half2*)&uc.y);
            float2 e01 = __half22float2(*(__half2*)&ud.x);
            float2 e23 = __half22float2(*(__half2*)&ud.y);
            float r0 = w00 * a01.x + w01 * b01.x + w10 * c01.x + w11 * e01.x;
            float r1 = w00 * a01.y + w01 * b01.y + w10 * c01.y + w11 * e01.y;
            float r2 = w00 * a23.x + w01 * b23.x + w10 * c23.x + w11 * e23.x;
            float r3 = w00 * a23.y + w01 * b23.y + w10 * c23.y + w11 * e23.y;
            float h0 = __half2float(__float2half_rn(r0));
            float h1 = __half2float(__float2half_rn(r1));
            float h2f = __half2float(__float2half_rn(r2));
            float h3 = __half2float(__float2half_rn(r3));
            const int wi = p * 68 + (c0s >> 1);
            *(uint2*)&ShB[wi] = make_uint2(packh(h0, h1), packh(h2f, h3));
            *(uint2*)&SlB[wi] = make_uint2(packh(r0 - h0, r1 - h1),
                                           packh(r2 - h2f, r3 - h3));
        }
    };

    sample_tap(0, Sbuf, Sbuf + 4352);
    __syncthreads();

    for (int gk = 0; gk < 50; gk++) {
        const int cur = gk & 1;
        if (gk < 49) {
            uint32_t* nb = Sbuf + (cur ^ 1) * 8704;
            sample_tap(gk + 1, nb, nb + 4352);
        }
        const uint32_t aH = sbase + cur * 34816 + lanePat;
        const uint32_t aL = aH + 17408;
        const uint2* BHt = BH + ((size_t)gk * 8 * 32 + wo * 8) * 32 + lane;
#pragma unroll
        for (int s = 0; s < 8; s++) {
            uint32_t Ah[2][4], Al[2][4];
            ldm4(Ah[0], aH + (wp * 32     ) * 272 + s * 32);
            ldm4(Ah[1], aH + (wp * 32 + 16) * 272 + s * 32);
            ldm4(Al[0], aL + (wp * 32     ) * 272 + s * 32);
            ldm4(Al[1], aL + (wp * 32 + 16) * 272 + s * 32);
            const uint2* bh = BHt + (size_t)s * 1024;
#pragma unroll
            for (int j2 = 0; j2 < 8; j2++) {
                uint2 Bh = bh[j2 * 32];
                float* d0 = &d[(0 * 8 + j2) * 4];
                float* d1 = &d[(1 * 8 + j2) * 4];
                mma16816(d0[0], d0[1], d0[2], d0[3], Ah[0], Bh.x, Bh.y);
                mma16816(d1[0], d1[1], d1[2], d1[3], Ah[1], Bh.x, Bh.y);
                mma16816(d0[0], d0[1], d0[2], d0[3], Al[0], Bh.x, Bh.y);
                mma16816(d1[0], d1[1], d1[2], d1[3], Al[1], Bh.x, Bh.y);
            }
        }
        __syncthreads();
    }

    const int ge = lane >> 2, tig = lane & 3;
    const size_t outbase = (size_t)row * 128 + px0;
#pragma unroll
    for (int mt = 0; mt < 2; mt++) {
#pragma unroll
        for (int j2 = 0; j2 < 8; j2++) {
            const float* dd = &d[(mt * 8 + j2) * 4];
            const int pxl = wp * 32 + mt * 16 + ge;
            const int o = wo * 64 + j2 * 8 + 2 * tig;
            float a0 = sBNa[o], b0v = sBNb[o];
            float a1 = sBNa[o + 1], b1v = sBNb[o + 1];
            float* y0 = yout + ((size_t)(b * 256 + o)) * NPIX + outbase;
            float* y1 = yout + ((size_t)(b * 256 + o + 1)) * NPIX + outbase;
            y0[pxl]     = fmaxf(dd[0] * a0 + b0v, 0.f);
            y1[pxl]     = fmaxf(dd[1] * a1 + b1v, 0.f);
            y0[pxl + 8] = fmaxf(dd[2] * a0 + b0v, 0.f);
            y1[pxl + 8] = fmaxf(dd[3] * a1 + b1v, 0.f);
        }
    }
}

// ---------------- SE / pool ----------------
__global__ void pool_kernel(const float* __restrict__ y, float* __restrict__ pool) {
    int bc = blockIdx.x;
    const float* plane = y + (size_t)bc * NPIX;
    float s = 0.f;
    for (int i = threadIdx.x; i < NPIX; i += 256) s += plane[i];
    __shared__ float red[256];
    red[threadIdx.x] = s;
    __syncthreads();
    for (int st = 128; st > 0; st >>= 1) {
        if (threadIdx.x < st) red[threadIdx.x] += red[threadIdx.x + st];
        __syncthreads();
    }
    if (threadIdx.x == 0) pool[bc] = red[0] * (1.f / NPIX);
}

__global__ void se_kernel(const float* __restrict__ pool,
                          const float* __restrict__ w1,
                          const float* __restrict__ w2,
                          float* __restrict__ scale) {
    int b = blockIdx.x;
    int tid = threadIdx.x;
    __shared__ float sp[256], shd[16];
    sp[tid] = pool[b * 256 + tid];
    __syncthreads();
    if (tid < 16) {
        float a = 0.f;
        for (int c = 0; c < 256; c++) a += sp[c] * w1[tid * 256 + c];
        shd[tid] = fmaxf(a, 0.f);
    }
    __syncthreads();
    float a = 0.f;
#pragma unroll
    for (int j = 0; j < 16; j++) a += shd[j] * w2[tid * 16 + j];
    scale[b * 256 + tid] = 1.f / (1.f + expf(-a));
}

// ---------------- final 1x1 conv + fused SE scale + BN + ReLU (fma2) ------
__global__ void __launch_bounds__(256) final_kernel(
    const float* __restrict__ xin, const float* __restrict__ sc,
    const float* __restrict__ redT,
    const float* __restrict__ bng, const float* __restrict__ bnb,
    const float* __restrict__ bnm, const float* __restrict__ bnv,
    float* __restrict__ out) {
    const int tid = threadIdx.x;
    const int b = blockIdx.y;
    const int p0 = blockIdx.x * 64;
    const int px = tid & 63, og = tid >> 6;
    __shared__ __align__(16) float sX[8][64];
    __shared__ __align__(16) float sWf[8][128];
    __shared__ float sBN[256];
    __shared__ float sSc[256];
    if (tid < 128) {
        float inv = bng[tid] * rsqrtf(bnv[tid] + 1e-5f);
        sBN[tid] = inv;
        sBN[128 + tid] = bnb[tid] - bnm[tid] * inv;
    }
    sSc[tid] = sc[b * 256 + tid];
    union { unsigned long long u[16]; float f[32]; } acc;
#pragma unroll
    for (int j = 0; j < 16; j++) acc.u[j] = 0ull;

    for (int cb = 0; cb < 256; cb += 8) {
        __syncthreads();
        {
            int i = tid;
            sX[i >> 6][i & 63] = xin[((size_t)(b * 256 + cb + (i >> 6))) * NPIX + p0 + (i & 63)]
                                 * sSc[cb + (i >> 6)];
            i = tid + 256;
            sX[i >> 6][i & 63] = xin[((size_t)(b * 256 + cb + (i >> 6))) * NPIX + p0 + (i & 63)]
                                 * sSc[cb + (i >> 6)];
            for (int t = tid; t < 1024; t += 256)
                sWf[t >> 7][t & 127] = redT[(cb + (t >> 7)) * 128 + (t & 127)];
        }
        __syncthreads();
#pragma unroll
        for (int c = 0; c < 8; c++) {
            float xv = sX[c][px];
            unsigned long long xd = pk2(xv, xv);
            const F4* wp = (const F4*)&sWf[c][og * 32];
#pragma unroll
            for (int j = 0; j < 8; j++) {
                F4 w = wp[j];
                fma2(acc.u[2 * j],     xd, w.u[0]);
                fma2(acc.u[2 * j + 1], xd, w.u[1]);
            }
        }
    }
#pragma unroll
    for (int j = 0; j < 32; j++) {
        int o = og * 32 + j;
        float v = acc.f[j] * sBN[o] + sBN[128 + o];
        out[((size_t)(b * 128 + o)) * NPIX + p0 + px] = fmaxf(v, 0.f);
    }
}

// ---------------- launch ----------------
extern "C" void kernel_launch(void* const* d_in, const int* in_sizes, int n_in,
                              void* d_out, int out_size) {
    const float* bev1   = (const float*)d_in[0];
    const float* bev2   = (const float*)d_in[1];
    const float* off_w1 = (const float*)d_in[2];
    const float* off_b1 = (const float*)d_in[3];
    const float* dcn_w1 = (const float*)d_in[4];
    const float* bn1_g  = (const float*)d_in[5];
    const float* bn1_b  = (const float*)d_in[6];
    const float* bn1_m  = (const float*)d_in[7];
    const float* bn1_v  = (const float*)d_in[8];
    const float* se1_w1 = (const float*)d_in[9];
    const float* se1_w2 = (const float*)d_in[10];
    const float* off_w2 = (const float*)d_in[11];
    const float* off_b2 = (const float*)d_in[12];
    const float* dcn_w2 = (const float*)d_in[13];
    const float* bn2_g  = (const float*)d_in[14];
    const float* bn2_b  = (const float*)d_in[15];
    const float* bn2_m  = (const float*)d_in[16];
    const float* bn2_v  = (const float*)d_in[17];
    const float* se2_w1 = (const float*)d_in[18];
    const float* se2_w2 = (const float*)d_in[19];
    const float* red_w  = (const float*)d_in[20];
    const float* bn3_g  = (const float*)d_in[21];
    const float* bn3_b  = (const float*)d_in[22];
    const float* bn3_m  = (const float*)d_in[23];
    const float* bn3_v  = (const float*)d_in[24];

    float *A, *B, *OFF, *RT, *POOL, *SCALE;
    __half *C;
    uint2 *BH, *OBH;
    cudaGetSymbolAddress((void**)&A,    g_bufA);
    cudaGetSymbolAddress((void**)&B,    g_bufB);
    cudaGetSymbolAddress((void**)&C,    g_bufC);
    cudaGetSymbolAddress((void**)&OFF,  g_off);
    cudaGetSymbolAddress((void**)&BH,   g_bh);
    cudaGetSymbolAddress((void**)&OBH,  g_obh);
    cudaGetSymbolAddress((void**)&RT,   g_rT);
    cudaGetSymbolAddress((void**)&POOL, g_pool);
    cudaGetSymbolAddress((void**)&SCALE,g_scale);

    const int OFF_SMEM = 2 * 4352 * 4;          // 34,816 B
    cudaFuncSetAttribute(offconv_hmma,
                         cudaFuncAttributeMaxDynamicSharedMemorySize, OFF_SMEM);
    cudaFuncSetAttribute(deform_hmma,
                         cudaFuncAttributeMaxDynamicSharedMemorySize, DEF_SMEM_BYTES);

    // ---- stage 1 ----
    concat_nhwc<<<dim3(512, 8, 4), 256>>>(bev1, bev2, C);
    prep_weights<<<2400, 256>>>(dcn_w1, off_w1, BH, OBH);
    offconv_hmma<<<dim3(256, 4), 256, OFF_SMEM>>>(C, OBH, off_b1, OFF);
    deform_hmma<<<dim3(256, 4), 256, DEF_SMEM_BYTES>>>(C, OFF, BH,
                                                 bn1_g, bn1_b, bn1_m, bn1_v, B);
    pool_kernel<<<1024, 256>>>(B, POOL);
    se_kernel<<<4, 256>>>(POOL, se1_w1, se1_w2, SCALE);

    // ---- stage 2 (scale1 fused into to_nhwc) ----
    to_nhwc_scaled<<<dim3(512, 8, 4), 256>>>(B, SCALE, C);
    prep_weights<<<2400, 256>>>(dcn_w2, off_w2, BH, OBH);
    offconv_hmma<<<dim3(256, 4), 256, OFF_SMEM>>>(C, OBH, off_b2, OFF);
    deform_hmma<<<dim3(256, 4), 256, DEF_SMEM_BYTES>>>(C, OFF, BH,
                                                 bn2_g, bn2_b, bn2_m, bn2_v, A);
    pool_kernel<<<1024, 256>>>(A, POOL);
    se_kernel<<<4, 256>>>(POOL, se2_w1, se2_w2, SCALE);

    // ---- final (scale2 fused) ----
    transpose_redw<<<128, 256>>>(red_w, RT);
    final_kernel<<<dim3(256, 4), 256>>>(A, SCALE, RT, bn3_g, bn3_b, bn3_m, bn3_v,
                                        (float*)d_out);
}

// round 15
// speedup vs baseline: 6.6462x; 1.1899x over previous
#include <cuda_runtime.h>
#include <cuda_fp16.h>
#include <math.h>
#include <stdint.h>

// ---------------- packed f32x2 helpers (final conv) ----------------
__device__ __forceinline__ unsigned long long pk2(float x, float y) {
    unsigned long long r;
    asm("mov.b64 %0, {%1, %2};" : "=l"(r) : "f"(x), "f"(y));
    return r;
}
__device__ __forceinline__ void fma2(unsigned long long& d,
                                     unsigned long long a, unsigned long long b) {
    asm("fma.rn.f32x2 %0, %1, %2, %0;" : "+l"(d) : "l"(a), "l"(b));
}
union F4 { float4 v; float f[4]; unsigned long long u[2]; };

// ---------------- mma.sync helpers ----------------
__device__ __forceinline__ void ldm4(uint32_t* r, uint32_t addr) {
    asm volatile("ldmatrix.sync.aligned.m8n8.x4.shared.b16 {%0,%1,%2,%3}, [%4];"
                 : "=r"(r[0]), "=r"(r[1]), "=r"(r[2]), "=r"(r[3]) : "r"(addr));
}
__device__ __forceinline__ void mma16816(float& d0, float& d1, float& d2, float& d3,
                                         const uint32_t* a, uint32_t b0, uint32_t b1) {
    asm volatile(
        "mma.sync.aligned.m16n8k16.row.col.f32.f16.f16.f32 "
        "{%0,%1,%2,%3}, {%4,%5,%6,%7}, {%8,%9}, {%0,%1,%2,%3};"
        : "+f"(d0), "+f"(d1), "+f"(d2), "+f"(d3)
        : "r"(a[0]), "r"(a[1]), "r"(a[2]), "r"(a[3]), "r"(b0), "r"(b1));
}
__device__ __forceinline__ uint32_t smem_u32(const void* p) {
    uint32_t a;
    asm("{ .reg .u64 t; cvta.to.shared.u64 t, %1; cvt.u32.u64 %0, t; }"
        : "=r"(a) : "l"(p));
    return a;
}
__device__ __forceinline__ uint32_t packh(float a, float b) {
    __half2 h = __halves2half2(__float2half_rn(a), __float2half_rn(b));
    return *(uint32_t*)&h;
}

// single extern smem symbol shared by kernels
extern __shared__ float smext[];

// ---------------- scratch ----------------
#define NPIX 16384
__device__ __align__(16) float  g_bufA[4 * 256 * NPIX];
__device__ __align__(16) float  g_bufB[4 * 256 * NPIX];
__device__ __align__(16) __half g_bufC[4 * 256 * NPIX];   // NHWC fp16
__device__ __align__(16) float  g_off [4 * 100 * NPIX];
__device__ __align__(16) uint2  g_bh  [50 * 8 * 32 * 32];
__device__ __align__(16) uint2  g_obh [50 * 8 * 16 * 32];
__device__ __align__(16) float  g_rT  [256 * 128];
__device__ float g_pool[1024];
__device__ float g_scale[1024];

// ---------------- concat -> NHWC fp16 C ----------
__global__ void __launch_bounds__(256) concat_nhwc(
    const float* __restrict__ bev1, const float* __restrict__ bev2,
    __half* __restrict__ C) {
    __shared__ float tile[32][33];
    const int bp = blockIdx.x, bc = blockIdx.y, b = blockIdx.z;
    const int tx = threadIdx.x & 31, ty = threadIdx.x >> 5;
    const float* src = ((bc < 4)
        ? bev1 + ((size_t)b * 128 + bc * 32) * NPIX
        : bev2 + ((size_t)b * 128 + (bc - 4) * 32) * NPIX) + bp * 32;
#pragma unroll
    for (int r = 0; r < 4; r++) {
        int c = ty + r * 8;
        tile[c][tx] = src[(size_t)c * NPIX + tx];
    }
    __syncthreads();
    __half* dst = C + ((size_t)b * NPIX + bp * 32) * 256 + bc * 32;
#pragma unroll
    for (int r = 0; r < 4; r++) {
        int p = ty + r * 8;
        dst[(size_t)p * 256 + tx] = __float2half_rn(tile[tx][p]);
    }
}

// ---------------- NCHW -> NHWC fp16 transpose with fused SE scale ----------
__global__ void __launch_bounds__(256) to_nhwc_scaled(
    const float* __restrict__ in, const float* __restrict__ sc,
    __half* __restrict__ outp) {
    __shared__ float tile[32][33];
    __shared__ float sSc[32];
    const int bp = blockIdx.x, bc = blockIdx.y, b = blockIdx.z;
    const int tx = threadIdx.x & 31, ty = threadIdx.x >> 5;
    if (threadIdx.x < 32) sSc[threadIdx.x] = sc[b * 256 + bc * 32 + threadIdx.x];
    const float* src = in + ((size_t)b * 256 + bc * 32) * NPIX + bp * 32;
#pragma unroll
    for (int r = 0; r < 4; r++) {
        int c = ty + r * 8;
        tile[c][tx] = src[(size_t)c * NPIX + tx];
    }
    __syncthreads();
    __half* dst = outp + ((size_t)b * NPIX + bp * 32) * 256 + bc * 32;
    const float s = sSc[tx];
#pragma unroll
    for (int r = 0; r < 4; r++) {
        int p = ty + r * 8;
        dst[(size_t)p * 256 + tx] = __float2half_rn(tile[tx][p] * s);
    }
}

// ---------------- weight prep: dcn hi + off hi fragment packs --------------
__global__ void prep_weights(const float* __restrict__ dcnw,
                             const float* __restrict__ offw,
                             uint2* __restrict__ BH,
                             uint2* __restrict__ OBH) {
    int idx = blockIdx.x * 256 + threadIdx.x;
    if (idx < 409600) {
        const int t  = idx & 31;
        const int j  = (idx >> 5) & 31;
        const int s  = (idx >> 10) & 7;
        const int gk = idx >> 13;
        const int k = gk % 25, g = gk / 25;
        const int o = j * 8 + (t >> 2);
        const int c0 = s * 16 + 2 * (t & 3);
        float w0 = dcnw[o * 6400 + (g * 128 + c0    ) * 25 + k] * 64.f;
        float w1 = dcnw[o * 6400 + (g * 128 + c0 + 1) * 25 + k] * 64.f;
        float w8 = dcnw[o * 6400 + (g * 128 + c0 + 8) * 25 + k] * 64.f;
        float w9 = dcnw[o * 6400 + (g * 128 + c0 + 9) * 25 + k] * 64.f;
        BH[idx] = make_uint2(packh(__half2float(__float2half_rn(w0)),
                                   __half2float(__float2half_rn(w1))),
                             packh(__half2float(__float2half_rn(w8)),
                                   __half2float(__float2half_rn(w9))));
    } else if (idx < 614400) {
        const int i2 = idx - 409600;
        const int t  = i2 & 31;
        const int j  = (i2 >> 5) & 15;
        const int s  = (i2 >> 9) & 7;
        const int it = i2 >> 12;
        const int k = it >> 1, h = it & 1;
        const int o = j * 8 + (t >> 2);
        const int c0 = h * 128 + s * 16 + 2 * (t & 3);
        float w0 = 0.f, w1 = 0.f, w8 = 0.f, w9 = 0.f;
        if (o < 100) {
            w0 = offw[o * 6400 + (c0    ) * 25 + k] * 1024.f;
            w1 = offw[o * 6400 + (c0 + 1) * 25 + k] * 1024.f;
            w8 = offw[o * 6400 + (c0 + 8) * 25 + k] * 1024.f;
            w9 = offw[o * 6400 + (c0 + 9) * 25 + k] * 1024.f;
        }
        OBH[i2] = make_uint2(packh(__half2float(__float2half_rn(w0)),
                                   __half2float(__float2half_rn(w1))),
                             packh(__half2float(__float2half_rn(w8)),
                                   __half2float(__float2half_rn(w9))));
    }
}

__global__ void transpose_redw(const float* __restrict__ w, float* __restrict__ dst) {
    int idx = blockIdx.x * 256 + threadIdx.x;
    int o = idx & 127;
    int c = idx >> 7;
    dst[idx] = w[o * 256 + c];
}

// ---------------- offset conv via mma.sync (fp16 in, single product) -------
// dynamic smem: uint32 Sbuf[2][4352] = 34,816 B
__global__ void __launch_bounds__(256, 2) offconv_hmma(
    const __half* __restrict__ xh,   // NHWC fp16 [b][p][256]
    const uint2* __restrict__ OBH,
    const float* __restrict__ offb,
    float* __restrict__ offout) {
    uint32_t* Sbuf = (uint32_t*)smext;

    const int tid = threadIdx.x;
    const int lane = tid & 31, warp = tid >> 5;
    const int b = blockIdx.y;
    const int row = blockIdx.x >> 1;
    const int px0 = (blockIdx.x & 1) << 6;

    const int wo = warp & 1;
    const int wp = warp >> 1;
    const int sh = warp & 1;
    const int cq = warp >> 1;
    const int lg = lane >> 3;
    const int c0s = cq * 32 + (lane & 7) * 4;

    float d[32];
#pragma unroll
    for (int q = 0; q < 32; q++) d[q] = 0.f;

    const uint32_t sbase = smem_u32(Sbuf);
    const uint32_t lanePat = (lane & 15) * 272 + (lane >> 4) * 16;
    const __half* xb = xh + (size_t)b * NPIX * 256;

    auto sample_tap = [&](int it2, uint32_t* ShB) {
        const int k2 = it2 >> 1, h2 = it2 & 1;
        const int kh2 = k2 / 5, kw2 = k2 % 5;
        const int gy2 = row + kh2 - 2;
        const bool vy2 = (gy2 >= 0) & (gy2 < 128);
#pragma unroll
        for (int j = 0; j < 8; j++) {
            const int p = sh * 32 + j * 4 + lg;
            const int gx = px0 + p + kw2 - 2;
            uint2 va = make_uint2(0u, 0u);
            if (vy2 && gx >= 0 && gx < 128)
                va = *(const uint2*)(xb + ((size_t)gy2 * 128 + gx) * 256 + h2 * 128 + c0s);
            *(uint2*)&ShB[p * 68 + (c0s >> 1)] = va;
        }
    };

    sample_tap(0, Sbuf);
    __syncthreads();

    for (int it = 0; it < 50; it++) {
        const int cur = it & 1;
        if (it < 49) sample_tap(it + 1, Sbuf + (cur ^ 1) * 4352);
        const uint32_t aH = sbase + cur * 17408 + lanePat;
        const uint2* BHt = OBH + ((size_t)it * 8 * 16 + wo * 8) * 32 + lane;
#pragma unroll
        for (int s = 0; s < 8; s++) {
            uint32_t Ah[4];
            ldm4(Ah, aH + (wp * 16) * 272 + s * 32);
            const uint2* bh = BHt + (size_t)s * 512;
#pragma unroll
            for (int j2 = 0; j2 < 8; j2++) {
                uint2 Bh = bh[j2 * 32];
                float* dd = &d[j2 * 4];
                mma16816(dd[0], dd[1], dd[2], dd[3], Ah, Bh.x, Bh.y);
            }
        }
        __syncthreads();
    }

    const int g2 = lane >> 2, tig = lane & 3;
    const int pxl = wp * 16 + g2;
    const size_t outbase = (size_t)row * 128 + px0;
#pragma unroll
    for (int j2 = 0; j2 < 8; j2++) {
        const int o = wo * 64 + j2 * 8 + 2 * tig;
        if (o < 100) {
            const float* dd = &d[j2 * 4];
            const float b0 = offb[o], b1 = offb[o + 1];
            float* y0 = offout + ((size_t)(b * 100 + o)) * NPIX + outbase;
            float* y1 = y0 + NPIX;
            y0[pxl]     = dd[0] * 0.0009765625f + b0;
            y1[pxl]     = dd[1] * 0.0009765625f + b1;
            y0[pxl + 8] = dd[2] * 0.0009765625f + b0;
            y1[pxl + 8] = dd[3] * 0.0009765625f + b1;
        }
    }
}

// ---------------- deformable conv via mma.sync (fp16, single product) ------
// smem floats: sPy[3200] sPx[3200] sBNa[256] sBNb[256] | u32 Sbuf[2][4352]
#define DEF_SMEM_BYTES (6912 * 4 + 2 * 4352 * 4)   // 62,464 B
__global__ void __launch_bounds__(256, 2) deform_hmma(
    const __half* __restrict__ xh,   // NHWC fp16 [b][p][256]
    const float* __restrict__ off,
    const uint2* __restrict__ BH,
    const float* __restrict__ bng, const float* __restrict__ bnb,
    const float* __restrict__ bnm, const float* __restrict__ bnv,
    float* __restrict__ yout) {
    float* sPy = smext;
    float* sPx = smext + 3200;
    float* sBNa = smext + 6400;
    float* sBNb = smext + 6656;
    uint32_t* Sbuf = (uint32_t*)(smext + 6912);

    const int tid = threadIdx.x;
    const int lane = tid & 31, warp = tid >> 5;
    const int b = blockIdx.y;
    const int row = blockIdx.x >> 1;
    const int px0 = (blockIdx.x & 1) << 6;

    const int wo = warp & 3;
    const int wp = warp >> 2;
    const int sh = warp & 1;
    const int cq = warp >> 1;
    const int lg = lane >> 3;
    const int c0s = cq * 32 + (lane & 7) * 4;

    if (tid < 256) {
        float inv = bng[tid] * rsqrtf(bnv[tid] + 1e-5f);
        sBNa[tid] = inv * 0.015625f;
        sBNb[tid] = bnb[tid] - bnm[tid] * inv;
    }
    for (int idx = tid; idx < 3200; idx += 256) {
        int gk = idx >> 6, p = idx & 63;
        int g = gk / 25, k = gk % 25;
        int kh = k / 5, kw = k % 5;
        int ch = b * 100 + g * 50 + 2 * k;
        float oy = off[(size_t)ch * NPIX + row * 128 + px0 + p];
        float ox = off[(size_t)(ch + 1) * NPIX + row * 128 + px0 + p];
        sPy[idx] = (float)(row + kh - 2) + oy;
        sPx[idx] = (float)(px0 + p + kw - 2) + ox;
    }
    __syncthreads();

    float d[64];
#pragma unroll
    for (int q = 0; q < 64; q++) d[q] = 0.f;

    const uint32_t sbase = smem_u32(Sbuf);
    const uint32_t lanePat = (lane & 15) * 272 + (lane >> 4) * 16;

    auto sample_tap = [&](int gk2, uint32_t* ShB) {
        const int gs = (gk2 >= 25) ? 1 : 0;
        const __half* xgb = xh + (size_t)b * NPIX * 256 + gs * 128 + c0s;
#pragma unroll
        for (int j = 0; j < 8; j++) {
            const int p = sh * 32 + j * 4 + lg;
            const float py = sPy[gk2 * 64 + p];
            const float pv = sPx[gk2 * 64 + p];
            const float y0f = floorf(py), x0f = floorf(pv);
            const float wy1 = py - y0f, wx1 = pv - x0f;
            const float wy0 = 1.f - wy1, wx0 = 1.f - wx1;
            const float w00 = wy0 * wx0, w01 = wy0 * wx1;
            const float w10 = wy1 * wx0, w11 = wy1 * wx1;
            const int iy = (int)y0f, ix = (int)x0f;
            const bool vy0 = (iy >= 0) & (iy < 128);
            const bool vy1 = (iy >= -1) & (iy < 127);
            const bool vx0 = (ix >= 0) & (ix < 128);
            const bool vx1 = (ix >= -1) & (ix < 127);
            const long base = ((long)iy * 128 + ix) * 256;
            const uint2 z2 = make_uint2(0u, 0u);
            uint2 ua = (vy0 & vx0) ? *(const uint2*)(xgb + base) : z2;
            uint2 ub = (vy0 & vx1) ? *(const uint2*)(xgb + base + 256) : z2;
            uint2 uc = (vy1 & vx0) ? *(const uint2*)(xgb + base + 128 * 256) : z2;
            uint2 ud = (vy1 & vx1) ? *(const uint2*)(xgb + base + 128 * 256 + 256) : z2;
            float2 a01 = __half22float2(*(__half2*)&ua.x);
            float2 a23 = __half22float2(*(__half2*)&ua.y);
            float2 b01 = __half22float2(*(__half2*)&ub.x);
            float2 b23 = __half22float2(*(__half2*)&ub.y);
            float2 c01 = __half22float2(*(__half2*)&uc.x);
            float2 c23 = __half22float2(*(__half2*)&uc.y);
            float2 e01 = __half22float2(*(__half2*)&ud.x);
            float2 e23 = __half22float2(*(__half2*)&ud.y);
            float r0 = w00 * a01.x + w01 * b01.x + w10 * c01.x + w11 * e01.x;
            float r1 = w00 * a01.y + w01 * b01.y + w10 * c01.y + w11 * e01.y;
            float r2 = w00 * a23.x + w01 * b23.x + w10 * c23.x + w11 * e23.x;
            float r3 = w00 * a23.y + w01 * b23.y + w10 * c23.y + w11 * e23.y;
            *(uint2*)&ShB[p * 68 + (c0s >> 1)] =
                make_uint2(packh(r0, r1), packh(r2, r3));
        }
    };

    sample_tap(0, Sbuf);
    __syncthreads();

    for (int gk = 0; gk < 50; gk++) {
        const int cur = gk & 1;
        if (gk < 49) sample_tap(gk + 1, Sbuf + (cur ^ 1) * 4352);
        const uint32_t aH = sbase + cur * 17408 + lanePat;
        const uint2* BHt = BH + ((size_t)gk * 8 * 32 + wo * 8) * 32 + lane;
#pragma unroll
        for (int s = 0; s < 8; s++) {
            uint32_t Ah[2][4];
            ldm4(Ah[0], aH + (wp * 32     ) * 272 + s * 32);
            ldm4(Ah[1], aH + (wp * 32 + 16) * 272 + s * 32);
            const uint2* bh = BHt + (size_t)s * 1024;
#pragma unroll
            for (int j2 = 0; j2 < 8; j2++) {
                uint2 Bh = bh[j2 * 32];
                float* d0 = &d[(0 * 8 + j2) * 4];
                float* d1 = &d[(1 * 8 + j2) * 4];
                mma16816(d0[0], d0[1], d0[2], d0[3], Ah[0], Bh.x, Bh.y);
                mma16816(d1[0], d1[1], d1[2], d1[3], Ah[1], Bh.x, Bh.y);
            }
        }
        __syncthreads();
    }

    const int ge = lane >> 2, tig = lane & 3;
    const size_t outbase = (size_t)row * 128 + px0;
#pragma unroll
    for (int mt = 0; mt < 2; mt++) {
#pragma unroll
        for (int j2 = 0; j2 < 8; j2++) {
            const float* dd = &d[(mt * 8 + j2) * 4];
            const int pxl = wp * 32 + mt * 16 + ge;
            const int o = wo * 64 + j2 * 8 + 2 * tig;
            float a0 = sBNa[o], b0v = sBNb[o];
            float a1 = sBNa[o + 1], b1v = sBNb[o + 1];
            float* y0 = yout + ((size_t)(b * 256 + o)) * NPIX + outbase;
            float* y1 = yout + ((size_t)(b * 256 + o + 1)) * NPIX + outbase;
            y0[pxl]     = fmaxf(dd[0] * a0 + b0v, 0.f);
            y1[pxl]     = fmaxf(dd[1] * a1 + b1v, 0.f);
            y0[pxl + 8] = fmaxf(dd[2] * a0 + b0v, 0.f);
            y1[pxl + 8] = fmaxf(dd[3] * a1 + b1v, 0.f);
        }
    }
}

// ---------------- SE / pool ----------------
__global__ void pool_kernel(const float* __restrict__ y, float* __restrict__ pool) {
    int bc = blockIdx.x;
    const float* plane = y + (size_t)bc * NPIX;
    float s = 0.f;
    for (int i = threadIdx.x; i < NPIX; i += 256) s += plane[i];
    __shared__ float red[256];
    red[threadIdx.x] = s;
    __syncthreads();
    for (int st = 128; st > 0; st >>= 1) {
        if (threadIdx.x < st) red[threadIdx.x] += red[threadIdx.x + st];
        __syncthreads();
    }
    if (threadIdx.x == 0) pool[bc] = red[0] * (1.f / NPIX);
}

__global__ void se_kernel(const float* __restrict__ pool,
                          const float* __restrict__ w1,
                          const float* __restrict__ w2,
                          float* __restrict__ scale) {
    int b = blockIdx.x;
    int tid = threadIdx.x;
    __shared__ float sp[256], shd[16];
    sp[tid] = pool[b * 256 + tid];
    __syncthreads();
    if (tid < 16) {
        float a = 0.f;
        for (int c = 0; c < 256; c++) a += sp[c] * w1[tid * 256 + c];
        shd[tid] = fmaxf(a, 0.f);
    }
    __syncthreads();
    float a = 0.f;
#pragma unroll
    for (int j = 0; j < 16; j++) a += shd[j] * w2[tid * 16 + j];
    scale[b * 256 + tid] = 1.f / (1.f + expf(-a));
}

// ---------------- final 1x1 conv + fused SE scale + BN + ReLU (fma2) ------
__global__ void __launch_bounds__(256) final_kernel(
    const float* __restrict__ xin, const float* __restrict__ sc,
    const float* __restrict__ redT,
    const float* __restrict__ bng, const float* __restrict__ bnb,
    const float* __restrict__ bnm, const float* __restrict__ bnv,
    float* __restrict__ out) {
    const int tid = threadIdx.x;
    const int b = blockIdx.y;
    const int p0 = blockIdx.x * 64;
    const int px = tid & 63, og = tid >> 6;
    __shared__ __align__(16) float sX[8][64];
    __shared__ __align__(16) float sWf[8][128];
    __shared__ float sBN[256];
    __shared__ float sSc[256];
    if (tid < 128) {
        float inv = bng[tid] * rsqrtf(bnv[tid] + 1e-5f);
        sBN[tid] = inv;
        sBN[128 + tid] = bnb[tid] - bnm[tid] * inv;
    }
    sSc[tid] = sc[b * 256 + tid];
    union { unsigned long long u[16]; float f[32]; } acc;
#pragma unroll
    for (int j = 0; j < 16; j++) acc.u[j] = 0ull;

    for (int cb = 0; cb < 256; cb += 8) {
        __syncthreads();
        {
            int i = tid;
            sX[i >> 6][i & 63] = xin[((size_t)(b * 256 + cb + (i >> 6))) * NPIX + p0 + (i & 63)]
                                 * sSc[cb + (i >> 6)];
            i = tid + 256;
            sX[i >> 6][i & 63] = xin[((size_t)(b * 256 + cb + (i >> 6))) * NPIX + p0 + (i & 63)]
                                 * sSc[cb + (i >> 6)];
            for (int t = tid; t < 1024; t += 256)
                sWf[t >> 7][t & 127] = redT[(cb + (t >> 7)) * 128 + (t & 127)];
        }
        __syncthreads();
#pragma unroll
        for (int c = 0; c < 8; c++) {
            float xv = sX[c][px];
            unsigned long long xd = pk2(xv, xv);
            const F4* wp = (const F4*)&sWf[c][og * 32];
#pragma unroll
            for (int j = 0; j < 8; j++) {
                F4 w = wp[j];
                fma2(acc.u[2 * j],     xd, w.u[0]);
                fma2(acc.u[2 * j + 1], xd, w.u[1]);
            }
        }
    }
#pragma unroll
    for (int j = 0; j < 32; j++) {
        int o = og * 32 + j;
        float v = acc.f[j] * sBN[o] + sBN[128 + o];
        out[((size_t)(b * 128 + o)) * NPIX + p0 + px] = fmaxf(v, 0.f);
    }
}

// ---------------- launch ----------------
extern "C" void kernel_launch(void* const* d_in, const int* in_sizes, int n_in,
                              void* d_out, int out_size) {
    const float* bev1   = (const float*)d_in[0];
    const float* bev2   = (const float*)d_in[1];
    const float* off_w1 = (const float*)d_in[2];
    const float* off_b1 = (const float*)d_in[3];
    const float* dcn_w1 = (const float*)d_in[4];
    const float* bn1_g  = (const float*)d_in[5];
    const float* bn1_b  = (const float*)d_in[6];
    const float* bn1_m  = (const float*)d_in[7];
    const float* bn1_v  = (const float*)d_in[8];
    const float* se1_w1 = (const float*)d_in[9];
    const float* se1_w2 = (const float*)d_in[10];
    const float* off_w2 = (const float*)d_in[11];
    const float* off_b2 = (const float*)d_in[12];
    const float* dcn_w2 = (const float*)d_in[13];
    const float* bn2_g  = (const float*)d_in[14];
    const float* bn2_b  = (const float*)d_in[15];
    const float* bn2_m  = (const float*)d_in[16];
    const float* bn2_v  = (const float*)d_in[17];
    const float* se2_w1 = (const float*)d_in[18];
    const float* se2_w2 = (const float*)d_in[19];
    const float* red_w  = (const float*)d_in[20];
    const float* bn3_g  = (const float*)d_in[21];
    const float* bn3_b  = (const float*)d_in[22];
    const float* bn3_m  = (const float*)d_in[23];
    const float* bn3_v  = (const float*)d_in[24];

    float *A, *B, *OFF, *RT, *POOL, *SCALE;
    __half *C;
    uint2 *BH, *OBH;
    cudaGetSymbolAddress((void**)&A,    g_bufA);
    cudaGetSymbolAddress((void**)&B,    g_bufB);
    cudaGetSymbolAddress((void**)&C,    g_bufC);
    cudaGetSymbolAddress((void**)&OFF,  g_off);
    cudaGetSymbolAddress((void**)&BH,   g_bh);
    cudaGetSymbolAddress((void**)&OBH,  g_obh);
    cudaGetSymbolAddress((void**)&RT,   g_rT);
    cudaGetSymbolAddress((void**)&POOL, g_pool);
    cudaGetSymbolAddress((void**)&SCALE,g_scale);

    const int OFF_SMEM = 2 * 4352 * 4;          // 34,816 B
    cudaFuncSetAttribute(offconv_hmma,
                         cudaFuncAttributeMaxDynamicSharedMemorySize, OFF_SMEM);
    cudaFuncSetAttribute(deform_hmma,
                         cudaFuncAttributeMaxDynamicSharedMemorySize, DEF_SMEM_BYTES);

    // ---- stage 1 ----
    concat_nhwc<<<dim3(512, 8, 4), 256>>>(bev1, bev2, C);
    prep_weights<<<2400, 256>>>(dcn_w1, off_w1, BH, OBH);
    offconv_hmma<<<dim3(256, 4), 256, OFF_SMEM>>>(C, OBH, off_b1, OFF);
    deform_hmma<<<dim3(256, 4), 256, DEF_SMEM_BYTES>>>(C, OFF, BH,
                                                 bn1_g, bn1_b, bn1_m, bn1_v, B);
    pool_kernel<<<1024, 256>>>(B, POOL);
    se_kernel<<<4, 256>>>(POOL, se1_w1, se1_w2, SCALE);

    // ---- stage 2 (scale1 fused into to_nhwc) ----
    to_nhwc_scaled<<<dim3(512, 8, 4), 256>>>(B, SCALE, C);
    prep_weights<<<2400, 256>>>(dcn_w2, off_w2, BH, OBH);
    offconv_hmma<<<dim3(256, 4), 256, OFF_SMEM>>>(C, OBH, off_b2, OFF);
    deform_hmma<<<dim3(256, 4), 256, DEF_SMEM_BYTES>>>(C, OFF, BH,
                                                 bn2_g, bn2_b, bn2_m, bn2_v, A);
    pool_kernel<<<1024, 256>>>(A, POOL);
    se_kernel<<<4, 256>>>(POOL, se2_w1, se2_w2, SCALE);

    // ---- final (scale2 fused) ----
    transpose_redw<<<128, 256>>>(red_w, RT);
    final_kernel<<<dim3(256, 4), 256>>>(A, SCALE, RT, bn3_g, bn3_b, bn3_m, bn3_v,
                                        (float*)d_out);
}